// round 1
// baseline (speedup 1.0000x reference)
#include <cuda_runtime.h>
#include <math.h>

#define CK_B   4
#define CK_S   1024
#define CK_HID 768
#define CK_H   6
#define CK_D   64
#define CK_AH  384
#define CK_KS  9
#define CK_BS  (CK_B*CK_S)

// ---------------- scratch (device globals; no allocation allowed) ----------
__device__ float g_mq [CK_BS*CK_AH];
__device__ float g_mk [CK_BS*CK_AH];
__device__ float g_mv [CK_BS*CK_AH];
__device__ float g_mkc[CK_BS*CK_AH];
__device__ float g_co [CK_BS*CK_AH];
__device__ float g_dw [CK_BS*CK_HID];
__device__ float g_pwT[CK_HID*CK_AH];
__device__ float g_ckb[CK_BS*CK_H*CK_KS];
__device__ float g_tds[CK_BS];

// ---------------- GEMM: C(MxN) = A(MxK) @ B(KxN) (+ bias) ------------------
__global__ __launch_bounds__(256) void gemm_bias_kernel(
    const float* __restrict__ A, const float* __restrict__ Bm,
    const float* __restrict__ bias, float* __restrict__ C,
    int M, int N, int K)
{
    __shared__ float As[16][65];
    __shared__ float Bs[16][64];
    int tid = threadIdx.x;
    int n0 = blockIdx.x * 64;
    int m0 = blockIdx.y * 64;
    int tx = tid & 15, ty = tid >> 4;
    float acc[4][4];
    #pragma unroll
    for (int i = 0; i < 4; i++)
        #pragma unroll
        for (int j = 0; j < 4; j++) acc[i][j] = 0.0f;

    for (int k0 = 0; k0 < K; k0 += 16) {
        #pragma unroll
        for (int it = 0; it < 4; it++) {
            int e = tid + it * 256;
            int kk = e & 15, m = e >> 4;
            As[kk][m] = A[(size_t)(m0 + m) * K + k0 + kk];
            int n = e & 63, kb = e >> 6;
            Bs[kb][n] = Bm[(size_t)(k0 + kb) * N + n0 + n];
        }
        __syncthreads();
        #pragma unroll
        for (int kk = 0; kk < 16; kk++) {
            float a[4], bv[4];
            #pragma unroll
            for (int i = 0; i < 4; i++) a[i] = As[kk][ty + 16 * i];
            #pragma unroll
            for (int j = 0; j < 4; j++) bv[j] = Bs[kk][tx + 16 * j];
            #pragma unroll
            for (int i = 0; i < 4; i++)
                #pragma unroll
                for (int j = 0; j < 4; j++)
                    acc[i][j] += a[i] * bv[j];
        }
        __syncthreads();
    }
    #pragma unroll
    for (int i = 0; i < 4; i++) {
        int m = m0 + ty + 16 * i;
        #pragma unroll
        for (int j = 0; j < 4; j++) {
            int n = n0 + tx + 16 * j;
            float v = acc[i][j];
            if (bias) v += bias[n];
            C[(size_t)m * N + n] = v;
        }
    }
}

// ---------------- transpose pw_w (AH,HID) -> (HID,AH) -----------------------
__global__ __launch_bounds__(256) void transpose_pw(
    const float* __restrict__ pw, float* __restrict__ pwT)
{
    int idx = blockIdx.x * 256 + threadIdx.x;
    if (idx >= CK_AH * CK_HID) return;
    int o = idx / CK_HID, c = idx % CK_HID;
    pwT[(size_t)c * CK_AH + o] = pw[idx];
}

// ---------------- depthwise conv over seq: out (B,S,HID) --------------------
__global__ __launch_bounds__(256) void dwconv_kernel(
    const float* __restrict__ Kin, const float* __restrict__ dww,
    float* __restrict__ outp)
{
    int idx = blockIdx.x * 256 + threadIdx.x;
    if (idx >= CK_BS * CK_HID) return;
    int c = idx % CK_HID;
    int s = (idx / CK_HID) % CK_S;
    int b = idx / (CK_HID * CK_S);
    float acc = 0.0f;
    #pragma unroll
    for (int t = 0; t < 9; t++) {
        int ss = s + t - 4;
        if (ss >= 0 && ss < CK_S)
            acc += Kin[((size_t)(b * CK_S + ss)) * CK_HID + c] * dww[c * 9 + t];
    }
    outp[idx] = acc;
}

// ---------- conv_attn = mkc*mq -> ck = softmax((ca @ ckW + b), KS) ----------
__global__ __launch_bounds__(128) void ck_kernel(
    const float* __restrict__ mq, const float* __restrict__ mkc,
    const float* __restrict__ ckW, const float* __restrict__ ckb,
    float* __restrict__ cko)
{
    __shared__ float ca[CK_AH];
    __shared__ float o[CK_H * CK_KS];
    int bs = blockIdx.x, tid = threadIdx.x;
    for (int c = tid; c < CK_AH; c += 128)
        ca[c] = mq[(size_t)bs * CK_AH + c] * mkc[(size_t)bs * CK_AH + c];
    __syncthreads();
    if (tid < 54) {
        float acc = ckb[tid];
        for (int c = 0; c < CK_AH; c++)
            acc += ca[c] * ckW[c * 54 + tid];
        o[tid] = acc;
    }
    __syncthreads();
    if (tid < CK_H) {
        float m = -1e30f;
        #pragma unroll
        for (int k = 0; k < 9; k++) m = fmaxf(m, o[tid * 9 + k]);
        float e[9]; float s = 0.0f;
        #pragma unroll
        for (int k = 0; k < 9; k++) { e[k] = __expf(o[tid * 9 + k] - m); s += e[k]; }
        float inv = 1.0f / s;
        #pragma unroll
        for (int k = 0; k < 9; k++)
            cko[(size_t)bs * 54 + tid * 9 + k] = e[k] * inv;
    }
}

// -------- dynamic-span conv out: sliding window of co x ck -> out[:,384:] ---
__global__ __launch_bounds__(256) void convout_kernel(
    const float* __restrict__ co, const float* __restrict__ cko,
    float* __restrict__ out)
{
    int idx = blockIdx.x * 256 + threadIdx.x;
    if (idx >= CK_BS * CK_AH) return;
    int hd = idx % CK_AH;
    int s  = (idx / CK_AH) % CK_S;
    int b  = idx / (CK_AH * CK_S);
    int h  = hd >> 6;
    const float* ckp = cko + ((size_t)(b * CK_S + s)) * 54 + h * 9;
    float acc = 0.0f;
    #pragma unroll
    for (int k = 0; k < 9; k++) {
        int ss = s + k - 4;
        if (ss >= 0 && ss < CK_S)
            acc += co[((size_t)(b * CK_S + ss)) * CK_AH + hd] * ckp[k];
    }
    out[((size_t)(b * CK_S + s)) * (2 * CK_AH) + CK_AH + hd] = acc;
}

// ---------------- masked softmax of normalized td (per batch) ---------------
__global__ __launch_bounds__(256) void tdsm_kernel(
    const float* __restrict__ td, const int* __restrict__ mask,
    float* __restrict__ out)
{
    __shared__ float red[256];
    int b = blockIdx.x, tid = threadIdx.x;
    float v[4]; float ss = 0.0f;
    #pragma unroll
    for (int t = 0; t < 4; t++) { v[t] = td[b * CK_S + tid + t * 256]; ss += v[t] * v[t]; }
    red[tid] = ss; __syncthreads();
    for (int s = 128; s > 0; s >>= 1) { if (tid < s) red[tid] += red[tid + s]; __syncthreads(); }
    float denom = fmaxf(sqrtf(red[0]), 1e-12f);
    __syncthreads();
    float x[4]; float m = -1e30f;
    #pragma unroll
    for (int t = 0; t < 4; t++) {
        int j = tid + t * 256;
        x[t] = mask[b * CK_S + j] ? (v[t] / denom) : -1e4f;
        m = fmaxf(m, x[t]);
    }
    red[tid] = m; __syncthreads();
    for (int s = 128; s > 0; s >>= 1) { if (tid < s) red[tid] = fmaxf(red[tid], red[tid + s]); __syncthreads(); }
    m = red[0]; __syncthreads();
    float e[4]; float se = 0.0f;
    #pragma unroll
    for (int t = 0; t < 4; t++) { e[t] = __expf(x[t] - m); se += e[t]; }
    red[tid] = se; __syncthreads();
    for (int s = 128; s > 0; s >>= 1) { if (tid < s) red[tid] += red[tid + s]; __syncthreads(); }
    float inv = 1.0f / red[0];
    #pragma unroll
    for (int t = 0; t < 4; t++) out[b * CK_S + tid + t * 256] = e[t] * inv;
}

// ---------------- fused attention with distance decay -----------------------
// One CTA = 16 query rows of one (b,h). SMEM scores [16][1040] (pad 1/64 for
// conflict-free segmented access). Cumsum state lives in registers (64/thread).
#define ATTN_SMEM_FLOATS (16*1040 + 256*65 + 16*65 + 1040 + 1040)
#define ATTN_SMEM_BYTES  (ATTN_SMEM_FLOATS*4)

__global__ __launch_bounds__(256) void attn_kernel(
    const float* __restrict__ mq, const float* __restrict__ mk,
    const float* __restrict__ mv, const int* __restrict__ mask,
    const float* __restrict__ tdsm, const float* __restrict__ gammas,
    float* __restrict__ out)
{
    extern __shared__ float smem[];
    float* sc  = smem;                 // [16][1040], idx = r*1040 + j + (j>>6)
    float* kv  = smem + 16 * 1040;     // [256][65]
    float* qs  = kv + 256 * 65;        // [16][65]  (reused as ctx at the end)
    float* amf = qs + 16 * 65;         // [1040] padded mask
    float* tds = amf + 1040;           // [1040] padded td softmax

    int tid = threadIdx.x;
    int blk = blockIdx.x;
    int it  = blk & 63;
    int h   = (blk >> 6) % CK_H;
    int b   = blk / (64 * CK_H);
    int i0  = it * 16;

    for (int e = tid; e < 16 * 64; e += 256) {
        int r = e >> 6, d = e & 63;
        qs[r * 65 + d] = mq[((size_t)(b * CK_S + i0 + r)) * CK_AH + h * CK_D + d] * 0.125f;
    }
    for (int j = tid; j < CK_S; j += 256) {
        int fj = j + (j >> 6);
        amf[fj] = mask[b * CK_S + j] ? 1.0f : 0.0f;
        tds[fj] = tdsm[b * CK_S + j];
    }
    float gamma = -log1pf(expf(gammas[h]));

    // ---- phase 1: scores = (q/8) @ k^T, 4x4 micro-tiles, interleaved -------
    {
        int rg = tid >> 6;   // 0..3 -> rows rg+4i
        int kg = tid & 63;   // keys kg+64j within 256-chunk
        for (int c0 = 0; c0 < CK_S; c0 += 256) {
            __syncthreads();
            for (int e = tid; e < 256 * 64; e += 256) {
                int j = e >> 6, d = e & 63;
                kv[j * 65 + d] = mk[((size_t)(b * CK_S + c0 + j)) * CK_AH + h * CK_D + d];
            }
            __syncthreads();
            float acc[4][4];
            #pragma unroll
            for (int i = 0; i < 4; i++)
                #pragma unroll
                for (int j = 0; j < 4; j++) acc[i][j] = 0.0f;
            #pragma unroll
            for (int d = 0; d < 64; d++) {
                float a[4], kk[4];
                #pragma unroll
                for (int i = 0; i < 4; i++) a[i] = qs[(rg + 4 * i) * 65 + d];
                #pragma unroll
                for (int j = 0; j < 4; j++) kk[j] = kv[(kg + 64 * j) * 65 + d];
                #pragma unroll
                for (int i = 0; i < 4; i++)
                    #pragma unroll
                    for (int j = 0; j < 4; j++)
                        acc[i][j] += a[i] * kk[j];
            }
            #pragma unroll
            for (int i = 0; i < 4; i++)
                #pragma unroll
                for (int j = 0; j < 4; j++) {
                    int gj = c0 + kg + 64 * j;
                    sc[(rg + 4 * i) * 1040 + gj + (gj >> 6)] = acc[i][j];
                }
        }
    }
    __syncthreads();

    // ---- phase 2+3: softmax -> cumsum -> effect -> second softmax ----------
    {
        int r = tid >> 4;          // row 0..15
        int l = tid & 15;          // 64-wide segment l*64..l*64+63
        unsigned lane = tid & 31;
        unsigned sub  = lane & 15;
        float* scr = sc + r * 1040 + l * 65;   // f(l*64+t) = l*65+t
        const float* amfl = amf + l * 65;
        const float* tdsl = tds + l * 65;
        int irow = i0 + r;

        float ev[64];
        float m = -1e30f;
        #pragma unroll
        for (int t = 0; t < 64; t++) {
            float x = (amfl[t] != 0.0f) ? scr[t] : -1e8f;
            ev[t] = x;
            m = fmaxf(m, x);
        }
        #pragma unroll
        for (int dl = 8; dl >= 1; dl >>= 1)
            m = fmaxf(m, __shfl_xor_sync(0xffffffffu, m, dl));
        float sum = 0.0f;
        #pragma unroll
        for (int t = 0; t < 64; t++) { float p = __expf(ev[t] - m); ev[t] = p; sum += p; }
        #pragma unroll
        for (int dl = 8; dl >= 1; dl >>= 1)
            sum += __shfl_xor_sync(0xffffffffu, sum, dl);
        float inv = 1.0f / sum;
        // masked probs + local inclusive cumsum (register resident)
        float c = 0.0f;
        #pragma unroll
        for (int t = 0; t < 64; t++) { c += ev[t] * inv * amfl[t]; ev[t] = c; }
        // 16-lane segmented inclusive scan of segment totals
        float x = c;
        #pragma unroll
        for (int dl = 1; dl < 16; dl <<= 1) {
            float v = __shfl_up_sync(0xffffffffu, x, dl);
            if (sub >= (unsigned)dl) x += v;
        }
        float excl = x - c;
        float tot  = __shfl_sync(0xffffffffu, x, (lane & 16) | 15);

        float m2 = -1e30f;
        #pragma unroll
        for (int t = 0; t < 64; t++) {
            float dc = ev[t] + excl;              // inclusive cumsum at j
            int j = l * 64 + t;
            float pos = fabsf((float)(j - irow));
            float ds  = sqrtf(fmaxf((tot - dc) * pos, 0.0f));
            float eff = __expf(ds * gamma);
            eff = fminf(fmaxf(eff, 1e-5f), 1e5f);
            if (j < irow) eff -= tdsl[t];
            float x2 = (amfl[t] != 0.0f) ? scr[t] * eff : -1e8f;
            ev[t] = x2;
            m2 = fmaxf(m2, x2);
        }
        #pragma unroll
        for (int dl = 8; dl >= 1; dl >>= 1)
            m2 = fmaxf(m2, __shfl_xor_sync(0xffffffffu, m2, dl));
        float s2 = 0.0f;
        #pragma unroll
        for (int t = 0; t < 64; t++) { float p = __expf(ev[t] - m2); ev[t] = p; s2 += p; }
        #pragma unroll
        for (int dl = 8; dl >= 1; dl >>= 1)
            s2 += __shfl_xor_sync(0xffffffffu, s2, dl);
        float inv2 = 1.0f / s2;
        #pragma unroll
        for (int t = 0; t < 64; t++) scr[t] = ev[t] * inv2;   // probs -> SMEM
    }
    __syncthreads();

    // ---- phase 4: ctx = P @ V, 4x4 micro, 4-way j-split --------------------
    {
        int rg = tid >> 6;         // 0..3 -> rows rg+4i
        int jg = (tid >> 4) & 3;   // j-slice: j = 4*jj + jg
        int dg = tid & 15;         // cols dg*4 + t
        float acc[4][4];
        #pragma unroll
        for (int i = 0; i < 4; i++)
            #pragma unroll
            for (int t = 0; t < 4; t++) acc[i][t] = 0.0f;

        for (int c0 = 0; c0 < CK_S; c0 += 256) {
            __syncthreads();
            for (int e = tid; e < 256 * 64; e += 256) {
                int j = e >> 6, d = e & 63;
                kv[j * 65 + d] = mv[((size_t)(b * CK_S + c0 + j)) * CK_AH + h * CK_D + d];
            }
            __syncthreads();
            #pragma unroll 4
            for (int jj = 0; jj < 64; jj++) {
                int j  = 4 * jj + jg;
                int gj = c0 + j;
                int fj = gj + (gj >> 6);
                float p[4], v[4];
                #pragma unroll
                for (int i = 0; i < 4; i++) p[i] = sc[(rg + 4 * i) * 1040 + fj];
                #pragma unroll
                for (int t = 0; t < 4; t++) v[t] = kv[j * 65 + dg * 4 + t];
                #pragma unroll
                for (int i = 0; i < 4; i++)
                    #pragma unroll
                    for (int t = 0; t < 4; t++)
                        acc[i][t] += p[i] * v[t];
            }
        }
        __syncthreads();
        float* ctxs = qs;  // reuse q buffer [16][65]
        for (int g = 0; g < 4; g++) {
            if (jg == g) {
                #pragma unroll
                for (int i = 0; i < 4; i++)
                    #pragma unroll
                    for (int t = 0; t < 4; t++) {
                        int idx = (rg + 4 * i) * 65 + dg * 4 + t;
                        if (g == 0) ctxs[idx] = acc[i][t];
                        else        ctxs[idx] += acc[i][t];
                    }
            }
            __syncthreads();
        }
        for (int e = tid; e < 16 * 64; e += 256) {
            int r = e >> 6, d = e & 63;
            out[((size_t)(b * CK_S + i0 + r)) * (2 * CK_AH) + h * CK_D + d] = ctxs[r * 65 + d];
        }
    }
}

// ---------------------------------------------------------------------------
extern "C" void kernel_launch(void* const* d_in, const int* in_sizes, int n_in,
                              void* d_out, int out_size)
{
    const float* Q    = (const float*)d_in[0];
    const float* K    = (const float*)d_in[1];
    const float* V    = (const float*)d_in[2];
    const float* td   = (const float*)d_in[3];
    const int*   mask = (const int*)  d_in[4];
    const float* Wq   = (const float*)d_in[5];
    const float* Wk   = (const float*)d_in[6];
    const float* Wv   = (const float*)d_in[7];
    const float* dww  = (const float*)d_in[8];
    const float* pww  = (const float*)d_in[9];
    const float* sepb = (const float*)d_in[10];
    const float* ckW  = (const float*)d_in[11];
    const float* ckb  = (const float*)d_in[12];
    const float* coW  = (const float*)d_in[13];
    const float* cob  = (const float*)d_in[14];
    const float* gam  = (const float*)d_in[15];
    float* out = (float*)d_out;

    float *mq, *mk, *mv, *mkc, *co, *dw, *pwT, *cko, *tds;
    cudaGetSymbolAddress((void**)&mq,  g_mq);
    cudaGetSymbolAddress((void**)&mk,  g_mk);
    cudaGetSymbolAddress((void**)&mv,  g_mv);
    cudaGetSymbolAddress((void**)&mkc, g_mkc);
    cudaGetSymbolAddress((void**)&co,  g_co);
    cudaGetSymbolAddress((void**)&dw,  g_dw);
    cudaGetSymbolAddress((void**)&pwT, g_pwT);
    cudaGetSymbolAddress((void**)&cko, g_ckb);
    cudaGetSymbolAddress((void**)&tds, g_tds);

    dim3 ggrid(CK_AH / 64, CK_BS / 64);   // (6, 64)
    gemm_bias_kernel<<<ggrid, 256>>>(Q, Wq, nullptr, mq, CK_BS, CK_AH, CK_HID);
    gemm_bias_kernel<<<ggrid, 256>>>(K, Wk, nullptr, mk, CK_BS, CK_AH, CK_HID);
    gemm_bias_kernel<<<ggrid, 256>>>(V, Wv, nullptr, mv, CK_BS, CK_AH, CK_HID);
    gemm_bias_kernel<<<ggrid, 256>>>(V, coW, cob, co, CK_BS, CK_AH, CK_HID);

    transpose_pw<<<(CK_AH * CK_HID + 255) / 256, 256>>>(pww, pwT);
    dwconv_kernel<<<(CK_BS * CK_HID + 255) / 256, 256>>>(K, dww, dw);
    gemm_bias_kernel<<<ggrid, 256>>>(dw, pwT, sepb, mkc, CK_BS, CK_AH, CK_HID);

    ck_kernel<<<CK_BS, 128>>>(mq, mkc, ckW, ckb, cko);
    convout_kernel<<<(CK_BS * CK_AH + 255) / 256, 256>>>(co, cko, out);

    tdsm_kernel<<<CK_B, 256>>>(td, mask, tds);

    cudaFuncSetAttribute(attn_kernel, cudaFuncAttributeMaxDynamicSharedMemorySize,
                         ATTN_SMEM_BYTES);
    attn_kernel<<<CK_B * CK_H * (CK_S / 16), 256, ATTN_SMEM_BYTES>>>(
        mq, mk, mv, mask, tds, gam, out);
}

// round 2
// speedup vs baseline: 1.9171x; 1.9171x over previous
#include <cuda_runtime.h>
#include <math.h>
#include <stdint.h>

#define CK_B   4
#define CK_S   1024
#define CK_HID 768
#define CK_H   6
#define CK_D   64
#define CK_AH  384
#define CK_KS  9
#define CK_BS  (CK_B*CK_S)

// ---------------- scratch (device globals; no allocation allowed) ----------
__device__ float g_mq [CK_BS*CK_AH];
__device__ float g_mk [CK_BS*CK_AH];
__device__ float g_mv [CK_BS*CK_AH];
__device__ float g_mkc[CK_BS*CK_AH];
__device__ float g_co [CK_BS*CK_AH];
__device__ float g_dw [CK_BS*CK_HID];
__device__ float g_pwT[CK_HID*CK_AH];
__device__ float g_ckb[CK_BS*CK_H*CK_KS];
__device__ float g_tds[CK_BS];

// ---------------- tf32 helpers ---------------------------------------------
__device__ __forceinline__ uint32_t f2tf32(float f) {
    uint32_t u;
    asm("cvt.rna.tf32.f32 %0, %1;" : "=r"(u) : "f"(f));
    return u;
}
__device__ __forceinline__ void mma_tf32(float c[4], const uint32_t a[4],
                                         const uint32_t b[2]) {
    asm volatile(
        "mma.sync.aligned.m16n8k8.row.col.f32.tf32.tf32.f32 "
        "{%0,%1,%2,%3}, {%4,%5,%6,%7}, {%8,%9}, {%0,%1,%2,%3};"
        : "+f"(c[0]), "+f"(c[1]), "+f"(c[2]), "+f"(c[3])
        : "r"(a[0]), "r"(a[1]), "r"(a[2]), "r"(a[3]), "r"(b[0]), "r"(b[1]));
}

// ---------------- batched TF32 tensor-core GEMM ----------------------------
// C(4096x384) = A(4096x768) @ B(768x384) (+bias); blockIdx.z picks operands.
// Tile 128x128x32; 8 warps each 32x64 (2x8 m16n8k8 tiles per k-step).
__global__ __launch_bounds__(256, 2) void gemm5_tf32(
    const float* __restrict__ Q, const float* __restrict__ Kin,
    const float* __restrict__ V, const float* __restrict__ dw,
    const float* __restrict__ Wq, const float* __restrict__ Wk,
    const float* __restrict__ Wv, const float* __restrict__ coW,
    const float* __restrict__ pwT,
    const float* __restrict__ cob, const float* __restrict__ sepb,
    float* __restrict__ mq, float* __restrict__ mk, float* __restrict__ mv,
    float* __restrict__ co, float* __restrict__ mkc)
{
    const float *A, *B, *bias; float* C;
    switch (blockIdx.z) {
        case 0:  A = Q;   B = Wq;  bias = nullptr; C = mq;  break;
        case 1:  A = Kin; B = Wk;  bias = nullptr; C = mk;  break;
        case 2:  A = V;   B = Wv;  bias = nullptr; C = mv;  break;
        case 3:  A = V;   B = coW; bias = cob;     C = co;  break;
        default: A = dw;  B = pwT; bias = sepb;    C = mkc; break;
    }
    __shared__ uint32_t As[128][36];   // pad 36: bank = (4g+t)%32, distinct
    __shared__ uint32_t Bs[32][132];   // pad 132: bank = (4t+g+c)%32, distinct

    int tid  = threadIdx.x;
    int m0   = blockIdx.y * 128;
    int n0   = blockIdx.x * 128;
    int lane = tid & 31;
    int g    = lane >> 2;      // groupID
    int t    = lane & 3;       // threadID_in_group
    int warp = tid >> 5;
    int wm   = warp >> 1;      // 0..3
    int wn   = warp & 1;       // 0..1

    float c[2][8][4];
    #pragma unroll
    for (int i = 0; i < 2; i++)
        #pragma unroll
        for (int j = 0; j < 8; j++)
            #pragma unroll
            for (int r = 0; r < 4; r++) c[i][j][r] = 0.0f;

    for (int k0 = 0; k0 < CK_HID; k0 += 32) {
        __syncthreads();
        #pragma unroll
        for (int i = 0; i < 4; i++) {
            int e = tid + i * 256;                  // float4 index 0..1023
            int row = e >> 3, kq = (e & 7) << 2;    // A: 128 rows x 32 k
            float4 v = *(const float4*)&A[(size_t)(m0 + row) * CK_HID + k0 + kq];
            *(uint4*)&As[row][kq] =
                make_uint4(f2tf32(v.x), f2tf32(v.y), f2tf32(v.z), f2tf32(v.w));
            int kr = e >> 5, nq = (e & 31) << 2;    // B: 32 k x 128 n
            float4 w = *(const float4*)&B[(size_t)(k0 + kr) * CK_AH + n0 + nq];
            *(uint4*)&Bs[kr][nq] =
                make_uint4(f2tf32(w.x), f2tf32(w.y), f2tf32(w.z), f2tf32(w.w));
        }
        __syncthreads();
        #pragma unroll
        for (int ks = 0; ks < 4; ks++) {
            int kk = ks * 8;
            uint32_t a[2][4], b[8][2];
            #pragma unroll
            for (int i = 0; i < 2; i++) {
                int bm = wm * 32 + i * 16;
                a[i][0] = As[bm + g    ][kk + t];
                a[i][1] = As[bm + g + 8][kk + t];
                a[i][2] = As[bm + g    ][kk + t + 4];
                a[i][3] = As[bm + g + 8][kk + t + 4];
            }
            #pragma unroll
            for (int j = 0; j < 8; j++) {
                int bn = wn * 64 + j * 8;
                b[j][0] = Bs[kk + t    ][bn + g];
                b[j][1] = Bs[kk + t + 4][bn + g];
            }
            #pragma unroll
            for (int i = 0; i < 2; i++)
                #pragma unroll
                for (int j = 0; j < 8; j++)
                    mma_tf32(c[i][j], a[i], b[j]);
        }
    }
    #pragma unroll
    for (int i = 0; i < 2; i++) {
        int r0 = m0 + wm * 32 + i * 16 + g;
        #pragma unroll
        for (int j = 0; j < 8; j++) {
            int col = n0 + wn * 64 + j * 8 + t * 2;
            float b0 = bias ? bias[col]     : 0.0f;
            float b1 = bias ? bias[col + 1] : 0.0f;
            C[(size_t)r0 * CK_AH + col]           = c[i][j][0] + b0;
            C[(size_t)r0 * CK_AH + col + 1]       = c[i][j][1] + b1;
            C[(size_t)(r0 + 8) * CK_AH + col]     = c[i][j][2] + b0;
            C[(size_t)(r0 + 8) * CK_AH + col + 1] = c[i][j][3] + b1;
        }
    }
}

// ---------------- transpose pw_w (AH,HID) -> (HID,AH) -----------------------
__global__ __launch_bounds__(256) void transpose_pw(
    const float* __restrict__ pw, float* __restrict__ pwT)
{
    int idx = blockIdx.x * 256 + threadIdx.x;
    if (idx >= CK_AH * CK_HID) return;
    int o = idx / CK_HID, c = idx % CK_HID;
    pwT[(size_t)c * CK_AH + o] = pw[idx];
}

// ---------------- depthwise conv over seq: out (B,S,HID) --------------------
__global__ __launch_bounds__(256) void dwconv_kernel(
    const float* __restrict__ Kin, const float* __restrict__ dww,
    float* __restrict__ outp)
{
    int idx = blockIdx.x * 256 + threadIdx.x;
    if (idx >= CK_BS * CK_HID) return;
    int c = idx % CK_HID;
    int s = (idx / CK_HID) % CK_S;
    int b = idx / (CK_HID * CK_S);
    float acc = 0.0f;
    #pragma unroll
    for (int t = 0; t < 9; t++) {
        int ss = s + t - 4;
        if (ss >= 0 && ss < CK_S)
            acc += Kin[((size_t)(b * CK_S + ss)) * CK_HID + c] * dww[c * 9 + t];
    }
    outp[idx] = acc;
}

// ---------- conv kernel layer: 8 positions per block (amortize ckW) ---------
__global__ __launch_bounds__(128) void ck_kernel(
    const float* __restrict__ mq, const float* __restrict__ mkc,
    const float* __restrict__ ckW, const float* __restrict__ ckb,
    float* __restrict__ cko)
{
    __shared__ float ca[8][CK_AH];
    __shared__ float o[8][56];
    int p0 = blockIdx.x * 8, tid = threadIdx.x;
    for (int e = tid; e < 8 * CK_AH; e += 128) {
        int p = e / CK_AH, c = e % CK_AH;
        size_t idx = (size_t)(p0 + p) * CK_AH + c;
        ca[p][c] = mq[idx] * mkc[idx];
    }
    __syncthreads();
    if (tid < 54) {
        float acc[8];
        #pragma unroll
        for (int p = 0; p < 8; p++) acc[p] = ckb[tid];
        #pragma unroll 4
        for (int c = 0; c < CK_AH; c++) {
            float w = ckW[c * 54 + tid];
            #pragma unroll
            for (int p = 0; p < 8; p++) acc[p] += ca[p][c] * w;
        }
        #pragma unroll
        for (int p = 0; p < 8; p++) o[p][tid] = acc[p];
    }
    __syncthreads();
    if (tid < 48) {
        int p = tid / 6, h = tid % 6;
        float m = -1e30f;
        #pragma unroll
        for (int k = 0; k < 9; k++) m = fmaxf(m, o[p][h * 9 + k]);
        float e[9]; float s = 0.0f;
        #pragma unroll
        for (int k = 0; k < 9; k++) { e[k] = __expf(o[p][h * 9 + k] - m); s += e[k]; }
        float inv = 1.0f / s;
        #pragma unroll
        for (int k = 0; k < 9; k++)
            cko[(size_t)(p0 + p) * 54 + h * 9 + k] = e[k] * inv;
    }
}

// -------- dynamic-span conv out: sliding window of co x ck -> out[:,384:] ---
__global__ __launch_bounds__(256) void convout_kernel(
    const float* __restrict__ co, const float* __restrict__ cko,
    float* __restrict__ out)
{
    int idx = blockIdx.x * 256 + threadIdx.x;
    if (idx >= CK_BS * CK_AH) return;
    int hd = idx % CK_AH;
    int s  = (idx / CK_AH) % CK_S;
    int b  = idx / (CK_AH * CK_S);
    int h  = hd >> 6;
    const float* ckp = cko + ((size_t)(b * CK_S + s)) * 54 + h * 9;
    float acc = 0.0f;
    #pragma unroll
    for (int k = 0; k < 9; k++) {
        int ss = s + k - 4;
        if (ss >= 0 && ss < CK_S)
            acc += co[((size_t)(b * CK_S + ss)) * CK_AH + hd] * ckp[k];
    }
    out[((size_t)(b * CK_S + s)) * (2 * CK_AH) + CK_AH + hd] = acc;
}

// ---------------- masked softmax of normalized td (per batch) ---------------
__global__ __launch_bounds__(256) void tdsm_kernel(
    const float* __restrict__ td, const int* __restrict__ mask,
    float* __restrict__ out)
{
    __shared__ float red[256];
    int b = blockIdx.x, tid = threadIdx.x;
    float v[4]; float ss = 0.0f;
    #pragma unroll
    for (int t = 0; t < 4; t++) { v[t] = td[b * CK_S + tid + t * 256]; ss += v[t] * v[t]; }
    red[tid] = ss; __syncthreads();
    for (int s = 128; s > 0; s >>= 1) { if (tid < s) red[tid] += red[tid + s]; __syncthreads(); }
    float denom = fmaxf(sqrtf(red[0]), 1e-12f);
    __syncthreads();
    float x[4]; float m = -1e30f;
    #pragma unroll
    for (int t = 0; t < 4; t++) {
        int j = tid + t * 256;
        x[t] = mask[b * CK_S + j] ? (v[t] / denom) : -1e4f;
        m = fmaxf(m, x[t]);
    }
    red[tid] = m; __syncthreads();
    for (int s = 128; s > 0; s >>= 1) { if (tid < s) red[tid] = fmaxf(red[tid], red[tid + s]); __syncthreads(); }
    m = red[0]; __syncthreads();
    float e[4]; float se = 0.0f;
    #pragma unroll
    for (int t = 0; t < 4; t++) { e[t] = __expf(x[t] - m); se += e[t]; }
    red[tid] = se; __syncthreads();
    for (int s = 128; s > 0; s >>= 1) { if (tid < s) red[tid] += red[tid + s]; __syncthreads(); }
    float inv = 1.0f / red[0];
    #pragma unroll
    for (int t = 0; t < 4; t++) out[b * CK_S + tid + t * 256] = e[t] * inv;
}

// ---------------- fused attention with distance decay -----------------------
// One CTA = 16 query rows of one (b,h). KV chunked at 128 rows so smem fits
// 2 CTAs/SM (110 KB): 16 warps resident to hide LDS/MUFU latency.
#define ATTN_CH 128
#define ATTN_SMEM_FLOATS (16*1040 + ATTN_CH*65 + 16*65 + 1040 + 1040)
#define ATTN_SMEM_BYTES  (ATTN_SMEM_FLOATS*4)

__global__ __launch_bounds__(256, 2) void attn_kernel(
    const float* __restrict__ mq, const float* __restrict__ mk,
    const float* __restrict__ mv, const int* __restrict__ mask,
    const float* __restrict__ tdsm, const float* __restrict__ gammas,
    float* __restrict__ out)
{
    extern __shared__ float smem[];
    float* sc  = smem;                    // [16][1040], idx = r*1040 + j + (j>>6)
    float* kv  = smem + 16 * 1040;        // [ATTN_CH][65]
    float* qs  = kv + ATTN_CH * 65;       // [16][65]  (reused as ctx at the end)
    float* amf = qs + 16 * 65;            // [1040] padded mask
    float* tds = amf + 1040;              // [1040] padded td softmax

    int tid = threadIdx.x;
    int blk = blockIdx.x;
    int it  = blk & 63;
    int h   = (blk >> 6) % CK_H;
    int b   = blk / (64 * CK_H);
    int i0  = it * 16;

    for (int e = tid; e < 16 * 64; e += 256) {
        int r = e >> 6, d = e & 63;
        qs[r * 65 + d] = mq[((size_t)(b * CK_S + i0 + r)) * CK_AH + h * CK_D + d] * 0.125f;
    }
    for (int j = tid; j < CK_S; j += 256) {
        int fj = j + (j >> 6);
        amf[fj] = mask[b * CK_S + j] ? 1.0f : 0.0f;
        tds[fj] = tdsm[b * CK_S + j];
    }
    float gamma = -log1pf(expf(gammas[h]));

    // ---- phase 1: scores = (q/8) @ k^T --------------------------------------
    {
        int rg = tid >> 6;   // rows rg+4i
        int kg = tid & 63;   // keys kg, kg+64 within chunk
        for (int c0 = 0; c0 < CK_S; c0 += ATTN_CH) {
            __syncthreads();
            for (int e = tid; e < ATTN_CH * 64; e += 256) {
                int j = e >> 6, d = e & 63;
                kv[j * 65 + d] = mk[((size_t)(b * CK_S + c0 + j)) * CK_AH + h * CK_D + d];
            }
            __syncthreads();
            float acc[4][2];
            #pragma unroll
            for (int i = 0; i < 4; i++) { acc[i][0] = 0.0f; acc[i][1] = 0.0f; }
            #pragma unroll
            for (int d = 0; d < 64; d++) {
                float a[4], kk[2];
                #pragma unroll
                for (int i = 0; i < 4; i++) a[i] = qs[(rg + 4 * i) * 65 + d];
                kk[0] = kv[kg * 65 + d];
                kk[1] = kv[(kg + 64) * 65 + d];
                #pragma unroll
                for (int i = 0; i < 4; i++) {
                    acc[i][0] += a[i] * kk[0];
                    acc[i][1] += a[i] * kk[1];
                }
            }
            #pragma unroll
            for (int i = 0; i < 4; i++)
                #pragma unroll
                for (int j = 0; j < 2; j++) {
                    int gj = c0 + kg + 64 * j;
                    sc[(rg + 4 * i) * 1040 + gj + (gj >> 6)] = acc[i][j];
                }
        }
    }
    __syncthreads();

    // ---- phase 2+3: softmax -> cumsum -> effect -> second softmax ----------
    {
        int r = tid >> 4;
        int l = tid & 15;
        unsigned lane = tid & 31;
        unsigned sub  = lane & 15;
        float* scr = sc + r * 1040 + l * 65;
        const float* amfl = amf + l * 65;
        const float* tdsl = tds + l * 65;
        int irow = i0 + r;

        float ev[64];
        float m = -1e30f;
        #pragma unroll
        for (int t = 0; t < 64; t++) {
            float x = (amfl[t] != 0.0f) ? scr[t] : -1e8f;
            ev[t] = x;
            m = fmaxf(m, x);
        }
        #pragma unroll
        for (int dl = 8; dl >= 1; dl >>= 1)
            m = fmaxf(m, __shfl_xor_sync(0xffffffffu, m, dl));
        float sum = 0.0f;
        #pragma unroll
        for (int t = 0; t < 64; t++) { float p = __expf(ev[t] - m); ev[t] = p; sum += p; }
        #pragma unroll
        for (int dl = 8; dl >= 1; dl >>= 1)
            sum += __shfl_xor_sync(0xffffffffu, sum, dl);
        float inv = 1.0f / sum;
        float c = 0.0f;
        #pragma unroll
        for (int t = 0; t < 64; t++) { c += ev[t] * inv * amfl[t]; ev[t] = c; }
        float x = c;
        #pragma unroll
        for (int dl = 1; dl < 16; dl <<= 1) {
            float v = __shfl_up_sync(0xffffffffu, x, dl);
            if (sub >= (unsigned)dl) x += v;
        }
        float excl = x - c;
        float tot  = __shfl_sync(0xffffffffu, x, (lane & 16) | 15);

        float m2 = -1e30f;
        #pragma unroll
        for (int t = 0; t < 64; t++) {
            float dc = ev[t] + excl;
            int j = l * 64 + t;
            float pos = fabsf((float)(j - irow));
            float ds  = sqrtf(fmaxf((tot - dc) * pos, 0.0f));
            float eff = __expf(ds * gamma);
            eff = fminf(fmaxf(eff, 1e-5f), 1e5f);
            if (j < irow) eff -= tdsl[t];
            float x2 = (amfl[t] != 0.0f) ? scr[t] * eff : -1e8f;
            ev[t] = x2;
            m2 = fmaxf(m2, x2);
        }
        #pragma unroll
        for (int dl = 8; dl >= 1; dl >>= 1)
            m2 = fmaxf(m2, __shfl_xor_sync(0xffffffffu, m2, dl));
        float s2 = 0.0f;
        #pragma unroll
        for (int t = 0; t < 64; t++) { float p = __expf(ev[t] - m2); ev[t] = p; s2 += p; }
        #pragma unroll
        for (int dl = 8; dl >= 1; dl >>= 1)
            s2 += __shfl_xor_sync(0xffffffffu, s2, dl);
        float inv2 = 1.0f / s2;
        #pragma unroll
        for (int t = 0; t < 64; t++) scr[t] = ev[t] * inv2;
    }
    __syncthreads();

    // ---- phase 4: ctx = P @ V ----------------------------------------------
    {
        int rg = tid >> 6;
        int jg = (tid >> 4) & 3;
        int dg = tid & 15;
        float acc[4][4];
        #pragma unroll
        for (int i = 0; i < 4; i++)
            #pragma unroll
            for (int t = 0; t < 4; t++) acc[i][t] = 0.0f;

        for (int c0 = 0; c0 < CK_S; c0 += ATTN_CH) {
            __syncthreads();
            for (int e = tid; e < ATTN_CH * 64; e += 256) {
                int j = e >> 6, d = e & 63;
                kv[j * 65 + d] = mv[((size_t)(b * CK_S + c0 + j)) * CK_AH + h * CK_D + d];
            }
            __syncthreads();
            #pragma unroll 4
            for (int jj = 0; jj < ATTN_CH / 4; jj++) {
                int j  = 4 * jj + jg;
                int gj = c0 + j;
                int fj = gj + (gj >> 6);
                float p[4], v[4];
                #pragma unroll
                for (int i = 0; i < 4; i++) p[i] = sc[(rg + 4 * i) * 1040 + fj];
                #pragma unroll
                for (int t = 0; t < 4; t++) v[t] = kv[j * 65 + dg * 4 + t];
                #pragma unroll
                for (int i = 0; i < 4; i++)
                    #pragma unroll
                    for (int t = 0; t < 4; t++)
                        acc[i][t] += p[i] * v[t];
            }
        }
        __syncthreads();
        float* ctxs = qs;
        for (int g = 0; g < 4; g++) {
            if (jg == g) {
                #pragma unroll
                for (int i = 0; i < 4; i++)
                    #pragma unroll
                    for (int t = 0; t < 4; t++) {
                        int idx = (rg + 4 * i) * 65 + dg * 4 + t;
                        if (g == 0) ctxs[idx] = acc[i][t];
                        else        ctxs[idx] += acc[i][t];
                    }
            }
            __syncthreads();
        }
        for (int e = tid; e < 16 * 64; e += 256) {
            int r = e >> 6, d = e & 63;
            out[((size_t)(b * CK_S + i0 + r)) * (2 * CK_AH) + h * CK_D + d] = ctxs[r * 65 + d];
        }
    }
}

// ---------------------------------------------------------------------------
extern "C" void kernel_launch(void* const* d_in, const int* in_sizes, int n_in,
                              void* d_out, int out_size)
{
    const float* Q    = (const float*)d_in[0];
    const float* K    = (const float*)d_in[1];
    const float* V    = (const float*)d_in[2];
    const float* td   = (const float*)d_in[3];
    const int*   mask = (const int*)  d_in[4];
    const float* Wq   = (const float*)d_in[5];
    const float* Wk   = (const float*)d_in[6];
    const float* Wv   = (const float*)d_in[7];
    const float* dww  = (const float*)d_in[8];
    const float* pww  = (const float*)d_in[9];
    const float* sepb = (const float*)d_in[10];
    const float* ckW  = (const float*)d_in[11];
    const float* ckb  = (const float*)d_in[12];
    const float* coW  = (const float*)d_in[13];
    const float* cob  = (const float*)d_in[14];
    const float* gam  = (const float*)d_in[15];
    float* out = (float*)d_out;

    float *mq, *mk, *mv, *mkc, *co, *dw, *pwT, *cko, *tds;
    cudaGetSymbolAddress((void**)&mq,  g_mq);
    cudaGetSymbolAddress((void**)&mk,  g_mk);
    cudaGetSymbolAddress((void**)&mv,  g_mv);
    cudaGetSymbolAddress((void**)&mkc, g_mkc);
    cudaGetSymbolAddress((void**)&co,  g_co);
    cudaGetSymbolAddress((void**)&dw,  g_dw);
    cudaGetSymbolAddress((void**)&pwT, g_pwT);
    cudaGetSymbolAddress((void**)&cko, g_ckb);
    cudaGetSymbolAddress((void**)&tds, g_tds);

    transpose_pw<<<(CK_AH * CK_HID + 255) / 256, 256>>>(pww, pwT);
    dwconv_kernel<<<(CK_BS * CK_HID + 255) / 256, 256>>>(K, dww, dw);

    dim3 ggrid(CK_AH / 128, CK_BS / 128, 5);   // (3, 32, 5)
    gemm5_tf32<<<ggrid, 256>>>(Q, K, V, dw, Wq, Wk, Wv, coW, pwT,
                               cob, sepb, mq, mk, mv, co, mkc);

    ck_kernel<<<CK_BS / 8, 128>>>(mq, mkc, ckW, ckb, cko);
    convout_kernel<<<(CK_BS * CK_AH + 255) / 256, 256>>>(co, cko, out);
    tdsm_kernel<<<CK_B, 256>>>(td, mask, tds);

    cudaFuncSetAttribute(attn_kernel, cudaFuncAttributeMaxDynamicSharedMemorySize,
                         ATTN_SMEM_BYTES);
    attn_kernel<<<CK_B * CK_H * (CK_S / 16), 256, ATTN_SMEM_BYTES>>>(
        mq, mk, mv, mask, tds, gam, out);
}

// round 3
// speedup vs baseline: 2.4056x; 1.2548x over previous
#include <cuda_runtime.h>
#include <math.h>
#include <stdint.h>

#define CK_B   4
#define CK_S   1024
#define CK_HID 768
#define CK_H   6
#define CK_D   64
#define CK_AH  384
#define CK_KS  9
#define CK_BS  (CK_B*CK_S)

// ---------------- scratch (device globals; no allocation allowed) ----------
__device__ float g_mq [CK_BS*CK_AH];
__device__ float g_mk [CK_BS*CK_AH];
__device__ float g_mv [CK_BS*CK_AH];
__device__ float g_mkc[CK_BS*CK_AH];
__device__ float g_co [CK_BS*CK_AH];
__device__ float g_dw [CK_BS*CK_HID];
__device__ float g_pwT[CK_HID*CK_AH];
__device__ float g_ckl[CK_BS*64];
__device__ float g_cko[CK_BS*CK_H*CK_KS];
__device__ float g_tds[CK_BS];

// ---------------- tf32 helpers ---------------------------------------------
__device__ __forceinline__ uint32_t f2tf32(float f) {
    uint32_t u;
    asm("cvt.rna.tf32.f32 %0, %1;" : "=r"(u) : "f"(f));
    return u;
}
__device__ __forceinline__ void mma_tf32(float c[4], const uint32_t a[4],
                                         const uint32_t b[2]) {
    asm volatile(
        "mma.sync.aligned.m16n8k8.row.col.f32.tf32.tf32.f32 "
        "{%0,%1,%2,%3}, {%4,%5,%6,%7}, {%8,%9}, {%0,%1,%2,%3};"
        : "+f"(c[0]), "+f"(c[1]), "+f"(c[2]), "+f"(c[3])
        : "r"(a[0]), "r"(a[1]), "r"(a[2]), "r"(a[3]), "r"(b[0]), "r"(b[1]));
}

// ---------------- batched TF32 tensor-core GEMM ----------------------------
__global__ __launch_bounds__(256, 2) void gemm5_tf32(
    const float* __restrict__ Q, const float* __restrict__ Kin,
    const float* __restrict__ V, const float* __restrict__ dw,
    const float* __restrict__ Wq, const float* __restrict__ Wk,
    const float* __restrict__ Wv, const float* __restrict__ coW,
    const float* __restrict__ pwT,
    const float* __restrict__ cob, const float* __restrict__ sepb,
    float* __restrict__ mq, float* __restrict__ mk, float* __restrict__ mv,
    float* __restrict__ co, float* __restrict__ mkc)
{
    const float *A, *B, *bias; float* C;
    switch (blockIdx.z) {
        case 0:  A = Q;   B = Wq;  bias = nullptr; C = mq;  break;
        case 1:  A = Kin; B = Wk;  bias = nullptr; C = mk;  break;
        case 2:  A = V;   B = Wv;  bias = nullptr; C = mv;  break;
        case 3:  A = V;   B = coW; bias = cob;     C = co;  break;
        default: A = dw;  B = pwT; bias = sepb;    C = mkc; break;
    }
    __shared__ uint32_t As[128][36];
    __shared__ uint32_t Bs[32][132];

    int tid  = threadIdx.x;
    int m0   = blockIdx.y * 128;
    int n0   = blockIdx.x * 128;
    int lane = tid & 31;
    int g    = lane >> 2;
    int t    = lane & 3;
    int warp = tid >> 5;
    int wm   = warp >> 1;
    int wn   = warp & 1;

    float c[2][8][4];
    #pragma unroll
    for (int i = 0; i < 2; i++)
        #pragma unroll
        for (int j = 0; j < 8; j++)
            #pragma unroll
            for (int r = 0; r < 4; r++) c[i][j][r] = 0.0f;

    for (int k0 = 0; k0 < CK_HID; k0 += 32) {
        __syncthreads();
        #pragma unroll
        for (int i = 0; i < 4; i++) {
            int e = tid + i * 256;
            int row = e >> 3, kq = (e & 7) << 2;
            float4 v = *(const float4*)&A[(size_t)(m0 + row) * CK_HID + k0 + kq];
            *(uint4*)&As[row][kq] =
                make_uint4(f2tf32(v.x), f2tf32(v.y), f2tf32(v.z), f2tf32(v.w));
            int kr = e >> 5, nq = (e & 31) << 2;
            float4 w = *(const float4*)&B[(size_t)(k0 + kr) * CK_AH + n0 + nq];
            *(uint4*)&Bs[kr][nq] =
                make_uint4(f2tf32(w.x), f2tf32(w.y), f2tf32(w.z), f2tf32(w.w));
        }
        __syncthreads();
        #pragma unroll
        for (int ks = 0; ks < 4; ks++) {
            int kk = ks * 8;
            uint32_t a[2][4], b[8][2];
            #pragma unroll
            for (int i = 0; i < 2; i++) {
                int bm = wm * 32 + i * 16;
                a[i][0] = As[bm + g    ][kk + t];
                a[i][1] = As[bm + g + 8][kk + t];
                a[i][2] = As[bm + g    ][kk + t + 4];
                a[i][3] = As[bm + g + 8][kk + t + 4];
            }
            #pragma unroll
            for (int j = 0; j < 8; j++) {
                int bn = wn * 64 + j * 8;
                b[j][0] = Bs[kk + t    ][bn + g];
                b[j][1] = Bs[kk + t + 4][bn + g];
            }
            #pragma unroll
            for (int i = 0; i < 2; i++)
                #pragma unroll
                for (int j = 0; j < 8; j++)
                    mma_tf32(c[i][j], a[i], b[j]);
        }
    }
    #pragma unroll
    for (int i = 0; i < 2; i++) {
        int r0 = m0 + wm * 32 + i * 16 + g;
        #pragma unroll
        for (int j = 0; j < 8; j++) {
            int col = n0 + wn * 64 + j * 8 + t * 2;
            float b0 = bias ? bias[col]     : 0.0f;
            float b1 = bias ? bias[col + 1] : 0.0f;
            C[(size_t)r0 * CK_AH + col]           = c[i][j][0] + b0;
            C[(size_t)r0 * CK_AH + col + 1]       = c[i][j][1] + b1;
            C[(size_t)(r0 + 8) * CK_AH + col]     = c[i][j][2] + b0;
            C[(size_t)(r0 + 8) * CK_AH + col + 1] = c[i][j][3] + b1;
        }
    }
}

// ---------------- transpose pw_w (AH,HID) -> (HID,AH) -----------------------
__global__ __launch_bounds__(256) void transpose_pw(
    const float* __restrict__ pw, float* __restrict__ pwT)
{
    int idx = blockIdx.x * 256 + threadIdx.x;
    if (idx >= CK_AH * CK_HID) return;
    int o = idx / CK_HID, c = idx % CK_HID;
    pwT[(size_t)c * CK_AH + o] = pw[idx];
}

// ---------------- depthwise conv over seq: out (B,S,HID) --------------------
__global__ __launch_bounds__(256) void dwconv_kernel(
    const float* __restrict__ Kin, const float* __restrict__ dww,
    float* __restrict__ outp)
{
    int idx = blockIdx.x * 256 + threadIdx.x;
    if (idx >= CK_BS * CK_HID) return;
    int c = idx % CK_HID;
    int s = (idx / CK_HID) % CK_S;
    int b = idx / (CK_HID * CK_S);
    float acc = 0.0f;
    #pragma unroll
    for (int t = 0; t < 9; t++) {
        int ss = s + t - 4;
        if (ss >= 0 && ss < CK_S)
            acc += Kin[((size_t)(b * CK_S + ss)) * CK_HID + c] * dww[c * 9 + t];
    }
    outp[idx] = acc;
}

// ---------- ck logits as TF32 MMA GEMM: (mq*mkc)(4096x384) @ ckW(384x54) ----
__global__ __launch_bounds__(256) void ckgemm_tf32(
    const float* __restrict__ mq, const float* __restrict__ mkc,
    const float* __restrict__ ckW, float* __restrict__ ckl)
{
    __shared__ uint32_t As[128][76];
    __shared__ uint32_t Bs[64][72];
    int tid = threadIdx.x;
    int warp = tid >> 5, lane = tid & 31;
    int g = lane >> 2, t = lane & 3;
    int m0 = blockIdx.x * 128;

    float c[8][4];
    #pragma unroll
    for (int nt = 0; nt < 8; nt++)
        #pragma unroll
        for (int r = 0; r < 4; r++) c[nt][r] = 0.0f;

    for (int k0 = 0; k0 < CK_AH; k0 += 64) {
        __syncthreads();
        #pragma unroll
        for (int i = 0; i < 8; i++) {
            int e4 = tid + i * 256;
            int row = e4 >> 4, d4 = (e4 & 15) << 2;
            float4 a4 = *(const float4*)&mq[(size_t)(m0 + row) * CK_AH + k0 + d4];
            float4 b4 = *(const float4*)&mkc[(size_t)(m0 + row) * CK_AH + k0 + d4];
            uint4 u;
            u.x = f2tf32(a4.x * b4.x); u.y = f2tf32(a4.y * b4.y);
            u.z = f2tf32(a4.z * b4.z); u.w = f2tf32(a4.w * b4.w);
            *(uint4*)&As[row][d4] = u;
        }
        for (int e = tid; e < 64 * 72; e += 256) {
            int kc = e / 72, o = e % 72;
            float v = (o < 54) ? ckW[(size_t)(k0 + kc) * 54 + o] : 0.0f;
            Bs[kc][o] = f2tf32(v);
        }
        __syncthreads();
        #pragma unroll
        for (int kk = 0; kk < 64; kk += 8) {
            uint32_t a[4];
            int mb = warp * 16;
            a[0] = As[mb + g    ][kk + t];
            a[1] = As[mb + g + 8][kk + t];
            a[2] = As[mb + g    ][kk + t + 4];
            a[3] = As[mb + g + 8][kk + t + 4];
            #pragma unroll
            for (int nt = 0; nt < 8; nt++) {
                uint32_t bb[2];
                bb[0] = Bs[kk + t    ][nt * 8 + g];
                bb[1] = Bs[kk + t + 4][nt * 8 + g];
                mma_tf32(c[nt], a, bb);
            }
        }
    }
    #pragma unroll
    for (int nt = 0; nt < 8; nt++) {
        int colb = nt * 8 + t * 2;
        int r = m0 + warp * 16 + g;
        ckl[(size_t)r * 64 + colb]           = c[nt][0];
        ckl[(size_t)r * 64 + colb + 1]       = c[nt][1];
        ckl[(size_t)(r + 8) * 64 + colb]     = c[nt][2];
        ckl[(size_t)(r + 8) * 64 + colb + 1] = c[nt][3];
    }
}

// ---------- softmax over KS=9 per (pos, head) --------------------------------
__global__ __launch_bounds__(256) void ck_softmax(
    const float* __restrict__ ckl, const float* __restrict__ ckb,
    float* __restrict__ cko)
{
    int gid = blockIdx.x * 256 + threadIdx.x;
    if (gid >= CK_BS * CK_H) return;
    int p = gid / CK_H, h = gid % CK_H;
    float v[9]; float m = -1e30f;
    #pragma unroll
    for (int k = 0; k < 9; k++) {
        v[k] = ckl[(size_t)p * 64 + h * 9 + k] + ckb[h * 9 + k];
        m = fmaxf(m, v[k]);
    }
    float s = 0.0f;
    #pragma unroll
    for (int k = 0; k < 9; k++) { v[k] = __expf(v[k] - m); s += v[k]; }
    float inv = 1.0f / s;
    #pragma unroll
    for (int k = 0; k < 9; k++)
        cko[(size_t)p * 54 + h * 9 + k] = v[k] * inv;
}

// -------- dynamic-span conv out: sliding window of co x ck -> out[:,384:] ---
__global__ __launch_bounds__(256) void convout_kernel(
    const float* __restrict__ co, const float* __restrict__ cko,
    float* __restrict__ out)
{
    int idx = blockIdx.x * 256 + threadIdx.x;
    if (idx >= CK_BS * CK_AH) return;
    int hd = idx % CK_AH;
    int s  = (idx / CK_AH) % CK_S;
    int b  = idx / (CK_AH * CK_S);
    int h  = hd >> 6;
    const float* ckp = cko + ((size_t)(b * CK_S + s)) * 54 + h * 9;
    float acc = 0.0f;
    #pragma unroll
    for (int k = 0; k < 9; k++) {
        int ss = s + k - 4;
        if (ss >= 0 && ss < CK_S)
            acc += co[((size_t)(b * CK_S + ss)) * CK_AH + hd] * ckp[k];
    }
    out[((size_t)(b * CK_S + s)) * (2 * CK_AH) + CK_AH + hd] = acc;
}

// ---------------- masked softmax of normalized td (per batch) ---------------
__global__ __launch_bounds__(256) void tdsm_kernel(
    const float* __restrict__ td, const int* __restrict__ mask,
    float* __restrict__ out)
{
    __shared__ float red[256];
    int b = blockIdx.x, tid = threadIdx.x;
    float v[4]; float ss = 0.0f;
    #pragma unroll
    for (int t = 0; t < 4; t++) { v[t] = td[b * CK_S + tid + t * 256]; ss += v[t] * v[t]; }
    red[tid] = ss; __syncthreads();
    for (int s = 128; s > 0; s >>= 1) { if (tid < s) red[tid] += red[tid + s]; __syncthreads(); }
    float denom = fmaxf(sqrtf(red[0]), 1e-12f);
    __syncthreads();
    float x[4]; float m = -1e30f;
    #pragma unroll
    for (int t = 0; t < 4; t++) {
        int j = tid + t * 256;
        x[t] = mask[b * CK_S + j] ? (v[t] / denom) : -1e4f;
        m = fmaxf(m, x[t]);
    }
    red[tid] = m; __syncthreads();
    for (int s = 128; s > 0; s >>= 1) { if (tid < s) red[tid] = fmaxf(red[tid], red[tid + s]); __syncthreads(); }
    m = red[0]; __syncthreads();
    float e[4]; float se = 0.0f;
    #pragma unroll
    for (int t = 0; t < 4; t++) { e[t] = __expf(x[t] - m); se += e[t]; }
    red[tid] = se; __syncthreads();
    for (int s = 128; s > 0; s >>= 1) { if (tid < s) red[tid] += red[tid + s]; __syncthreads(); }
    float inv = 1.0f / red[0];
    #pragma unroll
    for (int t = 0; t < 4; t++) out[b * CK_S + tid + t * 256] = e[t] * inv;
}

// ---------------- fused attention: 3xTF32 MMA phases 1 & 4 ------------------
#define ATTN_SCP 1044   // sc row stride (1044 % 32 == 20 -> conflict-free frags)
#define ATTN_CH  64
#define ATTN_KVP 76     // 76 % 32 == 12
#define ATTN_QSP 24
#define ATTN_SMEM_FLOATS (16*ATTN_SCP + ATTN_CH*ATTN_KVP + 64*ATTN_QSP + 1040 + 1040)
#define ATTN_SMEM_BYTES  (ATTN_SMEM_FLOATS*4)

__global__ __launch_bounds__(256, 2) void attn_kernel(
    const float* __restrict__ mq, const float* __restrict__ mk,
    const float* __restrict__ mv, const int* __restrict__ mask,
    const float* __restrict__ tdsm, const float* __restrict__ gammas,
    float* __restrict__ out)
{
    extern __shared__ float smem[];
    float* sc  = smem;                         // [16][1044], f(j)=j+(j>>6)
    float* kv  = smem + 16 * ATTN_SCP;         // [64][76] fp32 K/V chunk
    float* qs  = kv + ATTN_CH * ATTN_KVP;      // [64][24] fp32 q transposed [d][i]
    float* amf = qs + 64 * ATTN_QSP;           // [1040]
    float* tds = amf + 1040;                   // [1040]

    int tid  = threadIdx.x;
    int warp = tid >> 5, lane = tid & 31;
    int g = lane >> 2, t = lane & 3;
    int blk = blockIdx.x;
    int it  = blk & 63;
    int h   = (blk >> 6) % CK_H;
    int b   = blk / (64 * CK_H);
    int i0  = it * 16;

    for (int e = tid; e < 16 * 64; e += 256) {
        int r = e >> 6, d = e & 63;
        qs[d * ATTN_QSP + r] =
            mq[((size_t)(b * CK_S + i0 + r)) * CK_AH + h * CK_D + d] * 0.125f;
    }
    for (int j = tid; j < CK_S; j += 256) {
        int fj = j + (j >> 6);
        amf[fj] = mask[b * CK_S + j] ? 1.0f : 0.0f;
        tds[fj] = tdsm[b * CK_S + j];
    }
    float gamma = -log1pf(expf(gammas[h]));

    // ---- phase 1: scores^T = K @ q^T via 3xTF32 mma ------------------------
    {
        int jg = warp >> 1;            // 16-key subtile within 64-chunk
        int n0 = (warp & 1) * 8;       // 8 query rows
        for (int c0 = 0; c0 < CK_S; c0 += ATTN_CH) {
            __syncthreads();
            #pragma unroll
            for (int i = 0; i < 4; i++) {
                int e4 = tid + i * 256;
                int j = e4 >> 4, d4 = (e4 & 15) << 2;
                float4 v = *(const float4*)
                    &mk[((size_t)(b * CK_S + c0 + j)) * CK_AH + h * CK_D + d4];
                *(float4*)&kv[j * ATTN_KVP + d4] = v;
            }
            __syncthreads();
            float c[4] = {0.f, 0.f, 0.f, 0.f};
            int jb = jg * 16;
            #pragma unroll
            for (int kk = 0; kk < 64; kk += 8) {
                float af[4], bf[2];
                af[0] = kv[(jb + g    ) * ATTN_KVP + kk + t];
                af[1] = kv[(jb + g + 8) * ATTN_KVP + kk + t];
                af[2] = kv[(jb + g    ) * ATTN_KVP + kk + t + 4];
                af[3] = kv[(jb + g + 8) * ATTN_KVP + kk + t + 4];
                bf[0] = qs[(kk + t    ) * ATTN_QSP + n0 + g];
                bf[1] = qs[(kk + t + 4) * ATTN_QSP + n0 + g];
                uint32_t ah[4], al[4], bh[2], bl[2];
                #pragma unroll
                for (int q = 0; q < 4; q++) {
                    ah[q] = f2tf32(af[q]);
                    al[q] = f2tf32(af[q] - __uint_as_float(ah[q]));
                }
                #pragma unroll
                for (int q = 0; q < 2; q++) {
                    bh[q] = f2tf32(bf[q]);
                    bl[q] = f2tf32(bf[q] - __uint_as_float(bh[q]));
                }
                mma_tf32(c, al, bh);
                mma_tf32(c, ah, bl);
                mma_tf32(c, ah, bh);
            }
            #pragma unroll
            for (int half = 0; half < 2; half++)
                #pragma unroll
                for (int e = 0; e < 2; e++) {
                    int jglob = c0 + jb + g + 8 * half;
                    sc[(n0 + t * 2 + e) * ATTN_SCP + jglob + (jglob >> 6)] =
                        c[2 * half + e];
                }
        }
    }
    __syncthreads();

    // ---- phase 2+3: softmax -> cumsum -> effect -> second softmax ----------
    {
        int r = tid >> 4;
        int l = tid & 15;
        unsigned ln  = tid & 31;
        unsigned sub = ln & 15;
        float* scr = sc + r * ATTN_SCP + l * 65;
        const float* amfl = amf + l * 65;
        const float* tdsl = tds + l * 65;
        int irow = i0 + r;

        float ev[64];
        float m = -1e30f;
        #pragma unroll
        for (int k = 0; k < 64; k++) {
            float x = (amfl[k] != 0.0f) ? scr[k] : -1e8f;
            ev[k] = x;
            m = fmaxf(m, x);
        }
        #pragma unroll
        for (int dl = 8; dl >= 1; dl >>= 1)
            m = fmaxf(m, __shfl_xor_sync(0xffffffffu, m, dl));
        float sum = 0.0f;
        #pragma unroll
        for (int k = 0; k < 64; k++) { float p = __expf(ev[k] - m); ev[k] = p; sum += p; }
        #pragma unroll
        for (int dl = 8; dl >= 1; dl >>= 1)
            sum += __shfl_xor_sync(0xffffffffu, sum, dl);
        float inv = 1.0f / sum;
        float cum = 0.0f;
        #pragma unroll
        for (int k = 0; k < 64; k++) { cum += ev[k] * inv * amfl[k]; ev[k] = cum; }
        float x = cum;
        #pragma unroll
        for (int dl = 1; dl < 16; dl <<= 1) {
            float v = __shfl_up_sync(0xffffffffu, x, dl);
            if (sub >= (unsigned)dl) x += v;
        }
        float excl = x - cum;
        float tot  = __shfl_sync(0xffffffffu, x, (ln & 16) | 15);

        float m2 = -1e30f;
        #pragma unroll
        for (int k = 0; k < 64; k++) {
            float dc = ev[k] + excl;
            int j = l * 64 + k;
            float pos = fabsf((float)(j - irow));
            float ds  = sqrtf(fmaxf((tot - dc) * pos, 0.0f));
            float eff = __expf(ds * gamma);
            eff = fminf(fmaxf(eff, 1e-5f), 1e5f);
            if (j < irow) eff -= tdsl[k];
            float x2 = (amfl[k] != 0.0f) ? scr[k] * eff : -1e8f;
            ev[k] = x2;
            m2 = fmaxf(m2, x2);
        }
        #pragma unroll
        for (int dl = 8; dl >= 1; dl >>= 1)
            m2 = fmaxf(m2, __shfl_xor_sync(0xffffffffu, m2, dl));
        float s2 = 0.0f;
        #pragma unroll
        for (int k = 0; k < 64; k++) { float p = __expf(ev[k] - m2); ev[k] = p; s2 += p; }
        #pragma unroll
        for (int dl = 8; dl >= 1; dl >>= 1)
            s2 += __shfl_xor_sync(0xffffffffu, s2, dl);
        float inv2 = 1.0f / s2;
        #pragma unroll
        for (int k = 0; k < 64; k++) scr[k] = ev[k] * inv2;
    }

    // ---- phase 4: ctx = P @ V via 3xTF32 mma (warp owns 8 d-cols) ----------
    {
        int n0 = warp * 8;
        float c[4] = {0.f, 0.f, 0.f, 0.f};
        for (int c0 = 0; c0 < CK_S; c0 += ATTN_CH) {
            __syncthreads();
            #pragma unroll
            for (int i = 0; i < 4; i++) {
                int e4 = tid + i * 256;
                int j = e4 >> 4, d4 = (e4 & 15) << 2;
                float4 v = *(const float4*)
                    &mv[((size_t)(b * CK_S + c0 + j)) * CK_AH + h * CK_D + d4];
                *(float4*)&kv[j * ATTN_KVP + d4] = v;
            }
            __syncthreads();
            int cbase = c0 + (c0 >> 6);
            #pragma unroll
            for (int kk = 0; kk < 64; kk += 8) {
                float af[4], bf[2];
                int f0 = cbase + kk + t, f1 = f0 + 4;
                af[0] = sc[(g    ) * ATTN_SCP + f0];
                af[1] = sc[(g + 8) * ATTN_SCP + f0];
                af[2] = sc[(g    ) * ATTN_SCP + f1];
                af[3] = sc[(g + 8) * ATTN_SCP + f1];
                bf[0] = kv[(kk + t    ) * ATTN_KVP + n0 + g];
                bf[1] = kv[(kk + t + 4) * ATTN_KVP + n0 + g];
                uint32_t ah[4], al[4], bh[2], bl[2];
                #pragma unroll
                for (int q = 0; q < 4; q++) {
                    ah[q] = f2tf32(af[q]);
                    al[q] = f2tf32(af[q] - __uint_as_float(ah[q]));
                }
                #pragma unroll
                for (int q = 0; q < 2; q++) {
                    bh[q] = f2tf32(bf[q]);
                    bl[q] = f2tf32(bf[q] - __uint_as_float(bh[q]));
                }
                mma_tf32(c, al, bh);
                mma_tf32(c, ah, bl);
                mma_tf32(c, ah, bh);
            }
        }
        #pragma unroll
        for (int half = 0; half < 2; half++) {
            int r = i0 + g + 8 * half;
            float* op = out + ((size_t)(b * CK_S + r)) * (2 * CK_AH)
                            + h * CK_D + n0 + t * 2;
            op[0] = c[2 * half + 0];
            op[1] = c[2 * half + 1];
        }
    }
}

// ---------------------------------------------------------------------------
extern "C" void kernel_launch(void* const* d_in, const int* in_sizes, int n_in,
                              void* d_out, int out_size)
{
    const float* Q    = (const float*)d_in[0];
    const float* K    = (const float*)d_in[1];
    const float* V    = (const float*)d_in[2];
    const float* td   = (const float*)d_in[3];
    const int*   mask = (const int*)  d_in[4];
    const float* Wq   = (const float*)d_in[5];
    const float* Wk   = (const float*)d_in[6];
    const float* Wv   = (const float*)d_in[7];
    const float* dww  = (const float*)d_in[8];
    const float* pww  = (const float*)d_in[9];
    const float* sepb = (const float*)d_in[10];
    const float* ckW  = (const float*)d_in[11];
    const float* ckb  = (const float*)d_in[12];
    const float* coW  = (const float*)d_in[13];
    const float* cob  = (const float*)d_in[14];
    const float* gam  = (const float*)d_in[15];
    float* out = (float*)d_out;

    float *mq, *mk, *mv, *mkc, *co, *dw, *pwT, *ckl, *cko, *tds;
    cudaGetSymbolAddress((void**)&mq,  g_mq);
    cudaGetSymbolAddress((void**)&mk,  g_mk);
    cudaGetSymbolAddress((void**)&mv,  g_mv);
    cudaGetSymbolAddress((void**)&mkc, g_mkc);
    cudaGetSymbolAddress((void**)&co,  g_co);
    cudaGetSymbolAddress((void**)&dw,  g_dw);
    cudaGetSymbolAddress((void**)&pwT, g_pwT);
    cudaGetSymbolAddress((void**)&ckl, g_ckl);
    cudaGetSymbolAddress((void**)&cko, g_cko);
    cudaGetSymbolAddress((void**)&tds, g_tds);

    transpose_pw<<<(CK_AH * CK_HID + 255) / 256, 256>>>(pww, pwT);
    dwconv_kernel<<<(CK_BS * CK_HID + 255) / 256, 256>>>(K, dww, dw);

    dim3 ggrid(CK_AH / 128, CK_BS / 128, 5);
    gemm5_tf32<<<ggrid, 256>>>(Q, K, V, dw, Wq, Wk, Wv, coW, pwT,
                               cob, sepb, mq, mk, mv, co, mkc);

    ckgemm_tf32<<<CK_BS / 128, 256>>>(mq, mkc, ckW, ckl);
    ck_softmax<<<(CK_BS * CK_H + 255) / 256, 256>>>(ckl, ckb, cko);
    convout_kernel<<<(CK_BS * CK_AH + 255) / 256, 256>>>(co, cko, out);
    tdsm_kernel<<<CK_B, 256>>>(td, mask, tds);

    cudaFuncSetAttribute(attn_kernel, cudaFuncAttributeMaxDynamicSharedMemorySize,
                         ATTN_SMEM_BYTES);
    attn_kernel<<<CK_B * CK_H * (CK_S / 16), 256, ATTN_SMEM_BYTES>>>(
        mq, mk, mv, mask, tds, gam, out);
}

// round 6
// speedup vs baseline: 2.6656x; 1.1081x over previous
#include <cuda_runtime.h>
#include <math.h>
#include <stdint.h>

#define CK_B   4
#define CK_S   1024
#define CK_HID 768
#define CK_H   6
#define CK_D   64
#define CK_AH  384
#define CK_KS  9
#define CK_BS  (CK_B*CK_S)

// ---------------- scratch (device globals; no allocation allowed) ----------
__device__ float g_mq [CK_BS*CK_AH];
__device__ float g_mk [CK_BS*CK_AH];
__device__ float g_mv [CK_BS*CK_AH];
__device__ float g_mkc[CK_BS*CK_AH];
__device__ float g_co [CK_BS*CK_AH];
__device__ float g_dw [CK_BS*CK_HID];
__device__ float g_pwT[CK_HID*CK_AH];
__device__ float g_ckl[CK_BS*64];
__device__ float g_cko[CK_BS*CK_H*CK_KS];
__device__ float g_tds[CK_BS];

// ---------------- tf32 helpers ---------------------------------------------
__device__ __forceinline__ uint32_t f2tf32(float f) {
    uint32_t u;
    asm("cvt.rna.tf32.f32 %0, %1;" : "=r"(u) : "f"(f));
    return u;
}
__device__ __forceinline__ void mma_tf32(float c[4], const uint32_t a[4],
                                         const uint32_t b[2]) {
    asm volatile(
        "mma.sync.aligned.m16n8k8.row.col.f32.tf32.tf32.f32 "
        "{%0,%1,%2,%3}, {%4,%5,%6,%7}, {%8,%9}, {%0,%1,%2,%3};"
        : "+f"(c[0]), "+f"(c[1]), "+f"(c[2]), "+f"(c[3])
        : "r"(a[0]), "r"(a[1]), "r"(a[2]), "r"(a[3]), "r"(b[0]), "r"(b[1]));
}

// ---------------- batched TF32 tensor-core GEMM ----------------------------
__global__ __launch_bounds__(256, 2) void gemm5_tf32(
    const float* __restrict__ Q, const float* __restrict__ Kin,
    const float* __restrict__ V, const float* __restrict__ dw,
    const float* __restrict__ Wq, const float* __restrict__ Wk,
    const float* __restrict__ Wv, const float* __restrict__ coW,
    const float* __restrict__ pwT,
    const float* __restrict__ cob, const float* __restrict__ sepb,
    float* __restrict__ mq, float* __restrict__ mk, float* __restrict__ mv,
    float* __restrict__ co, float* __restrict__ mkc)
{
    const float *A, *B, *bias; float* C;
    switch (blockIdx.z) {
        case 0:  A = Q;   B = Wq;  bias = nullptr; C = mq;  break;
        case 1:  A = Kin; B = Wk;  bias = nullptr; C = mk;  break;
        case 2:  A = V;   B = Wv;  bias = nullptr; C = mv;  break;
        case 3:  A = V;   B = coW; bias = cob;     C = co;  break;
        default: A = dw;  B = pwT; bias = sepb;    C = mkc; break;
    }
    __shared__ uint32_t As[128][36];
    __shared__ uint32_t Bs[32][132];

    int tid  = threadIdx.x;
    int m0   = blockIdx.y * 128;
    int n0   = blockIdx.x * 128;
    int lane = tid & 31;
    int g    = lane >> 2;
    int t    = lane & 3;
    int warp = tid >> 5;
    int wm   = warp >> 1;
    int wn   = warp & 1;

    float c[2][8][4];
    #pragma unroll
    for (int i = 0; i < 2; i++)
        #pragma unroll
        for (int j = 0; j < 8; j++)
            #pragma unroll
            for (int r = 0; r < 4; r++) c[i][j][r] = 0.0f;

    for (int k0 = 0; k0 < CK_HID; k0 += 32) {
        __syncthreads();
        #pragma unroll
        for (int i = 0; i < 4; i++) {
            int e = tid + i * 256;
            int row = e >> 3, kq = (e & 7) << 2;
            float4 v = *(const float4*)&A[(size_t)(m0 + row) * CK_HID + k0 + kq];
            *(uint4*)&As[row][kq] =
                make_uint4(f2tf32(v.x), f2tf32(v.y), f2tf32(v.z), f2tf32(v.w));
            int kr = e >> 5, nq = (e & 31) << 2;
            float4 w = *(const float4*)&B[(size_t)(k0 + kr) * CK_AH + n0 + nq];
            *(uint4*)&Bs[kr][nq] =
                make_uint4(f2tf32(w.x), f2tf32(w.y), f2tf32(w.z), f2tf32(w.w));
        }
        __syncthreads();
        #pragma unroll
        for (int ks = 0; ks < 4; ks++) {
            int kk = ks * 8;
            uint32_t a[2][4], b[8][2];
            #pragma unroll
            for (int i = 0; i < 2; i++) {
                int bm = wm * 32 + i * 16;
                a[i][0] = As[bm + g    ][kk + t];
                a[i][1] = As[bm + g + 8][kk + t];
                a[i][2] = As[bm + g    ][kk + t + 4];
                a[i][3] = As[bm + g + 8][kk + t + 4];
            }
            #pragma unroll
            for (int j = 0; j < 8; j++) {
                int bn = wn * 64 + j * 8;
                b[j][0] = Bs[kk + t    ][bn + g];
                b[j][1] = Bs[kk + t + 4][bn + g];
            }
            #pragma unroll
            for (int i = 0; i < 2; i++)
                #pragma unroll
                for (int j = 0; j < 8; j++)
                    mma_tf32(c[i][j], a[i], b[j]);
        }
    }
    #pragma unroll
    for (int i = 0; i < 2; i++) {
        int r0 = m0 + wm * 32 + i * 16 + g;
        #pragma unroll
        for (int j = 0; j < 8; j++) {
            int col = n0 + wn * 64 + j * 8 + t * 2;
            float b0 = bias ? bias[col]     : 0.0f;
            float b1 = bias ? bias[col + 1] : 0.0f;
            C[(size_t)r0 * CK_AH + col]           = c[i][j][0] + b0;
            C[(size_t)r0 * CK_AH + col + 1]       = c[i][j][1] + b1;
            C[(size_t)(r0 + 8) * CK_AH + col]     = c[i][j][2] + b0;
            C[(size_t)(r0 + 8) * CK_AH + col + 1] = c[i][j][3] + b1;
        }
    }
}

// ---------------- transpose pw_w (AH,HID) -> (HID,AH) -----------------------
__global__ __launch_bounds__(256) void transpose_pw(
    const float* __restrict__ pw, float* __restrict__ pwT)
{
    int idx = blockIdx.x * 256 + threadIdx.x;
    if (idx >= CK_AH * CK_HID) return;
    int o = idx / CK_HID, c = idx % CK_HID;
    pwT[(size_t)c * CK_AH + o] = pw[idx];
}

// ---------------- depthwise conv over seq: out (B,S,HID) --------------------
__global__ __launch_bounds__(256) void dwconv_kernel(
    const float* __restrict__ Kin, const float* __restrict__ dww,
    float* __restrict__ outp)
{
    int idx = blockIdx.x * 256 + threadIdx.x;
    if (idx >= CK_BS * CK_HID) return;
    int c = idx % CK_HID;
    int s = (idx / CK_HID) % CK_S;
    int b = idx / (CK_HID * CK_S);
    float acc = 0.0f;
    #pragma unroll
    for (int t = 0; t < 9; t++) {
        int ss = s + t - 4;
        if (ss >= 0 && ss < CK_S)
            acc += Kin[((size_t)(b * CK_S + ss)) * CK_HID + c] * dww[c * 9 + t];
    }
    outp[idx] = acc;
}

// ---------- ck logits GEMM: (mq*mkc)(4096x384) @ ckW(384x54), M-tile 32 -----
__global__ __launch_bounds__(256) void ckgemm_tf32(
    const float* __restrict__ mq, const float* __restrict__ mkc,
    const float* __restrict__ ckW, float* __restrict__ ckl)
{
    __shared__ uint32_t As[32][68];
    __shared__ uint32_t Bs[64][72];
    int tid = threadIdx.x;
    int warp = tid >> 5, lane = tid & 31;
    int g = lane >> 2, t = lane & 3;
    int m0 = blockIdx.x * 32;
    int wm = warp & 1, wn = warp >> 1;

    float c[2][4];
    #pragma unroll
    for (int nt = 0; nt < 2; nt++)
        #pragma unroll
        for (int r = 0; r < 4; r++) c[nt][r] = 0.0f;

    for (int k0 = 0; k0 < CK_AH; k0 += 64) {
        __syncthreads();
        #pragma unroll
        for (int i = 0; i < 2; i++) {
            int e4 = tid + i * 256;
            int row = e4 >> 4, d4 = (e4 & 15) << 2;
            float4 a4 = *(const float4*)&mq[(size_t)(m0 + row) * CK_AH + k0 + d4];
            float4 b4 = *(const float4*)&mkc[(size_t)(m0 + row) * CK_AH + k0 + d4];
            uint4 u;
            u.x = f2tf32(a4.x * b4.x); u.y = f2tf32(a4.y * b4.y);
            u.z = f2tf32(a4.z * b4.z); u.w = f2tf32(a4.w * b4.w);
            *(uint4*)&As[row][d4] = u;
        }
        for (int e = tid; e < 64 * 72; e += 256) {
            int kc = e / 72, o = e % 72;
            float v = (o < 54) ? ckW[(size_t)(k0 + kc) * 54 + o] : 0.0f;
            Bs[kc][o] = f2tf32(v);
        }
        __syncthreads();
        #pragma unroll
        for (int kk = 0; kk < 64; kk += 8) {
            uint32_t a[4];
            int mb = wm * 16;
            a[0] = As[mb + g    ][kk + t];
            a[1] = As[mb + g + 8][kk + t];
            a[2] = As[mb + g    ][kk + t + 4];
            a[3] = As[mb + g + 8][kk + t + 4];
            #pragma unroll
            for (int nt = 0; nt < 2; nt++) {
                uint32_t bb[2];
                int bn = wn * 16 + nt * 8;
                bb[0] = Bs[kk + t    ][bn + g];
                bb[1] = Bs[kk + t + 4][bn + g];
                mma_tf32(c[nt], a, bb);
            }
        }
    }
    int r = m0 + wm * 16 + g;
    #pragma unroll
    for (int nt = 0; nt < 2; nt++) {
        int col = wn * 16 + nt * 8 + t * 2;
        ckl[(size_t)r * 64 + col]           = c[nt][0];
        ckl[(size_t)r * 64 + col + 1]       = c[nt][1];
        ckl[(size_t)(r + 8) * 64 + col]     = c[nt][2];
        ckl[(size_t)(r + 8) * 64 + col + 1] = c[nt][3];
    }
}

// ---------- softmax over KS=9 per (pos, head) --------------------------------
__global__ __launch_bounds__(256) void ck_softmax(
    const float* __restrict__ ckl, const float* __restrict__ ckb,
    float* __restrict__ cko)
{
    int gid = blockIdx.x * 256 + threadIdx.x;
    if (gid >= CK_BS * CK_H) return;
    int p = gid / CK_H, h = gid % CK_H;
    float v[9]; float m = -1e30f;
    #pragma unroll
    for (int k = 0; k < 9; k++) {
        v[k] = ckl[(size_t)p * 64 + h * 9 + k] + ckb[h * 9 + k];
        m = fmaxf(m, v[k]);
    }
    float s = 0.0f;
    #pragma unroll
    for (int k = 0; k < 9; k++) { v[k] = __expf(v[k] - m); s += v[k]; }
    float inv = 1.0f / s;
    #pragma unroll
    for (int k = 0; k < 9; k++)
        cko[(size_t)p * 54 + h * 9 + k] = v[k] * inv;
}

// -------- dynamic-span conv out: sliding window of co x ck -> out[:,384:] ---
__global__ __launch_bounds__(256) void convout_kernel(
    const float* __restrict__ co, const float* __restrict__ cko,
    float* __restrict__ out)
{
    int idx = blockIdx.x * 256 + threadIdx.x;
    if (idx >= CK_BS * CK_AH) return;
    int hd = idx % CK_AH;
    int s  = (idx / CK_AH) % CK_S;
    int b  = idx / (CK_AH * CK_S);
    int h  = hd >> 6;
    const float* ckp = cko + ((size_t)(b * CK_S + s)) * 54 + h * 9;
    float acc = 0.0f;
    #pragma unroll
    for (int k = 0; k < 9; k++) {
        int ss = s + k - 4;
        if (ss >= 0 && ss < CK_S)
            acc += co[((size_t)(b * CK_S + ss)) * CK_AH + hd] * ckp[k];
    }
    out[((size_t)(b * CK_S + s)) * (2 * CK_AH) + CK_AH + hd] = acc;
}

// ---------------- masked softmax of normalized td (per batch) ---------------
__global__ __launch_bounds__(256) void tdsm_kernel(
    const float* __restrict__ td, const int* __restrict__ mask,
    float* __restrict__ out)
{
    __shared__ float red[256];
    int b = blockIdx.x, tid = threadIdx.x;
    float v[4]; float ss = 0.0f;
    #pragma unroll
    for (int t = 0; t < 4; t++) { v[t] = td[b * CK_S + tid + t * 256]; ss += v[t] * v[t]; }
    red[tid] = ss; __syncthreads();
    for (int s = 128; s > 0; s >>= 1) { if (tid < s) red[tid] += red[tid + s]; __syncthreads(); }
    float denom = fmaxf(sqrtf(red[0]), 1e-12f);
    __syncthreads();
    float x[4]; float m = -1e30f;
    #pragma unroll
    for (int t = 0; t < 4; t++) {
        int j = tid + t * 256;
        x[t] = mask[b * CK_S + j] ? (v[t] / denom) : -1e4f;
        m = fmaxf(m, x[t]);
    }
    red[tid] = m; __syncthreads();
    for (int s = 128; s > 0; s >>= 1) { if (tid < s) red[tid] = fmaxf(red[tid], red[tid + s]); __syncthreads(); }
    m = red[0]; __syncthreads();
    float e[4]; float se = 0.0f;
    #pragma unroll
    for (int t = 0; t < 4; t++) { e[t] = __expf(x[t] - m); se += e[t]; }
    red[tid] = se; __syncthreads();
    for (int s = 128; s > 0; s >>= 1) { if (tid < s) red[tid] += red[tid + s]; __syncthreads(); }
    float inv = 1.0f / red[0];
    #pragma unroll
    for (int t = 0; t < 4; t++) out[b * CK_S + tid + t * 256] = e[t] * inv;
}

// ---------------- fused attention: MMA with hoisted conversions -------------
// smem words: sc 16*1044 + kvh 64*72 + kvl 64*72 + qsu 64*24 + tds 1040
//             + amf 264 (1040 bytes padded)
#define ATTN_SCP  1044   // 1044 % 32 == 20
#define ATTN_CH   64
#define ATTN_KP1  68     // phase-1 pitch: a-frag bank 4g+t (distinct)
#define ATTN_KP4  72     // phase-4 pitch: b-frag bank 8t+g (distinct)
#define ATTN_QSP  24
#define ATTN_SMEM_WORDS (16*ATTN_SCP + 64*ATTN_KP4 + 64*ATTN_KP4 + 64*ATTN_QSP + 1040 + 264)
#define ATTN_SMEM_BYTES (ATTN_SMEM_WORDS*4)

__global__ __launch_bounds__(256, 2) void attn_kernel(
    const float* __restrict__ mq, const float* __restrict__ mk,
    const float* __restrict__ mv, const int* __restrict__ mask,
    const float* __restrict__ tdsm, const float* __restrict__ gammas,
    float* __restrict__ out)
{
    extern __shared__ float smem[];
    float*    sc  = smem;                          // [16][1044], f(j)=j+(j>>6)
    uint32_t* kvh = (uint32_t*)(smem + 16 * ATTN_SCP);      // tf32 hi
    uint32_t* kvl = kvh + 64 * ATTN_KP4;                    // tf32 lo (phase 4)
    uint32_t* qsu = kvl + 64 * ATTN_KP4;                    // q tf32 [d][i]
    float*    tds = (float*)(qsu + 64 * ATTN_QSP);          // [1040]
    uint8_t*  amf = (uint8_t*)(tds + 1040);                 // [1040] bytes

    int tid  = threadIdx.x;
    int warp = tid >> 5, lane = tid & 31;
    int g = lane >> 2, t = lane & 3;
    int blk = blockIdx.x;
    int it  = blk & 63;
    int h   = (blk >> 6) % CK_H;
    int b   = blk / (64 * CK_H);
    int i0  = it * 16;

    for (int e = tid; e < 16 * 64; e += 256) {
        int r = e >> 6, d = e & 63;
        qsu[d * ATTN_QSP + r] = f2tf32(
            mq[((size_t)(b * CK_S + i0 + r)) * CK_AH + h * CK_D + d] * 0.125f);
    }
    for (int j = tid; j < CK_S; j += 256) {
        int fj = j + (j >> 6);
        amf[fj] = (uint8_t)(mask[b * CK_S + j] ? 1 : 0);
        tds[fj] = tdsm[b * CK_S + j];
    }
    float gamma = -log1pf(expf(gammas[h]));

    // ---- phase 1: scores^T = K @ q^T, single tf32, pre-converted smem ------
    {
        int jg = warp >> 1;            // 16-key subtile within 64-chunk
        int n0q = (warp & 1) * 8;      // 8 query rows
        int jb = jg * 16;
        for (int c0 = 0; c0 < CK_S; c0 += ATTN_CH) {
            __syncthreads();
            #pragma unroll
            for (int i = 0; i < 4; i++) {
                int e4 = tid + i * 256;
                int j = e4 >> 4, d4 = (e4 & 15) << 2;
                float4 v = *(const float4*)
                    &mk[((size_t)(b * CK_S + c0 + j)) * CK_AH + h * CK_D + d4];
                *(uint4*)&kvh[j * ATTN_KP1 + d4] =
                    make_uint4(f2tf32(v.x), f2tf32(v.y), f2tf32(v.z), f2tf32(v.w));
            }
            __syncthreads();
            float c[4] = {0.f, 0.f, 0.f, 0.f};
            #pragma unroll
            for (int kk = 0; kk < 64; kk += 8) {
                uint32_t a[4], bb[2];
                a[0] = kvh[(jb + g    ) * ATTN_KP1 + kk + t];
                a[1] = kvh[(jb + g + 8) * ATTN_KP1 + kk + t];
                a[2] = kvh[(jb + g    ) * ATTN_KP1 + kk + t + 4];
                a[3] = kvh[(jb + g + 8) * ATTN_KP1 + kk + t + 4];
                bb[0] = qsu[(kk + t    ) * ATTN_QSP + n0q + g];
                bb[1] = qsu[(kk + t + 4) * ATTN_QSP + n0q + g];
                mma_tf32(c, a, bb);
            }
            #pragma unroll
            for (int half = 0; half < 2; half++)
                #pragma unroll
                for (int e = 0; e < 2; e++) {
                    int jglob = c0 + jb + g + 8 * half;
                    sc[(n0q + t * 2 + e) * ATTN_SCP + jglob + (jglob >> 6)] =
                        c[2 * half + e];
                }
        }
    }
    __syncthreads();

    // ---- phase 2+3: softmax -> cumsum -> effect -> second softmax ----------
    {
        int r = tid >> 4;
        int l = tid & 15;
        unsigned ln  = tid & 31;
        unsigned sub = ln & 15;
        float* scr = sc + r * ATTN_SCP + l * 65;
        const uint8_t* amfl = amf + l * 65;
        const float*   tdsl = tds + l * 65;
        int irow = i0 + r;

        float ev[64];
        float m = -1e30f;
        #pragma unroll
        for (int k = 0; k < 64; k++) {
            float x = amfl[k] ? scr[k] : -1e8f;
            ev[k] = x;
            m = fmaxf(m, x);
        }
        #pragma unroll
        for (int dl = 8; dl >= 1; dl >>= 1)
            m = fmaxf(m, __shfl_xor_sync(0xffffffffu, m, dl));
        float sum = 0.0f;
        #pragma unroll
        for (int k = 0; k < 64; k++) { float p = __expf(ev[k] - m); ev[k] = p; sum += p; }
        #pragma unroll
        for (int dl = 8; dl >= 1; dl >>= 1)
            sum += __shfl_xor_sync(0xffffffffu, sum, dl);
        float inv = 1.0f / sum;
        float cum = 0.0f;
        #pragma unroll
        for (int k = 0; k < 64; k++) {
            float p = amfl[k] ? ev[k] * inv : 0.0f;
            cum += p; ev[k] = cum;
        }
        float x = cum;
        #pragma unroll
        for (int dl = 1; dl < 16; dl <<= 1) {
            float v = __shfl_up_sync(0xffffffffu, x, dl);
            if (sub >= (unsigned)dl) x += v;
        }
        float excl = x - cum;
        float tot  = __shfl_sync(0xffffffffu, x, (ln & 16) | 15);

        float m2 = -1e30f;
        #pragma unroll
        for (int k = 0; k < 64; k++) {
            float dc = ev[k] + excl;
            int j = l * 64 + k;
            float pos = fabsf((float)(j - irow));
            float ds  = sqrtf(fmaxf((tot - dc) * pos, 0.0f));
            float eff = __expf(ds * gamma);
            eff = fminf(fmaxf(eff, 1e-5f), 1e5f);
            if (j < irow) eff -= tdsl[k];
            float x2 = amfl[k] ? scr[k] * eff : -1e8f;
            ev[k] = x2;
            m2 = fmaxf(m2, x2);
        }
        #pragma unroll
        for (int dl = 8; dl >= 1; dl >>= 1)
            m2 = fmaxf(m2, __shfl_xor_sync(0xffffffffu, m2, dl));
        float s2 = 0.0f;
        #pragma unroll
        for (int k = 0; k < 64; k++) { float p = __expf(ev[k] - m2); ev[k] = p; s2 += p; }
        #pragma unroll
        for (int dl = 8; dl >= 1; dl >>= 1)
            s2 += __shfl_xor_sync(0xffffffffu, s2, dl);
        float inv2 = 1.0f / s2;
        #pragma unroll
        for (int k = 0; k < 64; k++) scr[k] = ev[k] * inv2;
    }

    // ---- phase 4: ctx = P @ V, 3xTF32, V hi/lo pre-converted ----------------
    {
        int n0 = warp * 8;
        float c[4] = {0.f, 0.f, 0.f, 0.f};
        for (int c0 = 0; c0 < CK_S; c0 += ATTN_CH) {
            __syncthreads();
            #pragma unroll
            for (int i = 0; i < 4; i++) {
                int e4 = tid + i * 256;
                int j = e4 >> 4, d4 = (e4 & 15) << 2;
                float4 v = *(const float4*)
                    &mv[((size_t)(b * CK_S + c0 + j)) * CK_AH + h * CK_D + d4];
                uint4 hi = make_uint4(f2tf32(v.x), f2tf32(v.y),
                                      f2tf32(v.z), f2tf32(v.w));
                uint4 lo = make_uint4(f2tf32(v.x - __uint_as_float(hi.x)),
                                      f2tf32(v.y - __uint_as_float(hi.y)),
                                      f2tf32(v.z - __uint_as_float(hi.z)),
                                      f2tf32(v.w - __uint_as_float(hi.w)));
                *(uint4*)&kvh[j * ATTN_KP4 + d4] = hi;
                *(uint4*)&kvl[j * ATTN_KP4 + d4] = lo;
            }
            __syncthreads();
            int cbase = c0 + (c0 >> 6);
            #pragma unroll
            for (int kk = 0; kk < 64; kk += 8) {
                float af[4];
                int f0 = cbase + kk + t, f1 = f0 + 4;
                af[0] = sc[(g    ) * ATTN_SCP + f0];
                af[1] = sc[(g + 8) * ATTN_SCP + f0];
                af[2] = sc[(g    ) * ATTN_SCP + f1];
                af[3] = sc[(g + 8) * ATTN_SCP + f1];
                uint32_t ah[4], al[4], bh[2], bl[2];
                #pragma unroll
                for (int q = 0; q < 4; q++) {
                    ah[q] = f2tf32(af[q]);
                    al[q] = f2tf32(af[q] - __uint_as_float(ah[q]));
                }
                bh[0] = kvh[(kk + t    ) * ATTN_KP4 + n0 + g];
                bh[1] = kvh[(kk + t + 4) * ATTN_KP4 + n0 + g];
                bl[0] = kvl[(kk + t    ) * ATTN_KP4 + n0 + g];
                bl[1] = kvl[(kk + t + 4) * ATTN_KP4 + n0 + g];
                mma_tf32(c, al, bh);
                mma_tf32(c, ah, bl);
                mma_tf32(c, ah, bh);
            }
        }
        #pragma unroll
        for (int half = 0; half < 2; half++) {
            int r = i0 + g + 8 * half;
            float* op = out + ((size_t)(b * CK_S + r)) * (2 * CK_AH)
                            + h * CK_D + n0 + t * 2;
            op[0] = c[2 * half + 0];
            op[1] = c[2 * half + 1];
        }
    }
}

// ---------------------------------------------------------------------------
extern "C" void kernel_launch(void* const* d_in, const int* in_sizes, int n_in,
                              void* d_out, int out_size)
{
    const float* Q    = (const float*)d_in[0];
    const float* K    = (const float*)d_in[1];
    const float* V    = (const float*)d_in[2];
    const float* td   = (const float*)d_in[3];
    const int*   mask = (const int*)  d_in[4];
    const float* Wq   = (const float*)d_in[5];
    const float* Wk   = (const float*)d_in[6];
    const float* Wv   = (const float*)d_in[7];
    const float* dww  = (const float*)d_in[8];
    const float* pww  = (const float*)d_in[9];
    const float* sepb = (const float*)d_in[10];
    const float* ckW  = (const float*)d_in[11];
    const float* ckb  = (const float*)d_in[12];
    const float* coW  = (const float*)d_in[13];
    const float* cob  = (const float*)d_in[14];
    const float* gam  = (const float*)d_in[15];
    float* out = (float*)d_out;

    float *mq, *mk, *mv, *mkc, *co, *dw, *pwT, *ckl, *cko, *tds;
    cudaGetSymbolAddress((void**)&mq,  g_mq);
    cudaGetSymbolAddress((void**)&mk,  g_mk);
    cudaGetSymbolAddress((void**)&mv,  g_mv);
    cudaGetSymbolAddress((void**)&mkc, g_mkc);
    cudaGetSymbolAddress((void**)&co,  g_co);
    cudaGetSymbolAddress((void**)&dw,  g_dw);
    cudaGetSymbolAddress((void**)&pwT, g_pwT);
    cudaGetSymbolAddress((void**)&ckl, g_ckl);
    cudaGetSymbolAddress((void**)&cko, g_cko);
    cudaGetSymbolAddress((void**)&tds, g_tds);

    transpose_pw<<<(CK_AH * CK_HID + 255) / 256, 256>>>(pww, pwT);
    dwconv_kernel<<<(CK_BS * CK_HID + 255) / 256, 256>>>(K, dww, dw);

    dim3 ggrid(CK_AH / 128, CK_BS / 128, 5);
    gemm5_tf32<<<ggrid, 256>>>(Q, K, V, dw, Wq, Wk, Wv, coW, pwT,
                               cob, sepb, mq, mk, mv, co, mkc);

    ckgemm_tf32<<<CK_BS / 32, 256>>>(mq, mkc, ckW, ckl);
    ck_softmax<<<(CK_BS * CK_H + 255) / 256, 256>>>(ckl, ckb, cko);
    convout_kernel<<<(CK_BS * CK_AH + 255) / 256, 256>>>(co, cko, out);
    tdsm_kernel<<<CK_B, 256>>>(td, mask, tds);

    cudaFuncSetAttribute(attn_kernel, cudaFuncAttributeMaxDynamicSharedMemorySize,
                         ATTN_SMEM_BYTES);
    attn_kernel<<<CK_B * CK_H * (CK_S / 16), 256, ATTN_SMEM_BYTES>>>(
        mq, mk, mv, mask, tds, gam, out);
}

// round 9
// speedup vs baseline: 2.7894x; 1.0464x over previous
#include <cuda_runtime.h>
#include <math.h>
#include <stdint.h>

#define CK_B   4
#define CK_S   1024
#define CK_HID 768
#define CK_H   6
#define CK_D   64
#define CK_AH  384
#define CK_KS  9
#define CK_BS  (CK_B*CK_S)

// ---------------- scratch (device globals; no allocation allowed) ----------
__device__ float g_mq [CK_BS*CK_AH];
__device__ float g_mk [CK_BS*CK_AH];
__device__ float g_mv [CK_BS*CK_AH];
__device__ float g_mkc[CK_BS*CK_AH];
__device__ float g_co [CK_BS*CK_AH];
__device__ float g_dw [CK_BS*CK_HID];
__device__ float g_pwT[CK_HID*CK_AH];
__device__ float g_ckl0[CK_BS*64];
__device__ float g_ckl1[CK_BS*64];
__device__ float g_cko[CK_BS*CK_H*CK_KS];
__device__ float g_tds[CK_BS];

// ---------------- tf32 helpers ---------------------------------------------
__device__ __forceinline__ uint32_t f2tf32(float f) {
    uint32_t u;
    asm("cvt.rna.tf32.f32 %0, %1;" : "=r"(u) : "f"(f));
    return u;
}
__device__ __forceinline__ void mma_tf32(float c[4], const uint32_t a[4],
                                         const uint32_t b[2]) {
    asm volatile(
        "mma.sync.aligned.m16n8k8.row.col.f32.tf32.tf32.f32 "
        "{%0,%1,%2,%3}, {%4,%5,%6,%7}, {%8,%9}, {%0,%1,%2,%3};"
        : "+f"(c[0]), "+f"(c[1]), "+f"(c[2]), "+f"(c[3])
        : "r"(a[0]), "r"(a[1]), "r"(a[2]), "r"(a[3]), "r"(b[0]), "r"(b[1]));
}

// ---------------- batched TF32 tensor-core GEMM ----------------------------
__global__ __launch_bounds__(256, 2) void gemm5_tf32(
    const float* __restrict__ Q, const float* __restrict__ Kin,
    const float* __restrict__ V, const float* __restrict__ dw,
    const float* __restrict__ Wq, const float* __restrict__ Wk,
    const float* __restrict__ Wv, const float* __restrict__ coW,
    const float* __restrict__ pwT,
    const float* __restrict__ cob, const float* __restrict__ sepb,
    float* __restrict__ mq, float* __restrict__ mk, float* __restrict__ mv,
    float* __restrict__ co, float* __restrict__ mkc)
{
    const float *A, *B, *bias; float* C;
    switch (blockIdx.z) {
        case 0:  A = Q;   B = Wq;  bias = nullptr; C = mq;  break;
        case 1:  A = Kin; B = Wk;  bias = nullptr; C = mk;  break;
        case 2:  A = V;   B = Wv;  bias = nullptr; C = mv;  break;
        case 3:  A = V;   B = coW; bias = cob;     C = co;  break;
        default: A = dw;  B = pwT; bias = sepb;    C = mkc; break;
    }
    __shared__ uint32_t As[128][36];
    __shared__ uint32_t Bs[32][132];

    int tid  = threadIdx.x;
    int m0   = blockIdx.y * 128;
    int n0   = blockIdx.x * 128;
    int lane = tid & 31;
    int g    = lane >> 2;
    int t    = lane & 3;
    int warp = tid >> 5;
    int wm   = warp >> 1;
    int wn   = warp & 1;

    float c[2][8][4];
    #pragma unroll
    for (int i = 0; i < 2; i++)
        #pragma unroll
        for (int j = 0; j < 8; j++)
            #pragma unroll
            for (int r = 0; r < 4; r++) c[i][j][r] = 0.0f;

    for (int k0 = 0; k0 < CK_HID; k0 += 32) {
        __syncthreads();
        #pragma unroll
        for (int i = 0; i < 4; i++) {
            int e = tid + i * 256;
            int row = e >> 3, kq = (e & 7) << 2;
            float4 v = *(const float4*)&A[(size_t)(m0 + row) * CK_HID + k0 + kq];
            *(uint4*)&As[row][kq] =
                make_uint4(f2tf32(v.x), f2tf32(v.y), f2tf32(v.z), f2tf32(v.w));
            int kr = e >> 5, nq = (e & 31) << 2;
            float4 w = *(const float4*)&B[(size_t)(k0 + kr) * CK_AH + n0 + nq];
            *(uint4*)&Bs[kr][nq] =
                make_uint4(f2tf32(w.x), f2tf32(w.y), f2tf32(w.z), f2tf32(w.w));
        }
        __syncthreads();
        #pragma unroll
        for (int ks = 0; ks < 4; ks++) {
            int kk = ks * 8;
            uint32_t a[2][4], b[8][2];
            #pragma unroll
            for (int i = 0; i < 2; i++) {
                int bm = wm * 32 + i * 16;
                a[i][0] = As[bm + g    ][kk + t];
                a[i][1] = As[bm + g + 8][kk + t];
                a[i][2] = As[bm + g    ][kk + t + 4];
                a[i][3] = As[bm + g + 8][kk + t + 4];
            }
            #pragma unroll
            for (int j = 0; j < 8; j++) {
                int bn = wn * 64 + j * 8;
                b[j][0] = Bs[kk + t    ][bn + g];
                b[j][1] = Bs[kk + t + 4][bn + g];
            }
            #pragma unroll
            for (int i = 0; i < 2; i++)
                #pragma unroll
                for (int j = 0; j < 8; j++)
                    mma_tf32(c[i][j], a[i], b[j]);
        }
    }
    #pragma unroll
    for (int i = 0; i < 2; i++) {
        int r0 = m0 + wm * 32 + i * 16 + g;
        #pragma unroll
        for (int j = 0; j < 8; j++) {
            int col = n0 + wn * 64 + j * 8 + t * 2;
            float b0 = bias ? bias[col]     : 0.0f;
            float b1 = bias ? bias[col + 1] : 0.0f;
            C[(size_t)r0 * CK_AH + col]           = c[i][j][0] + b0;
            C[(size_t)r0 * CK_AH + col + 1]       = c[i][j][1] + b1;
            C[(size_t)(r0 + 8) * CK_AH + col]     = c[i][j][2] + b0;
            C[(size_t)(r0 + 8) * CK_AH + col + 1] = c[i][j][3] + b1;
        }
    }
}

// ---------------- transpose pw_w (AH,HID) -> (HID,AH) -----------------------
__global__ __launch_bounds__(256) void transpose_pw(
    const float* __restrict__ pw, float* __restrict__ pwT)
{
    int idx = blockIdx.x * 256 + threadIdx.x;
    if (idx >= CK_AH * CK_HID) return;
    int o = idx / CK_HID, c = idx % CK_HID;
    pwT[(size_t)c * CK_AH + o] = pw[idx];
}

// ---------------- depthwise conv (float4 over channels) ---------------------
__global__ __launch_bounds__(256) void dwconv_kernel(
    const float* __restrict__ Kin, const float* __restrict__ dww,
    float* __restrict__ outp)
{
    int idx = blockIdx.x * 256 + threadIdx.x;           // over BS * HID/4
    if (idx >= CK_BS * (CK_HID / 4)) return;
    int c4 = idx % (CK_HID / 4);
    int bs = idx / (CK_HID / 4);
    int s  = bs % CK_S;
    int c  = c4 * 4;
    float w[4][9];
    #pragma unroll
    for (int j = 0; j < 4; j++)
        #pragma unroll
        for (int t = 0; t < 9; t++) w[j][t] = dww[(c + j) * 9 + t];
    float4 acc = make_float4(0.f, 0.f, 0.f, 0.f);
    #pragma unroll
    for (int t = 0; t < 9; t++) {
        int ss = s + t - 4;
        if (ss >= 0 && ss < CK_S) {
            float4 x = *(const float4*)&Kin[((size_t)(bs - s + ss)) * CK_HID + c];
            acc.x += x.x * w[0][t];
            acc.y += x.y * w[1][t];
            acc.z += x.z * w[2][t];
            acc.w += x.w * w[3][t];
        }
    }
    *(float4*)&outp[(size_t)bs * CK_HID + c] = acc;
}

// ---------- ck logits GEMM, k-split in 2 halves (grid.y) ---------------------
__global__ __launch_bounds__(256) void ckgemm_tf32(
    const float* __restrict__ mq, const float* __restrict__ mkc,
    const float* __restrict__ ckW,
    float* __restrict__ ckl0, float* __restrict__ ckl1)
{
    __shared__ uint32_t As[32][68];
    __shared__ uint32_t Bs[64][72];
    int tid = threadIdx.x;
    int warp = tid >> 5, lane = tid & 31;
    int g = lane >> 2, t = lane & 3;
    int m0 = blockIdx.x * 32;
    int kbase = blockIdx.y * 192;
    float* ckl = blockIdx.y ? ckl1 : ckl0;
    int wm = warp & 1, wn = warp >> 1;

    float c[2][4];
    #pragma unroll
    for (int nt = 0; nt < 2; nt++)
        #pragma unroll
        for (int r = 0; r < 4; r++) c[nt][r] = 0.0f;

    for (int kc = 0; kc < 3; kc++) {
        int k0 = kbase + kc * 64;
        __syncthreads();
        #pragma unroll
        for (int i = 0; i < 2; i++) {
            int e4 = tid + i * 256;
            int row = e4 >> 4, d4 = (e4 & 15) << 2;
            float4 a4 = *(const float4*)&mq[(size_t)(m0 + row) * CK_AH + k0 + d4];
            float4 b4 = *(const float4*)&mkc[(size_t)(m0 + row) * CK_AH + k0 + d4];
            uint4 u;
            u.x = f2tf32(a4.x * b4.x); u.y = f2tf32(a4.y * b4.y);
            u.z = f2tf32(a4.z * b4.z); u.w = f2tf32(a4.w * b4.w);
            *(uint4*)&As[row][d4] = u;
        }
        #pragma unroll
        for (int i = 0; i < 18; i++) {
            int e = tid + i * 256;
            int kr = e / 72, o = e - kr * 72;
            float v = (o < 54) ? ckW[(size_t)(k0 + kr) * 54 + o] : 0.0f;
            Bs[kr][o] = f2tf32(v);
        }
        __syncthreads();
        #pragma unroll
        for (int kk = 0; kk < 64; kk += 8) {
            uint32_t a[4];
            int mb = wm * 16;
            a[0] = As[mb + g    ][kk + t];
            a[1] = As[mb + g + 8][kk + t];
            a[2] = As[mb + g    ][kk + t + 4];
            a[3] = As[mb + g + 8][kk + t + 4];
            #pragma unroll
            for (int nt = 0; nt < 2; nt++) {
                uint32_t bb[2];
                int bn = wn * 16 + nt * 8;
                bb[0] = Bs[kk + t    ][bn + g];
                bb[1] = Bs[kk + t + 4][bn + g];
                mma_tf32(c[nt], a, bb);
            }
        }
    }
    int r = m0 + wm * 16 + g;
    #pragma unroll
    for (int nt = 0; nt < 2; nt++) {
        int col = wn * 16 + nt * 8 + t * 2;
        ckl[(size_t)r * 64 + col]           = c[nt][0];
        ckl[(size_t)r * 64 + col + 1]       = c[nt][1];
        ckl[(size_t)(r + 8) * 64 + col]     = c[nt][2];
        ckl[(size_t)(r + 8) * 64 + col + 1] = c[nt][3];
    }
}

// ---------- softmax over KS=9 per (pos, head), summing k-halves --------------
__global__ __launch_bounds__(256) void ck_softmax(
    const float* __restrict__ ckl0, const float* __restrict__ ckl1,
    const float* __restrict__ ckb, float* __restrict__ cko)
{
    int gid = blockIdx.x * 256 + threadIdx.x;
    if (gid >= CK_BS * CK_H) return;
    int p = gid / CK_H, h = gid % CK_H;
    float v[9]; float m = -1e30f;
    #pragma unroll
    for (int k = 0; k < 9; k++) {
        int col = h * 9 + k;
        v[k] = ckl0[(size_t)p * 64 + col] + ckl1[(size_t)p * 64 + col] + ckb[col];
        m = fmaxf(m, v[k]);
    }
    float s = 0.0f;
    #pragma unroll
    for (int k = 0; k < 9; k++) { v[k] = __expf(v[k] - m); s += v[k]; }
    float inv = 1.0f / s;
    #pragma unroll
    for (int k = 0; k < 9; k++)
        cko[(size_t)p * 54 + h * 9 + k] = v[k] * inv;
}

// -------- dynamic-span conv out (float4 over head-dim) ----------------------
__global__ __launch_bounds__(256) void convout_kernel(
    const float* __restrict__ co, const float* __restrict__ cko,
    float* __restrict__ out)
{
    int idx = blockIdx.x * 256 + threadIdx.x;          // over BS * AH/4
    if (idx >= CK_BS * (CK_AH / 4)) return;
    int hd4 = idx % (CK_AH / 4);
    int bs  = idx / (CK_AH / 4);
    int s   = bs % CK_S;
    int hd  = hd4 * 4;
    int h   = hd >> 6;
    const float* ckp = cko + (size_t)bs * 54 + h * 9;
    float ck[9];
    #pragma unroll
    for (int k = 0; k < 9; k++) ck[k] = ckp[k];
    float4 acc = make_float4(0.f, 0.f, 0.f, 0.f);
    #pragma unroll
    for (int k = 0; k < 9; k++) {
        int ss = s + k - 4;
        if (ss >= 0 && ss < CK_S) {
            float4 x = *(const float4*)&co[((size_t)(bs - s + ss)) * CK_AH + hd];
            acc.x += x.x * ck[k];
            acc.y += x.y * ck[k];
            acc.z += x.z * ck[k];
            acc.w += x.w * ck[k];
        }
    }
    *(float4*)&out[(size_t)bs * (2 * CK_AH) + CK_AH + hd] = acc;
}

// ---------------- masked softmax of normalized td (per batch) ---------------
__global__ __launch_bounds__(256) void tdsm_kernel(
    const float* __restrict__ td, const int* __restrict__ mask,
    float* __restrict__ out)
{
    __shared__ float red[256];
    int b = blockIdx.x, tid = threadIdx.x;
    float v[4]; float ss = 0.0f;
    #pragma unroll
    for (int t = 0; t < 4; t++) { v[t] = td[b * CK_S + tid + t * 256]; ss += v[t] * v[t]; }
    red[tid] = ss; __syncthreads();
    for (int s = 128; s > 0; s >>= 1) { if (tid < s) red[tid] += red[tid + s]; __syncthreads(); }
    float denom = fmaxf(sqrtf(red[0]), 1e-12f);
    __syncthreads();
    float x[4]; float m = -1e30f;
    #pragma unroll
    for (int t = 0; t < 4; t++) {
        int j = tid + t * 256;
        x[t] = mask[b * CK_S + j] ? (v[t] / denom) : -1e4f;
        m = fmaxf(m, x[t]);
    }
    red[tid] = m; __syncthreads();
    for (int s = 128; s > 0; s >>= 1) { if (tid < s) red[tid] = fmaxf(red[tid], red[tid + s]); __syncthreads(); }
    m = red[0]; __syncthreads();
    float e[4]; float se = 0.0f;
    #pragma unroll
    for (int t = 0; t < 4; t++) { e[t] = __expf(x[t] - m); se += e[t]; }
    red[tid] = se; __syncthreads();
    for (int s = 128; s > 0; s >>= 1) { if (tid < s) red[tid] += red[tid + s]; __syncthreads(); }
    float inv = 1.0f / red[0];
    #pragma unroll
    for (int t = 0; t < 4; t++) out[b * CK_S + tid + t * 256] = e[t] * inv;
}

// ---------------- fused attention -------------------------------------------
// Phase 1: 64-row K chunks (single tf32, pre-converted). Phase 4: 32-row V
// chunks with hi/lo split; probs stored as tf32 bit patterns by phase 2/3 so
// phase 4 has ZERO in-loop conversions (8 LDS + 2 MMA per kstep).
#define ATTN_SCP  1044   // 1044 % 32 == 20
#define ATTN_KP1  68     // phase-1 pitch (a-frag bank 4g+t)
#define ATTN_KP4  72     // phase-4 pitch (b-frag bank 8t+g)
#define ATTN_QSP  24
#define ATTN_KVW  4608   // max(64*68, 2*32*72)
#define ATTN_SMEM_WORDS (16*ATTN_SCP + ATTN_KVW + 64*ATTN_QSP + 1040 + 264)
#define ATTN_SMEM_BYTES (ATTN_SMEM_WORDS*4)

__global__ __launch_bounds__(256, 2) void attn_kernel(
    const float* __restrict__ mq, const float* __restrict__ mk,
    const float* __restrict__ mv, const int* __restrict__ mask,
    const float* __restrict__ tdsm, const float* __restrict__ gammas,
    float* __restrict__ out)
{
    extern __shared__ float smem[];
    float*    sc  = smem;                               // [16][1044]
    uint32_t* kvb = (uint32_t*)(smem + 16 * ATTN_SCP);  // shared K / V-hi+lo
    uint32_t* qsu = kvb + ATTN_KVW;                     // q tf32 [d][i]
    float*    tds = (float*)(qsu + 64 * ATTN_QSP);      // [1040]
    uint8_t*  amf = (uint8_t*)(tds + 1040);             // [1040] bytes

    int tid  = threadIdx.x;
    int warp = tid >> 5, lane = tid & 31;
    int g = lane >> 2, t = lane & 3;
    int blk = blockIdx.x;
    int it  = blk & 63;
    int h   = (blk >> 6) % CK_H;
    int b   = blk / (64 * CK_H);
    int i0  = it * 16;

    for (int e = tid; e < 16 * 64; e += 256) {
        int r = e >> 6, d = e & 63;
        qsu[d * ATTN_QSP + r] = f2tf32(
            mq[((size_t)(b * CK_S + i0 + r)) * CK_AH + h * CK_D + d] * 0.125f);
    }
    for (int j = tid; j < CK_S; j += 256) {
        int fj = j + (j >> 6);
        amf[fj] = (uint8_t)(mask[b * CK_S + j] ? 1 : 0);
        tds[fj] = tdsm[b * CK_S + j];
    }
    float gamma = -log1pf(expf(gammas[h]));

    // ---- phase 1: scores^T = K @ q^T, single tf32 --------------------------
    {
        int jg = warp >> 1;
        int n0q = (warp & 1) * 8;
        int jb = jg * 16;
        for (int c0 = 0; c0 < CK_S; c0 += 64) {
            __syncthreads();
            #pragma unroll
            for (int i = 0; i < 4; i++) {
                int e4 = tid + i * 256;
                int j = e4 >> 4, d4 = (e4 & 15) << 2;
                float4 v = *(const float4*)
                    &mk[((size_t)(b * CK_S + c0 + j)) * CK_AH + h * CK_D + d4];
                *(uint4*)&kvb[j * ATTN_KP1 + d4] =
                    make_uint4(f2tf32(v.x), f2tf32(v.y), f2tf32(v.z), f2tf32(v.w));
            }
            __syncthreads();
            float c[4] = {0.f, 0.f, 0.f, 0.f};
            #pragma unroll
            for (int kk = 0; kk < 64; kk += 8) {
                uint32_t a[4], bb[2];
                a[0] = kvb[(jb + g    ) * ATTN_KP1 + kk + t];
                a[1] = kvb[(jb + g + 8) * ATTN_KP1 + kk + t];
                a[2] = kvb[(jb + g    ) * ATTN_KP1 + kk + t + 4];
                a[3] = kvb[(jb + g + 8) * ATTN_KP1 + kk + t + 4];
                bb[0] = qsu[(kk + t    ) * ATTN_QSP + n0q + g];
                bb[1] = qsu[(kk + t + 4) * ATTN_QSP + n0q + g];
                mma_tf32(c, a, bb);
            }
            #pragma unroll
            for (int half = 0; half < 2; half++)
                #pragma unroll
                for (int e = 0; e < 2; e++) {
                    int jglob = c0 + jb + g + 8 * half;
                    sc[(n0q + t * 2 + e) * ATTN_SCP + jglob + (jglob >> 6)] =
                        c[2 * half + e];
                }
        }
    }
    __syncthreads();

    // ---- phase 2+3: softmax -> cumsum -> effect -> softmax -> tf32 probs ---
    {
        int r = tid >> 4;
        int l = tid & 15;
        unsigned ln  = tid & 31;
        unsigned sub = ln & 15;
        float* scr = sc + r * ATTN_SCP + l * 65;
        const uint8_t* amfl = amf + l * 65;
        const float*   tdsl = tds + l * 65;
        int irow = i0 + r;

        float ev[64];
        float m = -1e30f;
        #pragma unroll
        for (int k = 0; k < 64; k++) {
            float x = amfl[k] ? scr[k] : -1e8f;
            ev[k] = x;
            m = fmaxf(m, x);
        }
        #pragma unroll
        for (int dl = 8; dl >= 1; dl >>= 1)
            m = fmaxf(m, __shfl_xor_sync(0xffffffffu, m, dl));
        float sum = 0.0f;
        #pragma unroll
        for (int k = 0; k < 64; k++) { float p = __expf(ev[k] - m); ev[k] = p; sum += p; }
        #pragma unroll
        for (int dl = 8; dl >= 1; dl >>= 1)
            sum += __shfl_xor_sync(0xffffffffu, sum, dl);
        float inv = 1.0f / sum;
        float cum = 0.0f;
        #pragma unroll
        for (int k = 0; k < 64; k++) {
            float p = amfl[k] ? ev[k] * inv : 0.0f;
            cum += p; ev[k] = cum;
        }
        float x = cum;
        #pragma unroll
        for (int dl = 1; dl < 16; dl <<= 1) {
            float v = __shfl_up_sync(0xffffffffu, x, dl);
            if (sub >= (unsigned)dl) x += v;
        }
        float excl = x - cum;
        float tot  = __shfl_sync(0xffffffffu, x, (ln & 16) | 15);

        float m2 = -1e30f;
        #pragma unroll
        for (int k = 0; k < 64; k++) {
            float dc = ev[k] + excl;
            int j = l * 64 + k;
            float pos = fabsf((float)(j - irow));
            float ds  = sqrtf(fmaxf((tot - dc) * pos, 0.0f));
            float eff = __expf(ds * gamma);
            eff = fminf(fmaxf(eff, 1e-5f), 1e5f);
            if (j < irow) eff -= tdsl[k];
            float x2 = amfl[k] ? scr[k] * eff : -1e8f;
            ev[k] = x2;
            m2 = fmaxf(m2, x2);
        }
        #pragma unroll
        for (int dl = 8; dl >= 1; dl >>= 1)
            m2 = fmaxf(m2, __shfl_xor_sync(0xffffffffu, m2, dl));
        float s2 = 0.0f;
        #pragma unroll
        for (int k = 0; k < 64; k++) { float p = __expf(ev[k] - m2); ev[k] = p; s2 += p; }
        #pragma unroll
        for (int dl = 8; dl >= 1; dl >>= 1)
            s2 += __shfl_xor_sync(0xffffffffu, s2, dl);
        float inv2 = 1.0f / s2;
        #pragma unroll
        for (int k = 0; k < 64; k++)
            scr[k] = __uint_as_float(f2tf32(ev[k] * inv2));   // tf32 probs
    }

    // ---- phase 4: ctx = P @ V, probs pre-tf32, V hi/lo, 32-row chunks ------
    {
        uint32_t* vh = kvb;
        uint32_t* vl = kvb + 32 * ATTN_KP4;
        int n0 = warp * 8;
        float c[4] = {0.f, 0.f, 0.f, 0.f};
        for (int c0 = 0; c0 < CK_S; c0 += 32) {
            __syncthreads();
            #pragma unroll
            for (int i = 0; i < 2; i++) {
                int e4 = tid + i * 256;
                int j = e4 >> 4, d4 = (e4 & 15) << 2;
                float4 v = *(const float4*)
                    &mv[((size_t)(b * CK_S + c0 + j)) * CK_AH + h * CK_D + d4];
                uint4 hi = make_uint4(f2tf32(v.x), f2tf32(v.y),
                                      f2tf32(v.z), f2tf32(v.w));
                uint4 lo = make_uint4(f2tf32(v.x - __uint_as_float(hi.x)),
                                      f2tf32(v.y - __uint_as_float(hi.y)),
                                      f2tf32(v.z - __uint_as_float(hi.z)),
                                      f2tf32(v.w - __uint_as_float(hi.w)));
                *(uint4*)&vh[j * ATTN_KP4 + d4] = hi;
                *(uint4*)&vl[j * ATTN_KP4 + d4] = lo;
            }
            __syncthreads();
            int cbase = c0 + (c0 >> 6);
            const uint32_t* scu = (const uint32_t*)sc;
            #pragma unroll
            for (int kk = 0; kk < 32; kk += 8) {
                uint32_t a[4], bh[2], bl[2];
                int f0 = cbase + kk + t, f1 = f0 + 4;
                a[0] = scu[(g    ) * ATTN_SCP + f0];
                a[1] = scu[(g + 8) * ATTN_SCP + f0];
                a[2] = scu[(g    ) * ATTN_SCP + f1];
                a[3] = scu[(g + 8) * ATTN_SCP + f1];
                bh[0] = vh[(kk + t    ) * ATTN_KP4 + n0 + g];
                bh[1] = vh[(kk + t + 4) * ATTN_KP4 + n0 + g];
                bl[0] = vl[(kk + t    ) * ATTN_KP4 + n0 + g];
                bl[1] = vl[(kk + t + 4) * ATTN_KP4 + n0 + g];
                mma_tf32(c, a, bh);
                mma_tf32(c, a, bl);
            }
        }
        #pragma unroll
        for (int half = 0; half < 2; half++) {
            int r = i0 + g + 8 * half;
            float* op = out + ((size_t)(b * CK_S + r)) * (2 * CK_AH)
                            + h * CK_D + n0 + t * 2;
            op[0] = c[2 * half + 0];
            op[1] = c[2 * half + 1];
        }
    }
}

// ---------------------------------------------------------------------------
extern "C" void kernel_launch(void* const* d_in, const int* in_sizes, int n_in,
                              void* d_out, int out_size)
{
    const float* Q    = (const float*)d_in[0];
    const float* K    = (const float*)d_in[1];
    const float* V    = (const float*)d_in[2];
    const float* td   = (const float*)d_in[3];
    const int*   mask = (const int*)  d_in[4];
    const float* Wq   = (const float*)d_in[5];
    const float* Wk   = (const float*)d_in[6];
    const float* Wv   = (const float*)d_in[7];
    const float* dww  = (const float*)d_in[8];
    const float* pww  = (const float*)d_in[9];
    const float* sepb = (const float*)d_in[10];
    const float* ckW  = (const float*)d_in[11];
    const float* ckb  = (const float*)d_in[12];
    const float* coW  = (const float*)d_in[13];
    const float* cob  = (const float*)d_in[14];
    const float* gam  = (const float*)d_in[15];
    float* out = (float*)d_out;

    float *mq, *mk, *mv, *mkc, *co, *dw, *pwT, *ckl0, *ckl1, *cko, *tds;
    cudaGetSymbolAddress((void**)&mq,   g_mq);
    cudaGetSymbolAddress((void**)&mk,   g_mk);
    cudaGetSymbolAddress((void**)&mv,   g_mv);
    cudaGetSymbolAddress((void**)&mkc,  g_mkc);
    cudaGetSymbolAddress((void**)&co,   g_co);
    cudaGetSymbolAddress((void**)&dw,   g_dw);
    cudaGetSymbolAddress((void**)&pwT,  g_pwT);
    cudaGetSymbolAddress((void**)&ckl0, g_ckl0);
    cudaGetSymbolAddress((void**)&ckl1, g_ckl1);
    cudaGetSymbolAddress((void**)&cko,  g_cko);
    cudaGetSymbolAddress((void**)&tds,  g_tds);

    transpose_pw<<<(CK_AH * CK_HID + 255) / 256, 256>>>(pww, pwT);
    dwconv_kernel<<<(CK_BS * (CK_HID / 4) + 255) / 256, 256>>>(K, dww, dw);

    dim3 ggrid(CK_AH / 128, CK_BS / 128, 5);
    gemm5_tf32<<<ggrid, 256>>>(Q, K, V, dw, Wq, Wk, Wv, coW, pwT,
                               cob, sepb, mq, mk, mv, co, mkc);

    dim3 ckgrid(CK_BS / 32, 2);
    ckgemm_tf32<<<ckgrid, 256>>>(mq, mkc, ckW, ckl0, ckl1);
    ck_softmax<<<(CK_BS * CK_H + 255) / 256, 256>>>(ckl0, ckl1, ckb, cko);
    convout_kernel<<<(CK_BS * (CK_AH / 4) + 255) / 256, 256>>>(co, cko, out);
    tdsm_kernel<<<CK_B, 256>>>(td, mask, tds);

    cudaFuncSetAttribute(attn_kernel, cudaFuncAttributeMaxDynamicSharedMemorySize,
                         ATTN_SMEM_BYTES);
    attn_kernel<<<CK_B * CK_H * (CK_S / 16), 256, ATTN_SMEM_BYTES>>>(
        mq, mk, mv, mask, tds, gam, out);
}

// round 12
// speedup vs baseline: 3.2926x; 1.1804x over previous
#include <cuda_runtime.h>
#include <math.h>
#include <stdint.h>

#define CK_B   4
#define CK_S   1024
#define CK_HID 768
#define CK_H   6
#define CK_D   64
#define CK_AH  384
#define CK_KS  9
#define CK_BS  (CK_B*CK_S)

// ---------------- scratch (device globals; no allocation allowed) ----------
__device__ float g_mq [CK_BS*CK_AH];
__device__ float g_mk [CK_BS*CK_AH];
__device__ float g_mv [CK_BS*CK_AH];
__device__ float g_mkc[CK_BS*CK_AH];
__device__ float g_co [CK_BS*CK_AH];
__device__ float g_dw [CK_BS*CK_HID];
__device__ float g_pwT[CK_HID*CK_AH];
__device__ float g_ckl0[CK_BS*64];
__device__ float g_ckl1[CK_BS*64];
__device__ float g_ckl2[CK_BS*64];
__device__ float g_cko[CK_BS*CK_H*CK_KS];
__device__ float g_tds[CK_BS];

// ---------------- tf32 helpers ---------------------------------------------
__device__ __forceinline__ uint32_t f2tf32(float f) {
    uint32_t u;
    asm("cvt.rna.tf32.f32 %0, %1;" : "=r"(u) : "f"(f));
    return u;
}
__device__ __forceinline__ void mma_tf32(float c[4], const uint32_t a[4],
                                         const uint32_t b[2]) {
    asm volatile(
        "mma.sync.aligned.m16n8k8.row.col.f32.tf32.tf32.f32 "
        "{%0,%1,%2,%3}, {%4,%5,%6,%7}, {%8,%9}, {%0,%1,%2,%3};"
        : "+f"(c[0]), "+f"(c[1]), "+f"(c[2]), "+f"(c[3])
        : "r"(a[0]), "r"(a[1]), "r"(a[2]), "r"(a[3]), "r"(b[0]), "r"(b[1]));
}

// ---------------- batched TF32 tensor-core GEMM ----------------------------
__global__ __launch_bounds__(256, 2) void gemm5_tf32(
    const float* __restrict__ Q, const float* __restrict__ Kin,
    const float* __restrict__ V, const float* __restrict__ dw,
    const float* __restrict__ Wq, const float* __restrict__ Wk,
    const float* __restrict__ Wv, const float* __restrict__ coW,
    const float* __restrict__ pwT,
    const float* __restrict__ cob, const float* __restrict__ sepb,
    float* __restrict__ mq, float* __restrict__ mk, float* __restrict__ mv,
    float* __restrict__ co, float* __restrict__ mkc)
{
    const float *A, *B, *bias; float* C;
    switch (blockIdx.z) {
        case 0:  A = Q;   B = Wq;  bias = nullptr; C = mq;  break;
        case 1:  A = Kin; B = Wk;  bias = nullptr; C = mk;  break;
        case 2:  A = V;   B = Wv;  bias = nullptr; C = mv;  break;
        case 3:  A = V;   B = coW; bias = cob;     C = co;  break;
        default: A = dw;  B = pwT; bias = sepb;    C = mkc; break;
    }
    __shared__ uint32_t As[128][36];
    __shared__ uint32_t Bs[32][132];

    int tid  = threadIdx.x;
    int m0   = blockIdx.y * 128;
    int n0   = blockIdx.x * 128;
    int lane = tid & 31;
    int g    = lane >> 2;
    int t    = lane & 3;
    int warp = tid >> 5;
    int wm   = warp >> 1;
    int wn   = warp & 1;

    float c[2][8][4];
    #pragma unroll
    for (int i = 0; i < 2; i++)
        #pragma unroll
        for (int j = 0; j < 8; j++)
            #pragma unroll
            for (int r = 0; r < 4; r++) c[i][j][r] = 0.0f;

    for (int k0 = 0; k0 < CK_HID; k0 += 32) {
        __syncthreads();
        #pragma unroll
        for (int i = 0; i < 4; i++) {
            int e = tid + i * 256;
            int row = e >> 3, kq = (e & 7) << 2;
            float4 v = *(const float4*)&A[(size_t)(m0 + row) * CK_HID + k0 + kq];
            *(uint4*)&As[row][kq] =
                make_uint4(f2tf32(v.x), f2tf32(v.y), f2tf32(v.z), f2tf32(v.w));
            int kr = e >> 5, nq = (e & 31) << 2;
            float4 w = *(const float4*)&B[(size_t)(k0 + kr) * CK_AH + n0 + nq];
            *(uint4*)&Bs[kr][nq] =
                make_uint4(f2tf32(w.x), f2tf32(w.y), f2tf32(w.z), f2tf32(w.w));
        }
        __syncthreads();
        #pragma unroll
        for (int ks = 0; ks < 4; ks++) {
            int kk = ks * 8;
            uint32_t a[2][4], b[8][2];
            #pragma unroll
            for (int i = 0; i < 2; i++) {
                int bm = wm * 32 + i * 16;
                a[i][0] = As[bm + g    ][kk + t];
                a[i][1] = As[bm + g + 8][kk + t];
                a[i][2] = As[bm + g    ][kk + t + 4];
                a[i][3] = As[bm + g + 8][kk + t + 4];
            }
            #pragma unroll
            for (int j = 0; j < 8; j++) {
                int bn = wn * 64 + j * 8;
                b[j][0] = Bs[kk + t    ][bn + g];
                b[j][1] = Bs[kk + t + 4][bn + g];
            }
            #pragma unroll
            for (int i = 0; i < 2; i++)
                #pragma unroll
                for (int j = 0; j < 8; j++)
                    mma_tf32(c[i][j], a[i], b[j]);
        }
    }
    #pragma unroll
    for (int i = 0; i < 2; i++) {
        int r0 = m0 + wm * 32 + i * 16 + g;
        #pragma unroll
        for (int j = 0; j < 8; j++) {
            int col = n0 + wn * 64 + j * 8 + t * 2;
            float b0 = bias ? bias[col]     : 0.0f;
            float b1 = bias ? bias[col + 1] : 0.0f;
            C[(size_t)r0 * CK_AH + col]           = c[i][j][0] + b0;
            C[(size_t)r0 * CK_AH + col + 1]       = c[i][j][1] + b1;
            C[(size_t)(r0 + 8) * CK_AH + col]     = c[i][j][2] + b0;
            C[(size_t)(r0 + 8) * CK_AH + col + 1] = c[i][j][3] + b1;
        }
    }
}

// ---------------- transpose pw_w (AH,HID) -> (HID,AH) -----------------------
__global__ __launch_bounds__(256) void transpose_pw(
    const float* __restrict__ pw, float* __restrict__ pwT)
{
    int idx = blockIdx.x * 256 + threadIdx.x;
    if (idx >= CK_AH * CK_HID) return;
    int o = idx / CK_HID, c = idx % CK_HID;
    pwT[(size_t)c * CK_AH + o] = pw[idx];
}

// ---------------- depthwise conv (float4 over channels) ---------------------
__global__ __launch_bounds__(256) void dwconv_kernel(
    const float* __restrict__ Kin, const float* __restrict__ dww,
    float* __restrict__ outp)
{
    int idx = blockIdx.x * 256 + threadIdx.x;           // over BS * HID/4
    if (idx >= CK_BS * (CK_HID / 4)) return;
    int c4 = idx % (CK_HID / 4);
    int bs = idx / (CK_HID / 4);
    int s  = bs % CK_S;
    int c  = c4 * 4;
    float w[4][9];
    #pragma unroll
    for (int j = 0; j < 4; j++)
        #pragma unroll
        for (int t = 0; t < 9; t++) w[j][t] = dww[(c + j) * 9 + t];
    float4 acc = make_float4(0.f, 0.f, 0.f, 0.f);
    #pragma unroll
    for (int t = 0; t < 9; t++) {
        int ss = s + t - 4;
        if (ss >= 0 && ss < CK_S) {
            float4 x = *(const float4*)&Kin[((size_t)(bs - s + ss)) * CK_HID + c];
            acc.x += x.x * w[0][t];
            acc.y += x.y * w[1][t];
            acc.z += x.z * w[2][t];
            acc.w += x.w * w[3][t];
        }
    }
    *(float4*)&outp[(size_t)bs * CK_HID + c] = acc;
}

// ---------- ck logits GEMM, k-split in 3 slabs (grid.y) ----------------------
__global__ __launch_bounds__(256) void ckgemm_tf32(
    const float* __restrict__ mq, const float* __restrict__ mkc,
    const float* __restrict__ ckW,
    float* __restrict__ ckl0, float* __restrict__ ckl1,
    float* __restrict__ ckl2)
{
    __shared__ uint32_t As[32][68];
    __shared__ uint32_t Bs[64][72];
    int tid = threadIdx.x;
    int warp = tid >> 5, lane = tid & 31;
    int g = lane >> 2, t = lane & 3;
    int m0 = blockIdx.x * 32;
    int kbase = blockIdx.y * 128;
    float* ckl = (blockIdx.y == 0) ? ckl0 : ((blockIdx.y == 1) ? ckl1 : ckl2);
    int wm = warp & 1, wn = warp >> 1;

    float c[2][4];
    #pragma unroll
    for (int nt = 0; nt < 2; nt++)
        #pragma unroll
        for (int r = 0; r < 4; r++) c[nt][r] = 0.0f;

    for (int kc = 0; kc < 2; kc++) {
        int k0 = kbase + kc * 64;
        __syncthreads();
        #pragma unroll
        for (int i = 0; i < 2; i++) {
            int e4 = tid + i * 256;
            int row = e4 >> 4, d4 = (e4 & 15) << 2;
            float4 a4 = *(const float4*)&mq[(size_t)(m0 + row) * CK_AH + k0 + d4];
            float4 b4 = *(const float4*)&mkc[(size_t)(m0 + row) * CK_AH + k0 + d4];
            uint4 u;
            u.x = f2tf32(a4.x * b4.x); u.y = f2tf32(a4.y * b4.y);
            u.z = f2tf32(a4.z * b4.z); u.w = f2tf32(a4.w * b4.w);
            *(uint4*)&As[row][d4] = u;
        }
        #pragma unroll
        for (int i = 0; i < 18; i++) {
            int e = tid + i * 256;
            int kr = e / 72, o = e - kr * 72;
            float v = (o < 54) ? ckW[(size_t)(k0 + kr) * 54 + o] : 0.0f;
            Bs[kr][o] = f2tf32(v);
        }
        __syncthreads();
        #pragma unroll
        for (int kk = 0; kk < 64; kk += 8) {
            uint32_t a[4];
            int mb = wm * 16;
            a[0] = As[mb + g    ][kk + t];
            a[1] = As[mb + g + 8][kk + t];
            a[2] = As[mb + g    ][kk + t + 4];
            a[3] = As[mb + g + 8][kk + t + 4];
            #pragma unroll
            for (int nt = 0; nt < 2; nt++) {
                uint32_t bb[2];
                int bn = wn * 16 + nt * 8;
                bb[0] = Bs[kk + t    ][bn + g];
                bb[1] = Bs[kk + t + 4][bn + g];
                mma_tf32(c[nt], a, bb);
            }
        }
    }
    int r = m0 + wm * 16 + g;
    #pragma unroll
    for (int nt = 0; nt < 2; nt++) {
        int col = wn * 16 + nt * 8 + t * 2;
        ckl[(size_t)r * 64 + col]           = c[nt][0];
        ckl[(size_t)r * 64 + col + 1]       = c[nt][1];
        ckl[(size_t)(r + 8) * 64 + col]     = c[nt][2];
        ckl[(size_t)(r + 8) * 64 + col + 1] = c[nt][3];
    }
}

// ---------- softmax over KS=9 per (pos, head), summing k-slabs ---------------
__global__ __launch_bounds__(256) void ck_softmax(
    const float* __restrict__ ckl0, const float* __restrict__ ckl1,
    const float* __restrict__ ckl2, const float* __restrict__ ckb,
    float* __restrict__ cko)
{
    int gid = blockIdx.x * 256 + threadIdx.x;
    if (gid >= CK_BS * CK_H) return;
    int p = gid / CK_H, h = gid % CK_H;
    float v[9]; float m = -1e30f;
    #pragma unroll
    for (int k = 0; k < 9; k++) {
        int col = h * 9 + k;
        v[k] = ckl0[(size_t)p * 64 + col] + ckl1[(size_t)p * 64 + col]
             + ckl2[(size_t)p * 64 + col] + ckb[col];
        m = fmaxf(m, v[k]);
    }
    float s = 0.0f;
    #pragma unroll
    for (int k = 0; k < 9; k++) { v[k] = __expf(v[k] - m); s += v[k]; }
    float inv = 1.0f / s;
    #pragma unroll
    for (int k = 0; k < 9; k++)
        cko[(size_t)p * 54 + h * 9 + k] = v[k] * inv;
}

// -------- dynamic-span conv out (float4 over head-dim) ----------------------
__global__ __launch_bounds__(256) void convout_kernel(
    const float* __restrict__ co, const float* __restrict__ cko,
    float* __restrict__ out)
{
    int idx = blockIdx.x * 256 + threadIdx.x;          // over BS * AH/4
    if (idx >= CK_BS * (CK_AH / 4)) return;
    int hd4 = idx % (CK_AH / 4);
    int bs  = idx / (CK_AH / 4);
    int s   = bs % CK_S;
    int hd  = hd4 * 4;
    int h   = hd >> 6;
    const float* ckp = cko + (size_t)bs * 54 + h * 9;
    float ck[9];
    #pragma unroll
    for (int k = 0; k < 9; k++) ck[k] = ckp[k];
    float4 acc = make_float4(0.f, 0.f, 0.f, 0.f);
    #pragma unroll
    for (int k = 0; k < 9; k++) {
        int ss = s + k - 4;
        if (ss >= 0 && ss < CK_S) {
            float4 x = *(const float4*)&co[((size_t)(bs - s + ss)) * CK_AH + hd];
            acc.x += x.x * ck[k];
            acc.y += x.y * ck[k];
            acc.z += x.z * ck[k];
            acc.w += x.w * ck[k];
        }
    }
    *(float4*)&out[(size_t)bs * (2 * CK_AH) + CK_AH + hd] = acc;
}

// ---------------- masked softmax of normalized td (per batch) ---------------
__global__ __launch_bounds__(256) void tdsm_kernel(
    const float* __restrict__ td, const int* __restrict__ mask,
    float* __restrict__ out)
{
    __shared__ float red[256];
    int b = blockIdx.x, tid = threadIdx.x;
    float v[4]; float ss = 0.0f;
    #pragma unroll
    for (int t = 0; t < 4; t++) { v[t] = td[b * CK_S + tid + t * 256]; ss += v[t] * v[t]; }
    red[tid] = ss; __syncthreads();
    for (int s = 128; s > 0; s >>= 1) { if (tid < s) red[tid] += red[tid + s]; __syncthreads(); }
    float denom = fmaxf(sqrtf(red[0]), 1e-12f);
    __syncthreads();
    float x[4]; float m = -1e30f;
    #pragma unroll
    for (int t = 0; t < 4; t++) {
        int j = tid + t * 256;
        x[t] = mask[b * CK_S + j] ? (v[t] / denom) : -1e4f;
        m = fmaxf(m, x[t]);
    }
    red[tid] = m; __syncthreads();
    for (int s = 128; s > 0; s >>= 1) { if (tid < s) red[tid] = fmaxf(red[tid], red[tid + s]); __syncthreads(); }
    m = red[0]; __syncthreads();
    float e[4]; float se = 0.0f;
    #pragma unroll
    for (int t = 0; t < 4; t++) { e[t] = __expf(x[t] - m); se += e[t]; }
    red[tid] = se; __syncthreads();
    for (int s = 128; s > 0; s >>= 1) { if (tid < s) red[tid] += red[tid + s]; __syncthreads(); }
    float inv = 1.0f / red[0];
    #pragma unroll
    for (int t = 0; t < 4; t++) out[b * CK_S + tid + t * 256] = e[t] * inv;
}

// ---------------- fused attention -------------------------------------------
// Phase 1 stores MASKED scores (-1e8 on masked keys) so phases 2/3 carry no
// per-element mask loads/selects. Phase 4: probs stored as tf32 bit patterns,
// V single tf32, 64-row chunks -> 1 MMA + 6 LDS per kstep, zero in-loop ALU.
#define ATTN_SCP  1044   // 1044 % 32 == 20
#define ATTN_KP1  68     // phase-1 pitch (a-frag bank 4g+t)
#define ATTN_KP4  72     // phase-4 pitch (b-frag bank 8t+g)
#define ATTN_QSP  24
#define ATTN_KVW  4608   // max(64*68, 64*72)
#define ATTN_SMEM_WORDS (16*ATTN_SCP + ATTN_KVW + 64*ATTN_QSP + 1040 + 264)
#define ATTN_SMEM_BYTES (ATTN_SMEM_WORDS*4)

__global__ __launch_bounds__(256, 2) void attn_kernel(
    const float* __restrict__ mq, const float* __restrict__ mk,
    const float* __restrict__ mv, const int* __restrict__ mask,
    const float* __restrict__ tdsm, const float* __restrict__ gammas,
    float* __restrict__ out)
{
    extern __shared__ float smem[];
    float*    sc  = smem;                               // [16][1044]
    uint32_t* kvb = (uint32_t*)(smem + 16 * ATTN_SCP);  // shared K / V buffer
    uint32_t* qsu = kvb + ATTN_KVW;                     // q tf32 [d][i]
    float*    tds = (float*)(qsu + 64 * ATTN_QSP);      // [1040]
    uint8_t*  amf = (uint8_t*)(tds + 1040);             // [1040] bytes

    int tid  = threadIdx.x;
    int warp = tid >> 5, lane = tid & 31;
    int g = lane >> 2, t = lane & 3;
    int blk = blockIdx.x;
    int it  = blk & 63;
    int h   = (blk >> 6) % CK_H;
    int b   = blk / (64 * CK_H);
    int i0  = it * 16;

    for (int e = tid; e < 16 * 64; e += 256) {
        int r = e >> 6, d = e & 63;
        qsu[d * ATTN_QSP + r] = f2tf32(
            mq[((size_t)(b * CK_S + i0 + r)) * CK_AH + h * CK_D + d] * 0.125f);
    }
    for (int j = tid; j < CK_S; j += 256) {
        int fj = j + (j >> 6);
        amf[fj] = (uint8_t)(mask[b * CK_S + j] ? 1 : 0);
        tds[fj] = tdsm[b * CK_S + j];
    }
    float gamma = -log1pf(expf(gammas[h]));

    // ---- phase 1: scores^T = K @ q^T, single tf32, mask folded at store ----
    {
        int jg = warp >> 1;
        int n0q = (warp & 1) * 8;
        int jb = jg * 16;
        for (int c0 = 0; c0 < CK_S; c0 += 64) {
            __syncthreads();
            #pragma unroll
            for (int i = 0; i < 4; i++) {
                int e4 = tid + i * 256;
                int j = e4 >> 4, d4 = (e4 & 15) << 2;
                float4 v = *(const float4*)
                    &mk[((size_t)(b * CK_S + c0 + j)) * CK_AH + h * CK_D + d4];
                *(uint4*)&kvb[j * ATTN_KP1 + d4] =
                    make_uint4(f2tf32(v.x), f2tf32(v.y), f2tf32(v.z), f2tf32(v.w));
            }
            __syncthreads();
            float c[4] = {0.f, 0.f, 0.f, 0.f};
            #pragma unroll
            for (int kk = 0; kk < 64; kk += 8) {
                uint32_t a[4], bb[2];
                a[0] = kvb[(jb + g    ) * ATTN_KP1 + kk + t];
                a[1] = kvb[(jb + g + 8) * ATTN_KP1 + kk + t];
                a[2] = kvb[(jb + g    ) * ATTN_KP1 + kk + t + 4];
                a[3] = kvb[(jb + g + 8) * ATTN_KP1 + kk + t + 4];
                bb[0] = qsu[(kk + t    ) * ATTN_QSP + n0q + g];
                bb[1] = qsu[(kk + t + 4) * ATTN_QSP + n0q + g];
                mma_tf32(c, a, bb);
            }
            #pragma unroll
            for (int half = 0; half < 2; half++) {
                int jglob = c0 + jb + g + 8 * half;
                int fj = jglob + (jglob >> 6);
                bool on = amf[fj] != 0;
                #pragma unroll
                for (int e = 0; e < 2; e++) {
                    float val = on ? c[2 * half + e] : -1e8f;
                    sc[(n0q + t * 2 + e) * ATTN_SCP + fj] = val;
                }
            }
        }
    }
    __syncthreads();

    // ---- phase 2+3: softmax -> cumsum -> effect -> softmax (mask-free) -----
    {
        int r = tid >> 4;
        int l = tid & 15;
        unsigned ln  = tid & 31;
        unsigned sub = ln & 15;
        float* scr = sc + r * ATTN_SCP + l * 65;
        const float* tdsl = tds + l * 65;
        int irow = i0 + r;

        float ev[64];
        float m = -1e30f;
        #pragma unroll
        for (int k = 0; k < 64; k++) {
            float x = scr[k];
            ev[k] = x;
            m = fmaxf(m, x);
        }
        #pragma unroll
        for (int dl = 8; dl >= 1; dl >>= 1)
            m = fmaxf(m, __shfl_xor_sync(0xffffffffu, m, dl));
        float sum = 0.0f;
        #pragma unroll
        for (int k = 0; k < 64; k++) { float p = __expf(ev[k] - m); ev[k] = p; sum += p; }
        #pragma unroll
        for (int dl = 8; dl >= 1; dl >>= 1)
            sum += __shfl_xor_sync(0xffffffffu, sum, dl);
        float inv = 1.0f / sum;
        float cum = 0.0f;
        #pragma unroll
        for (int k = 0; k < 64; k++) { cum += ev[k] * inv; ev[k] = cum; }
        float x = cum;
        #pragma unroll
        for (int dl = 1; dl < 16; dl <<= 1) {
            float v = __shfl_up_sync(0xffffffffu, x, dl);
            if (sub >= (unsigned)dl) x += v;
        }
        float excl = x - cum;
        float tot  = __shfl_sync(0xffffffffu, x, (ln & 16) | 15);

        float m2 = -1e30f;
        #pragma unroll
        for (int k = 0; k < 64; k++) {
            float dc = ev[k] + excl;
            int j = l * 64 + k;
            float pos = fabsf((float)(j - irow));
            float ds  = sqrtf(fmaxf((tot - dc) * pos, 0.0f));
            float eff = __expf(ds * gamma);
            eff = fminf(fmaxf(eff, 1e-5f), 1e5f);
            if (j < irow) eff -= tdsl[k];
            float x2 = scr[k] * eff;
            ev[k] = x2;
            m2 = fmaxf(m2, x2);
        }
        #pragma unroll
        for (int dl = 8; dl >= 1; dl >>= 1)
            m2 = fmaxf(m2, __shfl_xor_sync(0xffffffffu, m2, dl));
        float s2 = 0.0f;
        #pragma unroll
        for (int k = 0; k < 64; k++) { float p = __expf(ev[k] - m2); ev[k] = p; s2 += p; }
        #pragma unroll
        for (int dl = 8; dl >= 1; dl >>= 1)
            s2 += __shfl_xor_sync(0xffffffffu, s2, dl);
        float inv2 = 1.0f / s2;
        #pragma unroll
        for (int k = 0; k < 64; k++)
            scr[k] = __uint_as_float(f2tf32(ev[k] * inv2));   // tf32 probs
    }

    // ---- phase 4: ctx = P @ V, probs pre-tf32, V single tf32, 64-row chunks
    {
        uint32_t* vh = kvb;
        int n0 = warp * 8;
        float c[4] = {0.f, 0.f, 0.f, 0.f};
        for (int c0 = 0; c0 < CK_S; c0 += 64) {
            __syncthreads();
            #pragma unroll
            for (int i = 0; i < 4; i++) {
                int e4 = tid + i * 256;
                int j = e4 >> 4, d4 = (e4 & 15) << 2;
                float4 v = *(const float4*)
                    &mv[((size_t)(b * CK_S + c0 + j)) * CK_AH + h * CK_D + d4];
                *(uint4*)&vh[j * ATTN_KP4 + d4] =
                    make_uint4(f2tf32(v.x), f2tf32(v.y), f2tf32(v.z), f2tf32(v.w));
            }
            __syncthreads();
            int cbase = c0 + (c0 >> 6);
            const uint32_t* scu = (const uint32_t*)sc;
            #pragma unroll
            for (int kk = 0; kk < 64; kk += 8) {
                uint32_t a[4], bh[2];
                int f0 = cbase + kk + t, f1 = f0 + 4;
                a[0] = scu[(g    ) * ATTN_SCP + f0];
                a[1] = scu[(g + 8) * ATTN_SCP + f0];
                a[2] = scu[(g    ) * ATTN_SCP + f1];
                a[3] = scu[(g + 8) * ATTN_SCP + f1];
                bh[0] = vh[(kk + t    ) * ATTN_KP4 + n0 + g];
                bh[1] = vh[(kk + t + 4) * ATTN_KP4 + n0 + g];
                mma_tf32(c, a, bh);
            }
        }
        #pragma unroll
        for (int half = 0; half < 2; half++) {
            int r = i0 + g + 8 * half;
            float* op = out + ((size_t)(b * CK_S + r)) * (2 * CK_AH)
                            + h * CK_D + n0 + t * 2;
            op[0] = c[2 * half + 0];
            op[1] = c[2 * half + 1];
        }
    }
}

// ---------------------------------------------------------------------------
extern "C" void kernel_launch(void* const* d_in, const int* in_sizes, int n_in,
                              void* d_out, int out_size)
{
    const float* Q    = (const float*)d_in[0];
    const float* K    = (const float*)d_in[1];
    const float* V    = (const float*)d_in[2];
    const float* td   = (const float*)d_in[3];
    const int*   mask = (const int*)  d_in[4];
    const float* Wq   = (const float*)d_in[5];
    const float* Wk   = (const float*)d_in[6];
    const float* Wv   = (const float*)d_in[7];
    const float* dww  = (const float*)d_in[8];
    const float* pww  = (const float*)d_in[9];
    const float* sepb = (const float*)d_in[10];
    const float* ckW  = (const float*)d_in[11];
    const float* ckb  = (const float*)d_in[12];
    const float* coW  = (const float*)d_in[13];
    const float* cob  = (const float*)d_in[14];
    const float* gam  = (const float*)d_in[15];
    float* out = (float*)d_out;

    float *mq, *mk, *mv, *mkc, *co, *dw, *pwT, *ckl0, *ckl1, *ckl2, *cko, *tds;
    cudaGetSymbolAddress((void**)&mq,   g_mq);
    cudaGetSymbolAddress((void**)&mk,   g_mk);
    cudaGetSymbolAddress((void**)&mv,   g_mv);
    cudaGetSymbolAddress((void**)&mkc,  g_mkc);
    cudaGetSymbolAddress((void**)&co,   g_co);
    cudaGetSymbolAddress((void**)&dw,   g_dw);
    cudaGetSymbolAddress((void**)&pwT,  g_pwT);
    cudaGetSymbolAddress((void**)&ckl0, g_ckl0);
    cudaGetSymbolAddress((void**)&ckl1, g_ckl1);
    cudaGetSymbolAddress((void**)&ckl2, g_ckl2);
    cudaGetSymbolAddress((void**)&cko,  g_cko);
    cudaGetSymbolAddress((void**)&tds,  g_tds);

    transpose_pw<<<(CK_AH * CK_HID + 255) / 256, 256>>>(pww, pwT);
    dwconv_kernel<<<(CK_BS * (CK_HID / 4) + 255) / 256, 256>>>(K, dww, dw);

    dim3 ggrid(CK_AH / 128, CK_BS / 128, 5);
    gemm5_tf32<<<ggrid, 256>>>(Q, K, V, dw, Wq, Wk, Wv, coW, pwT,
                               cob, sepb, mq, mk, mv, co, mkc);

    dim3 ckgrid(CK_BS / 32, 3);
    ckgemm_tf32<<<ckgrid, 256>>>(mq, mkc, ckW, ckl0, ckl1, ckl2);
    ck_softmax<<<(CK_BS * CK_H + 255) / 256, 256>>>(ckl0, ckl1, ckl2, ckb, cko);
    convout_kernel<<<(CK_BS * (CK_AH / 4) + 255) / 256, 256>>>(co, cko, out);
    tdsm_kernel<<<CK_B, 256>>>(td, mask, tds);

    cudaFuncSetAttribute(attn_kernel, cudaFuncAttributeMaxDynamicSharedMemorySize,
                         ATTN_SMEM_BYTES);
    attn_kernel<<<CK_B * CK_H * (CK_S / 16), 256, ATTN_SMEM_BYTES>>>(
        mq, mk, mv, mask, tds, gam, out);
}

// round 13
// speedup vs baseline: 3.3236x; 1.0094x over previous
#include <cuda_runtime.h>
#include <math.h>
#include <stdint.h>

#define CK_B   4
#define CK_S   1024
#define CK_HID 768
#define CK_H   6
#define CK_D   64
#define CK_AH  384
#define CK_KS  9
#define CK_BS  (CK_B*CK_S)

// ---------------- scratch (device globals; no allocation allowed) ----------
__device__ float g_mq [CK_BS*CK_AH];
__device__ float g_mk [CK_BS*CK_AH];
__device__ float g_mv [CK_BS*CK_AH];
__device__ float g_mkc[CK_BS*CK_AH];
__device__ float g_co [CK_BS*CK_AH];
__device__ float g_dw [CK_BS*CK_HID];
__device__ float g_pwT[CK_HID*CK_AH];
__device__ float g_ckl0[CK_BS*64];
__device__ float g_ckl1[CK_BS*64];
__device__ float g_ckl2[CK_BS*64];
__device__ float g_cko[CK_BS*CK_H*CK_KS];
__device__ float g_tds[CK_BS];

// ---------------- tf32 helpers ---------------------------------------------
__device__ __forceinline__ uint32_t f2tf32(float f) {
    uint32_t u;
    asm("cvt.rna.tf32.f32 %0, %1;" : "=r"(u) : "f"(f));
    return u;
}
__device__ __forceinline__ void mma_tf32(float c[4], const uint32_t a[4],
                                         const uint32_t b[2]) {
    asm volatile(
        "mma.sync.aligned.m16n8k8.row.col.f32.tf32.tf32.f32 "
        "{%0,%1,%2,%3}, {%4,%5,%6,%7}, {%8,%9}, {%0,%1,%2,%3};"
        : "+f"(c[0]), "+f"(c[1]), "+f"(c[2]), "+f"(c[3])
        : "r"(a[0]), "r"(a[1]), "r"(a[2]), "r"(a[3]), "r"(b[0]), "r"(b[1]));
}

// ---------------- batched TF32 tensor-core GEMM ----------------------------
__global__ __launch_bounds__(256, 2) void gemm5_tf32(
    const float* __restrict__ Q, const float* __restrict__ Kin,
    const float* __restrict__ V, const float* __restrict__ dw,
    const float* __restrict__ Wq, const float* __restrict__ Wk,
    const float* __restrict__ Wv, const float* __restrict__ coW,
    const float* __restrict__ pwT,
    const float* __restrict__ cob, const float* __restrict__ sepb,
    float* __restrict__ mq, float* __restrict__ mk, float* __restrict__ mv,
    float* __restrict__ co, float* __restrict__ mkc)
{
    const float *A, *B, *bias; float* C;
    switch (blockIdx.z) {
        case 0:  A = Q;   B = Wq;  bias = nullptr; C = mq;  break;
        case 1:  A = Kin; B = Wk;  bias = nullptr; C = mk;  break;
        case 2:  A = V;   B = Wv;  bias = nullptr; C = mv;  break;
        case 3:  A = V;   B = coW; bias = cob;     C = co;  break;
        default: A = dw;  B = pwT; bias = sepb;    C = mkc; break;
    }
    __shared__ uint32_t As[128][36];
    __shared__ uint32_t Bs[32][132];

    int tid  = threadIdx.x;
    int m0   = blockIdx.y * 128;
    int n0   = blockIdx.x * 128;
    int lane = tid & 31;
    int g    = lane >> 2;
    int t    = lane & 3;
    int warp = tid >> 5;
    int wm   = warp >> 1;
    int wn   = warp & 1;

    float c[2][8][4];
    #pragma unroll
    for (int i = 0; i < 2; i++)
        #pragma unroll
        for (int j = 0; j < 8; j++)
            #pragma unroll
            for (int r = 0; r < 4; r++) c[i][j][r] = 0.0f;

    for (int k0 = 0; k0 < CK_HID; k0 += 32) {
        __syncthreads();
        #pragma unroll
        for (int i = 0; i < 4; i++) {
            int e = tid + i * 256;
            int row = e >> 3, kq = (e & 7) << 2;
            float4 v = *(const float4*)&A[(size_t)(m0 + row) * CK_HID + k0 + kq];
            *(uint4*)&As[row][kq] =
                make_uint4(f2tf32(v.x), f2tf32(v.y), f2tf32(v.z), f2tf32(v.w));
            int kr = e >> 5, nq = (e & 31) << 2;
            float4 w = *(const float4*)&B[(size_t)(k0 + kr) * CK_AH + n0 + nq];
            *(uint4*)&Bs[kr][nq] =
                make_uint4(f2tf32(w.x), f2tf32(w.y), f2tf32(w.z), f2tf32(w.w));
        }
        __syncthreads();
        #pragma unroll
        for (int ks = 0; ks < 4; ks++) {
            int kk = ks * 8;
            uint32_t a[2][4], b[8][2];
            #pragma unroll
            for (int i = 0; i < 2; i++) {
                int bm = wm * 32 + i * 16;
                a[i][0] = As[bm + g    ][kk + t];
                a[i][1] = As[bm + g + 8][kk + t];
                a[i][2] = As[bm + g    ][kk + t + 4];
                a[i][3] = As[bm + g + 8][kk + t + 4];
            }
            #pragma unroll
            for (int j = 0; j < 8; j++) {
                int bn = wn * 64 + j * 8;
                b[j][0] = Bs[kk + t    ][bn + g];
                b[j][1] = Bs[kk + t + 4][bn + g];
            }
            #pragma unroll
            for (int i = 0; i < 2; i++)
                #pragma unroll
                for (int j = 0; j < 8; j++)
                    mma_tf32(c[i][j], a[i], b[j]);
        }
    }
    #pragma unroll
    for (int i = 0; i < 2; i++) {
        int r0 = m0 + wm * 32 + i * 16 + g;
        #pragma unroll
        for (int j = 0; j < 8; j++) {
            int col = n0 + wn * 64 + j * 8 + t * 2;
            float b0 = bias ? bias[col]     : 0.0f;
            float b1 = bias ? bias[col + 1] : 0.0f;
            C[(size_t)r0 * CK_AH + col]           = c[i][j][0] + b0;
            C[(size_t)r0 * CK_AH + col + 1]       = c[i][j][1] + b1;
            C[(size_t)(r0 + 8) * CK_AH + col]     = c[i][j][2] + b0;
            C[(size_t)(r0 + 8) * CK_AH + col + 1] = c[i][j][3] + b1;
        }
    }
}

// ---------------- transpose pw_w (AH,HID) -> (HID,AH) -----------------------
__global__ __launch_bounds__(256) void transpose_pw(
    const float* __restrict__ pw, float* __restrict__ pwT)
{
    int idx = blockIdx.x * 256 + threadIdx.x;
    if (idx >= CK_AH * CK_HID) return;
    int o = idx / CK_HID, c = idx % CK_HID;
    pwT[(size_t)c * CK_AH + o] = pw[idx];
}

// ---------------- depthwise conv (float4 over channels) ---------------------
__global__ __launch_bounds__(256) void dwconv_kernel(
    const float* __restrict__ Kin, const float* __restrict__ dww,
    float* __restrict__ outp)
{
    int idx = blockIdx.x * 256 + threadIdx.x;           // over BS * HID/4
    if (idx >= CK_BS * (CK_HID / 4)) return;
    int c4 = idx % (CK_HID / 4);
    int bs = idx / (CK_HID / 4);
    int s  = bs % CK_S;
    int c  = c4 * 4;
    float w[4][9];
    #pragma unroll
    for (int j = 0; j < 4; j++)
        #pragma unroll
        for (int t = 0; t < 9; t++) w[j][t] = dww[(c + j) * 9 + t];
    float4 acc = make_float4(0.f, 0.f, 0.f, 0.f);
    #pragma unroll
    for (int t = 0; t < 9; t++) {
        int ss = s + t - 4;
        if (ss >= 0 && ss < CK_S) {
            float4 x = *(const float4*)&Kin[((size_t)(bs - s + ss)) * CK_HID + c];
            acc.x += x.x * w[0][t];
            acc.y += x.y * w[1][t];
            acc.z += x.z * w[2][t];
            acc.w += x.w * w[3][t];
        }
    }
    *(float4*)&outp[(size_t)bs * CK_HID + c] = acc;
}

// ---------- ck logits GEMM, k-split in 3 slabs (grid.y) ----------------------
__global__ __launch_bounds__(256) void ckgemm_tf32(
    const float* __restrict__ mq, const float* __restrict__ mkc,
    const float* __restrict__ ckW,
    float* __restrict__ ckl0, float* __restrict__ ckl1,
    float* __restrict__ ckl2)
{
    __shared__ uint32_t As[32][68];
    __shared__ uint32_t Bs[64][72];
    int tid = threadIdx.x;
    int warp = tid >> 5, lane = tid & 31;
    int g = lane >> 2, t = lane & 3;
    int m0 = blockIdx.x * 32;
    int kbase = blockIdx.y * 128;
    float* ckl = (blockIdx.y == 0) ? ckl0 : ((blockIdx.y == 1) ? ckl1 : ckl2);
    int wm = warp & 1, wn = warp >> 1;

    float c[2][4];
    #pragma unroll
    for (int nt = 0; nt < 2; nt++)
        #pragma unroll
        for (int r = 0; r < 4; r++) c[nt][r] = 0.0f;

    for (int kc = 0; kc < 2; kc++) {
        int k0 = kbase + kc * 64;
        __syncthreads();
        #pragma unroll
        for (int i = 0; i < 2; i++) {
            int e4 = tid + i * 256;
            int row = e4 >> 4, d4 = (e4 & 15) << 2;
            float4 a4 = *(const float4*)&mq[(size_t)(m0 + row) * CK_AH + k0 + d4];
            float4 b4 = *(const float4*)&mkc[(size_t)(m0 + row) * CK_AH + k0 + d4];
            uint4 u;
            u.x = f2tf32(a4.x * b4.x); u.y = f2tf32(a4.y * b4.y);
            u.z = f2tf32(a4.z * b4.z); u.w = f2tf32(a4.w * b4.w);
            *(uint4*)&As[row][d4] = u;
        }
        #pragma unroll
        for (int i = 0; i < 18; i++) {
            int e = tid + i * 256;
            int kr = e / 72, o = e - kr * 72;
            float v = (o < 54) ? ckW[(size_t)(k0 + kr) * 54 + o] : 0.0f;
            Bs[kr][o] = f2tf32(v);
        }
        __syncthreads();
        #pragma unroll
        for (int kk = 0; kk < 64; kk += 8) {
            uint32_t a[4];
            int mb = wm * 16;
            a[0] = As[mb + g    ][kk + t];
            a[1] = As[mb + g + 8][kk + t];
            a[2] = As[mb + g    ][kk + t + 4];
            a[3] = As[mb + g + 8][kk + t + 4];
            #pragma unroll
            for (int nt = 0; nt < 2; nt++) {
                uint32_t bb[2];
                int bn = wn * 16 + nt * 8;
                bb[0] = Bs[kk + t    ][bn + g];
                bb[1] = Bs[kk + t + 4][bn + g];
                mma_tf32(c[nt], a, bb);
            }
        }
    }
    int r = m0 + wm * 16 + g;
    #pragma unroll
    for (int nt = 0; nt < 2; nt++) {
        int col = wn * 16 + nt * 8 + t * 2;
        ckl[(size_t)r * 64 + col]           = c[nt][0];
        ckl[(size_t)r * 64 + col + 1]       = c[nt][1];
        ckl[(size_t)(r + 8) * 64 + col]     = c[nt][2];
        ckl[(size_t)(r + 8) * 64 + col + 1] = c[nt][3];
    }
}

// ---------- softmax over KS=9 per (pos, head), summing k-slabs ---------------
__global__ __launch_bounds__(256) void ck_softmax(
    const float* __restrict__ ckl0, const float* __restrict__ ckl1,
    const float* __restrict__ ckl2, const float* __restrict__ ckb,
    float* __restrict__ cko)
{
    int gid = blockIdx.x * 256 + threadIdx.x;
    if (gid >= CK_BS * CK_H) return;
    int p = gid / CK_H, h = gid % CK_H;
    float v[9]; float m = -1e30f;
    #pragma unroll
    for (int k = 0; k < 9; k++) {
        int col = h * 9 + k;
        v[k] = ckl0[(size_t)p * 64 + col] + ckl1[(size_t)p * 64 + col]
             + ckl2[(size_t)p * 64 + col] + ckb[col];
        m = fmaxf(m, v[k]);
    }
    float s = 0.0f;
    #pragma unroll
    for (int k = 0; k < 9; k++) { v[k] = __expf(v[k] - m); s += v[k]; }
    float inv = 1.0f / s;
    #pragma unroll
    for (int k = 0; k < 9; k++)
        cko[(size_t)p * 54 + h * 9 + k] = v[k] * inv;
}

// -------- dynamic-span conv out (float4 over head-dim) ----------------------
__global__ __launch_bounds__(256) void convout_kernel(
    const float* __restrict__ co, const float* __restrict__ cko,
    float* __restrict__ out)
{
    int idx = blockIdx.x * 256 + threadIdx.x;          // over BS * AH/4
    if (idx >= CK_BS * (CK_AH / 4)) return;
    int hd4 = idx % (CK_AH / 4);
    int bs  = idx / (CK_AH / 4);
    int s   = bs % CK_S;
    int hd  = hd4 * 4;
    int h   = hd >> 6;
    const float* ckp = cko + (size_t)bs * 54 + h * 9;
    float ck[9];
    #pragma unroll
    for (int k = 0; k < 9; k++) ck[k] = ckp[k];
    float4 acc = make_float4(0.f, 0.f, 0.f, 0.f);
    #pragma unroll
    for (int k = 0; k < 9; k++) {
        int ss = s + k - 4;
        if (ss >= 0 && ss < CK_S) {
            float4 x = *(const float4*)&co[((size_t)(bs - s + ss)) * CK_AH + hd];
            acc.x += x.x * ck[k];
            acc.y += x.y * ck[k];
            acc.z += x.z * ck[k];
            acc.w += x.w * ck[k];
        }
    }
    *(float4*)&out[(size_t)bs * (2 * CK_AH) + CK_AH + hd] = acc;
}

// ---------------- masked softmax of normalized td (per batch) ---------------
__global__ __launch_bounds__(256) void tdsm_kernel(
    const float* __restrict__ td, const int* __restrict__ mask,
    float* __restrict__ out)
{
    __shared__ float red[256];
    int b = blockIdx.x, tid = threadIdx.x;
    float v[4]; float ss = 0.0f;
    #pragma unroll
    for (int t = 0; t < 4; t++) { v[t] = td[b * CK_S + tid + t * 256]; ss += v[t] * v[t]; }
    red[tid] = ss; __syncthreads();
    for (int s = 128; s > 0; s >>= 1) { if (tid < s) red[tid] += red[tid + s]; __syncthreads(); }
    float denom = fmaxf(sqrtf(red[0]), 1e-12f);
    __syncthreads();
    float x[4]; float m = -1e30f;
    #pragma unroll
    for (int t = 0; t < 4; t++) {
        int j = tid + t * 256;
        x[t] = mask[b * CK_S + j] ? (v[t] / denom) : -1e4f;
        m = fmaxf(m, x[t]);
    }
    red[tid] = m; __syncthreads();
    for (int s = 128; s > 0; s >>= 1) { if (tid < s) red[tid] = fmaxf(red[tid], red[tid + s]); __syncthreads(); }
    m = red[0]; __syncthreads();
    float e[4]; float se = 0.0f;
    #pragma unroll
    for (int t = 0; t < 4; t++) { e[t] = __expf(x[t] - m); se += e[t]; }
    red[tid] = se; __syncthreads();
    for (int s = 128; s > 0; s >>= 1) { if (tid < s) red[tid] += red[tid + s]; __syncthreads(); }
    float inv = 1.0f / red[0];
    #pragma unroll
    for (int t = 0; t < 4; t++) out[b * CK_S + tid + t * 256] = e[t] * inv;
}

// ---------------- fused attention: 32 rows/CTA, 512 threads -----------------
// 1 CTA/SM, 16 warps. Phase 1: q b-frags hoisted to regs (chunk-invariant),
// mask folded at score store. Phase 2/3: no-max softmaxes (bounded scores),
// raw cumsum with normalization folded into exp2 constant. Phase 4: probs
// stored as tf32, V single tf32, 64-row chunks.
#define ATTN_SCP  1044   // 1044 % 32 == 20
#define ATTN_KP1  68     // phase-1 pitch (a-frag bank 4g+t)
#define ATTN_KP4  72     // phase-4 pitch (b-frag bank 8t+g)
#define ATTN_QSP  40     // q pitch: bank 8t+g distinct
#define ATTN_KVW  4608   // max(64*68, 64*72)
#define ATTN_ROWS 32
#define ATTN_THR  512
#define ATTN_SMEM_WORDS (ATTN_ROWS*ATTN_SCP + ATTN_KVW + 64*ATTN_QSP + 1040 + 264)
#define ATTN_SMEM_BYTES (ATTN_SMEM_WORDS*4)
#define LOG2E 1.4426950408889634f

__global__ __launch_bounds__(ATTN_THR, 1) void attn_kernel(
    const float* __restrict__ mq, const float* __restrict__ mk,
    const float* __restrict__ mv, const int* __restrict__ mask,
    const float* __restrict__ tdsm, const float* __restrict__ gammas,
    float* __restrict__ out)
{
    extern __shared__ float smem[];
    float*    sc  = smem;                                      // [32][1044]
    uint32_t* kvb = (uint32_t*)(smem + ATTN_ROWS * ATTN_SCP);  // K / V buffer
    uint32_t* qsu = kvb + ATTN_KVW;                            // q tf32 [d][i]
    float*    tds = (float*)(qsu + 64 * ATTN_QSP);             // [1040]
    uint8_t*  amf = (uint8_t*)(tds + 1040);                    // [1040] bytes

    int tid  = threadIdx.x;
    int warp = tid >> 5, lane = tid & 31;
    int g = lane >> 2, t = lane & 3;
    int blk = blockIdx.x;
    int it  = blk & 31;
    int h   = (blk >> 5) % CK_H;
    int b   = blk / (32 * CK_H);
    int i0  = it * ATTN_ROWS;

    for (int e = tid; e < ATTN_ROWS * 64; e += ATTN_THR) {
        int r = e >> 6, d = e & 63;
        qsu[d * ATTN_QSP + r] = f2tf32(
            mq[((size_t)(b * CK_S + i0 + r)) * CK_AH + h * CK_D + d] * 0.125f);
    }
    for (int j = tid; j < CK_S; j += ATTN_THR) {
        int fj = j + (j >> 6);
        amf[fj] = (uint8_t)(mask[b * CK_S + j] ? 1 : 0);
        tds[fj] = tdsm[b * CK_S + j];
    }
    float gamma = -log1pf(expf(gammas[h]));
    __syncthreads();

    // ---- phase 1: scores^T = K @ q^T, q frags in regs ----------------------
    {
        int jb  = (warp & 3) * 16;       // key m-subtile within 64-chunk
        int n0q = (warp >> 2) * 8;       // 8 query rows of 32
        uint32_t bq[8][2];
        #pragma unroll
        for (int ks = 0; ks < 8; ks++) {
            int kk = ks * 8;
            bq[ks][0] = qsu[(kk + t    ) * ATTN_QSP + n0q + g];
            bq[ks][1] = qsu[(kk + t + 4) * ATTN_QSP + n0q + g];
        }
        for (int c0 = 0; c0 < CK_S; c0 += 64) {
            __syncthreads();
            #pragma unroll
            for (int i = 0; i < 2; i++) {
                int e4 = tid + i * ATTN_THR;
                int j = e4 >> 4, d4 = (e4 & 15) << 2;
                float4 v = *(const float4*)
                    &mk[((size_t)(b * CK_S + c0 + j)) * CK_AH + h * CK_D + d4];
                *(uint4*)&kvb[j * ATTN_KP1 + d4] =
                    make_uint4(f2tf32(v.x), f2tf32(v.y), f2tf32(v.z), f2tf32(v.w));
            }
            __syncthreads();
            float c[4] = {0.f, 0.f, 0.f, 0.f};
            #pragma unroll
            for (int ks = 0; ks < 8; ks++) {
                int kk = ks * 8;
                uint32_t a[4];
                a[0] = kvb[(jb + g    ) * ATTN_KP1 + kk + t];
                a[1] = kvb[(jb + g + 8) * ATTN_KP1 + kk + t];
                a[2] = kvb[(jb + g    ) * ATTN_KP1 + kk + t + 4];
                a[3] = kvb[(jb + g + 8) * ATTN_KP1 + kk + t + 4];
                mma_tf32(c, a, bq[ks]);
            }
            #pragma unroll
            for (int half = 0; half < 2; half++) {
                int jglob = c0 + jb + g + 8 * half;
                int fj = jglob + (jglob >> 6);
                bool on = amf[fj] != 0;
                #pragma unroll
                for (int e = 0; e < 2; e++) {
                    float val = on ? c[2 * half + e] : -1e8f;
                    sc[(n0q + t * 2 + e) * ATTN_SCP + fj] = val;
                }
            }
        }
    }
    __syncthreads();

    // ---- phase 2+3: no-max softmax -> raw cumsum -> effect -> softmax ------
    {
        int r = tid >> 4;                 // row 0..31
        int l = tid & 15;                 // 64-wide segment
        unsigned ln  = tid & 31;
        unsigned sub = ln & 15;
        float* scr = sc + r * ATTN_SCP + l * 65;
        const float* tdsl = tds + l * 65;
        int irow = i0 + r;

        float ev[64];
        float cum = 0.0f;
        #pragma unroll
        for (int k = 0; k < 64; k++) {
            float p = __expf(scr[k]);     // masked (-1e8) underflows to 0
            cum += p;
            ev[k] = cum;
        }
        float x = cum;
        #pragma unroll
        for (int dl = 1; dl < 16; dl <<= 1) {
            float v = __shfl_up_sync(0xffffffffu, x, dl);
            if (sub >= (unsigned)dl) x += v;
        }
        float excl = x - cum;
        float tot  = __shfl_sync(0xffffffffu, x, (ln & 16) | 15);
        float inv  = 1.0f / tot;
        float rem0 = tot - excl;
        float ig2  = inv * gamma * gamma * (LOG2E * LOG2E);
        float posbase = (float)(l * 64 - irow);

        float s2 = 0.0f;
        #pragma unroll
        for (int k = 0; k < 64; k++) {
            float rem = rem0 - ev[k];
            float pj  = posbase + (float)k;           // j - irow exactly
            float t1  = fmaxf(rem * fabsf(pj), 0.0f);
            float e2  = exp2f(-sqrtf(t1 * ig2));      // clip(exp(ds*gamma)) hi side <=1
            float eff = fmaxf(e2, 1e-5f);
            if (pj < 0.0f) eff -= tdsl[k];
            float x2 = scr[k] * eff;
            float p2 = __expf(x2);                    // bounded |x2| small
            s2 += p2;
            ev[k] = p2;
        }
        #pragma unroll
        for (int dl = 8; dl >= 1; dl >>= 1)
            s2 += __shfl_xor_sync(0xffffffffu, s2, dl);
        float inv2 = 1.0f / s2;
        #pragma unroll
        for (int k = 0; k < 64; k++)
            scr[k] = __uint_as_float(f2tf32(ev[k] * inv2));   // tf32 probs
    }

    // ---- phase 4: ctx = P @ V, probs pre-tf32, V single tf32 ---------------
    {
        uint32_t* vh = kvb;
        int mt = warp & 1;               // row tile (16 of 32)
        int n0 = (warp >> 1) * 8;        // 8 d-cols
        int mb = mt * 16;
        float c[4] = {0.f, 0.f, 0.f, 0.f};
        for (int c0 = 0; c0 < CK_S; c0 += 64) {
            __syncthreads();
            #pragma unroll
            for (int i = 0; i < 2; i++) {
                int e4 = tid + i * ATTN_THR;
                int j = e4 >> 4, d4 = (e4 & 15) << 2;
                float4 v = *(const float4*)
                    &mv[((size_t)(b * CK_S + c0 + j)) * CK_AH + h * CK_D + d4];
                *(uint4*)&vh[j * ATTN_KP4 + d4] =
                    make_uint4(f2tf32(v.x), f2tf32(v.y), f2tf32(v.z), f2tf32(v.w));
            }
            __syncthreads();
            int cbase = c0 + (c0 >> 6);
            const uint32_t* scu = (const uint32_t*)sc;
            #pragma unroll
            for (int kk = 0; kk < 64; kk += 8) {
                uint32_t a[4], bh[2];
                int f0 = cbase + kk + t, f1 = f0 + 4;
                a[0] = scu[(mb + g    ) * ATTN_SCP + f0];
                a[1] = scu[(mb + g + 8) * ATTN_SCP + f0];
                a[2] = scu[(mb + g    ) * ATTN_SCP + f1];
                a[3] = scu[(mb + g + 8) * ATTN_SCP + f1];
                bh[0] = vh[(kk + t    ) * ATTN_KP4 + n0 + g];
                bh[1] = vh[(kk + t + 4) * ATTN_KP4 + n0 + g];
                mma_tf32(c, a, bh);
            }
        }
        #pragma unroll
        for (int half = 0; half < 2; half++) {
            int r = i0 + mb + g + 8 * half;
            float* op = out + ((size_t)(b * CK_S + r)) * (2 * CK_AH)
                            + h * CK_D + n0 + t * 2;
            op[0] = c[2 * half + 0];
            op[1] = c[2 * half + 1];
        }
    }
}

// ---------------------------------------------------------------------------
extern "C" void kernel_launch(void* const* d_in, const int* in_sizes, int n_in,
                              void* d_out, int out_size)
{
    const float* Q    = (const float*)d_in[0];
    const float* K    = (const float*)d_in[1];
    const float* V    = (const float*)d_in[2];
    const float* td   = (const float*)d_in[3];
    const int*   mask = (const int*)  d_in[4];
    const float* Wq   = (const float*)d_in[5];
    const float* Wk   = (const float*)d_in[6];
    const float* Wv   = (const float*)d_in[7];
    const float* dww  = (const float*)d_in[8];
    const float* pww  = (const float*)d_in[9];
    const float* sepb = (const float*)d_in[10];
    const float* ckW  = (const float*)d_in[11];
    const float* ckb  = (const float*)d_in[12];
    const float* coW  = (const float*)d_in[13];
    const float* cob  = (const float*)d_in[14];
    const float* gam  = (const float*)d_in[15];
    float* out = (float*)d_out;

    float *mq, *mk, *mv, *mkc, *co, *dw, *pwT, *ckl0, *ckl1, *ckl2, *cko, *tds;
    cudaGetSymbolAddress((void**)&mq,   g_mq);
    cudaGetSymbolAddress((void**)&mk,   g_mk);
    cudaGetSymbolAddress((void**)&mv,   g_mv);
    cudaGetSymbolAddress((void**)&mkc,  g_mkc);
    cudaGetSymbolAddress((void**)&co,   g_co);
    cudaGetSymbolAddress((void**)&dw,   g_dw);
    cudaGetSymbolAddress((void**)&pwT,  g_pwT);
    cudaGetSymbolAddress((void**)&ckl0, g_ckl0);
    cudaGetSymbolAddress((void**)&ckl1, g_ckl1);
    cudaGetSymbolAddress((void**)&ckl2, g_ckl2);
    cudaGetSymbolAddress((void**)&cko,  g_cko);
    cudaGetSymbolAddress((void**)&tds,  g_tds);

    transpose_pw<<<(CK_AH * CK_HID + 255) / 256, 256>>>(pww, pwT);
    dwconv_kernel<<<(CK_BS * (CK_HID / 4) + 255) / 256, 256>>>(K, dww, dw);

    dim3 ggrid(CK_AH / 128, CK_BS / 128, 5);
    gemm5_tf32<<<ggrid, 256>>>(Q, K, V, dw, Wq, Wk, Wv, coW, pwT,
                               cob, sepb, mq, mk, mv, co, mkc);

    dim3 ckgrid(CK_BS / 32, 3);
    ckgemm_tf32<<<ckgrid, 256>>>(mq, mkc, ckW, ckl0, ckl1, ckl2);
    ck_softmax<<<(CK_BS * CK_H + 255) / 256, 256>>>(ckl0, ckl1, ckl2, ckb, cko);
    convout_kernel<<<(CK_BS * (CK_AH / 4) + 255) / 256, 256>>>(co, cko, out);
    tdsm_kernel<<<CK_B, 256>>>(td, mask, tds);

    cudaFuncSetAttribute(attn_kernel, cudaFuncAttributeMaxDynamicSharedMemorySize,
                         ATTN_SMEM_BYTES);
    attn_kernel<<<CK_B * CK_H * (CK_S / ATTN_ROWS), ATTN_THR, ATTN_SMEM_BYTES>>>(
        mq, mk, mv, mask, tds, gam, out);
}

// round 14
// speedup vs baseline: 3.5154x; 1.0577x over previous
#include <cuda_runtime.h>
#include <math.h>
#include <stdint.h>

#define CK_B   4
#define CK_S   1024
#define CK_HID 768
#define CK_H   6
#define CK_D   64
#define CK_AH  384
#define CK_KS  9
#define CK_BS  (CK_B*CK_S)

// ---------------- scratch (device globals; no allocation allowed) ----------
__device__ float g_mq [CK_BS*CK_AH];
__device__ float g_mk [CK_BS*CK_AH];
__device__ float g_mv [CK_BS*CK_AH];
__device__ float g_mkc[CK_BS*CK_AH];
__device__ float g_co [CK_BS*CK_AH];
__device__ float g_dw [CK_BS*CK_HID];
__device__ float g_pwT[CK_HID*CK_AH];
__device__ float g_ckl0[CK_BS*64];
__device__ float g_ckl1[CK_BS*64];
__device__ float g_ckl2[CK_BS*64];
__device__ float g_cko[CK_BS*CK_H*CK_KS];
__device__ float g_tds[CK_BS];

// ---------------- tf32 helpers ---------------------------------------------
__device__ __forceinline__ uint32_t f2tf32(float f) {
    uint32_t u;
    asm("cvt.rna.tf32.f32 %0, %1;" : "=r"(u) : "f"(f));
    return u;
}
__device__ __forceinline__ uint4 cvt4(float4 v) {
    return make_uint4(f2tf32(v.x), f2tf32(v.y), f2tf32(v.z), f2tf32(v.w));
}
__device__ __forceinline__ void mma_tf32(float c[4], const uint32_t a[4],
                                         const uint32_t b[2]) {
    asm volatile(
        "mma.sync.aligned.m16n8k8.row.col.f32.tf32.tf32.f32 "
        "{%0,%1,%2,%3}, {%4,%5,%6,%7}, {%8,%9}, {%0,%1,%2,%3};"
        : "+f"(c[0]), "+f"(c[1]), "+f"(c[2]), "+f"(c[3])
        : "r"(a[0]), "r"(a[1]), "r"(a[2]), "r"(a[3]), "r"(b[0]), "r"(b[1]));
}

// ---------------- batched TF32 tensor-core GEMM (reg-prefetch) --------------
__global__ __launch_bounds__(256, 2) void gemm5_tf32(
    const float* __restrict__ Q, const float* __restrict__ Kin,
    const float* __restrict__ V, const float* __restrict__ dw,
    const float* __restrict__ Wq, const float* __restrict__ Wk,
    const float* __restrict__ Wv, const float* __restrict__ coW,
    const float* __restrict__ pwT,
    const float* __restrict__ cob, const float* __restrict__ sepb,
    float* __restrict__ mq, float* __restrict__ mk, float* __restrict__ mv,
    float* __restrict__ co, float* __restrict__ mkc)
{
    const float *A, *B, *bias; float* C;
    switch (blockIdx.z) {
        case 0:  A = Q;   B = Wq;  bias = nullptr; C = mq;  break;
        case 1:  A = Kin; B = Wk;  bias = nullptr; C = mk;  break;
        case 2:  A = V;   B = Wv;  bias = nullptr; C = mv;  break;
        case 3:  A = V;   B = coW; bias = cob;     C = co;  break;
        default: A = dw;  B = pwT; bias = sepb;    C = mkc; break;
    }
    __shared__ uint32_t As[128][36];
    __shared__ uint32_t Bs[32][132];

    int tid  = threadIdx.x;
    int m0   = blockIdx.y * 128;
    int n0   = blockIdx.x * 128;
    int lane = tid & 31;
    int g    = lane >> 2;
    int t    = lane & 3;
    int warp = tid >> 5;
    int wm   = warp >> 1;
    int wn   = warp & 1;

    float c[2][8][4];
    #pragma unroll
    for (int i = 0; i < 2; i++)
        #pragma unroll
        for (int j = 0; j < 8; j++)
            #pragma unroll
            for (int r = 0; r < 4; r++) c[i][j][r] = 0.0f;

    // prefetch slab 0
    float4 pa[4], pb[4];
    #pragma unroll
    for (int i = 0; i < 4; i++) {
        int e = tid + i * 256;
        int row = e >> 3, kq = (e & 7) << 2;
        pa[i] = *(const float4*)&A[(size_t)(m0 + row) * CK_HID + kq];
        int kr = e >> 5, nq = (e & 31) << 2;
        pb[i] = *(const float4*)&B[(size_t)kr * CK_AH + n0 + nq];
    }

    for (int k0 = 0; k0 < CK_HID; k0 += 32) {
        __syncthreads();
        #pragma unroll
        for (int i = 0; i < 4; i++) {
            int e = tid + i * 256;
            int row = e >> 3, kq = (e & 7) << 2;
            *(uint4*)&As[row][kq] = cvt4(pa[i]);
            int kr = e >> 5, nq = (e & 31) << 2;
            *(uint4*)&Bs[kr][nq] = cvt4(pb[i]);
        }
        __syncthreads();
        if (k0 + 32 < CK_HID) {
            #pragma unroll
            for (int i = 0; i < 4; i++) {
                int e = tid + i * 256;
                int row = e >> 3, kq = (e & 7) << 2;
                pa[i] = *(const float4*)
                    &A[(size_t)(m0 + row) * CK_HID + k0 + 32 + kq];
                int kr = e >> 5, nq = (e & 31) << 2;
                pb[i] = *(const float4*)
                    &B[(size_t)(k0 + 32 + kr) * CK_AH + n0 + nq];
            }
        }
        #pragma unroll
        for (int ks = 0; ks < 4; ks++) {
            int kk = ks * 8;
            uint32_t a[2][4], b[8][2];
            #pragma unroll
            for (int i = 0; i < 2; i++) {
                int bm = wm * 32 + i * 16;
                a[i][0] = As[bm + g    ][kk + t];
                a[i][1] = As[bm + g + 8][kk + t];
                a[i][2] = As[bm + g    ][kk + t + 4];
                a[i][3] = As[bm + g + 8][kk + t + 4];
            }
            #pragma unroll
            for (int j = 0; j < 8; j++) {
                int bn = wn * 64 + j * 8;
                b[j][0] = Bs[kk + t    ][bn + g];
                b[j][1] = Bs[kk + t + 4][bn + g];
            }
            #pragma unroll
            for (int i = 0; i < 2; i++)
                #pragma unroll
                for (int j = 0; j < 8; j++)
                    mma_tf32(c[i][j], a[i], b[j]);
        }
    }
    #pragma unroll
    for (int i = 0; i < 2; i++) {
        int r0 = m0 + wm * 32 + i * 16 + g;
        #pragma unroll
        for (int j = 0; j < 8; j++) {
            int col = n0 + wn * 64 + j * 8 + t * 2;
            float b0 = bias ? bias[col]     : 0.0f;
            float b1 = bias ? bias[col + 1] : 0.0f;
            C[(size_t)r0 * CK_AH + col]           = c[i][j][0] + b0;
            C[(size_t)r0 * CK_AH + col + 1]       = c[i][j][1] + b1;
            C[(size_t)(r0 + 8) * CK_AH + col]     = c[i][j][2] + b0;
            C[(size_t)(r0 + 8) * CK_AH + col + 1] = c[i][j][3] + b1;
        }
    }
}

// ---------------- transpose pw_w (AH,HID) -> (HID,AH) -----------------------
__global__ __launch_bounds__(256) void transpose_pw(
    const float* __restrict__ pw, float* __restrict__ pwT)
{
    int idx = blockIdx.x * 256 + threadIdx.x;
    if (idx >= CK_AH * CK_HID) return;
    int o = idx / CK_HID, c = idx % CK_HID;
    pwT[(size_t)c * CK_AH + o] = pw[idx];
}

// ---------------- depthwise conv (float4 over channels) ---------------------
__global__ __launch_bounds__(256) void dwconv_kernel(
    const float* __restrict__ Kin, const float* __restrict__ dww,
    float* __restrict__ outp)
{
    int idx = blockIdx.x * 256 + threadIdx.x;           // over BS * HID/4
    if (idx >= CK_BS * (CK_HID / 4)) return;
    int c4 = idx % (CK_HID / 4);
    int bs = idx / (CK_HID / 4);
    int s  = bs % CK_S;
    int c  = c4 * 4;
    float w[4][9];
    #pragma unroll
    for (int j = 0; j < 4; j++)
        #pragma unroll
        for (int t = 0; t < 9; t++) w[j][t] = dww[(c + j) * 9 + t];
    float4 acc = make_float4(0.f, 0.f, 0.f, 0.f);
    #pragma unroll
    for (int t = 0; t < 9; t++) {
        int ss = s + t - 4;
        if (ss >= 0 && ss < CK_S) {
            float4 x = *(const float4*)&Kin[((size_t)(bs - s + ss)) * CK_HID + c];
            acc.x += x.x * w[0][t];
            acc.y += x.y * w[1][t];
            acc.z += x.z * w[2][t];
            acc.w += x.w * w[3][t];
        }
    }
    *(float4*)&outp[(size_t)bs * CK_HID + c] = acc;
}

// ---------- ck logits GEMM, k-split in 3 slabs (grid.y) ----------------------
__global__ __launch_bounds__(256) void ckgemm_tf32(
    const float* __restrict__ mq, const float* __restrict__ mkc,
    const float* __restrict__ ckW,
    float* __restrict__ ckl0, float* __restrict__ ckl1,
    float* __restrict__ ckl2)
{
    __shared__ uint32_t As[32][68];
    __shared__ uint32_t Bs[64][72];
    int tid = threadIdx.x;
    int warp = tid >> 5, lane = tid & 31;
    int g = lane >> 2, t = lane & 3;
    int m0 = blockIdx.x * 32;
    int kbase = blockIdx.y * 128;
    float* ckl = (blockIdx.y == 0) ? ckl0 : ((blockIdx.y == 1) ? ckl1 : ckl2);
    int wm = warp & 1, wn = warp >> 1;

    float c[2][4];
    #pragma unroll
    for (int nt = 0; nt < 2; nt++)
        #pragma unroll
        for (int r = 0; r < 4; r++) c[nt][r] = 0.0f;

    for (int kc = 0; kc < 2; kc++) {
        int k0 = kbase + kc * 64;
        __syncthreads();
        #pragma unroll
        for (int i = 0; i < 2; i++) {
            int e4 = tid + i * 256;
            int row = e4 >> 4, d4 = (e4 & 15) << 2;
            float4 a4 = *(const float4*)&mq[(size_t)(m0 + row) * CK_AH + k0 + d4];
            float4 b4 = *(const float4*)&mkc[(size_t)(m0 + row) * CK_AH + k0 + d4];
            uint4 u;
            u.x = f2tf32(a4.x * b4.x); u.y = f2tf32(a4.y * b4.y);
            u.z = f2tf32(a4.z * b4.z); u.w = f2tf32(a4.w * b4.w);
            *(uint4*)&As[row][d4] = u;
        }
        #pragma unroll
        for (int i = 0; i < 18; i++) {
            int e = tid + i * 256;
            int kr = e / 72, o = e - kr * 72;
            float v = (o < 54) ? ckW[(size_t)(k0 + kr) * 54 + o] : 0.0f;
            Bs[kr][o] = f2tf32(v);
        }
        __syncthreads();
        #pragma unroll
        for (int kk = 0; kk < 64; kk += 8) {
            uint32_t a[4];
            int mb = wm * 16;
            a[0] = As[mb + g    ][kk + t];
            a[1] = As[mb + g + 8][kk + t];
            a[2] = As[mb + g    ][kk + t + 4];
            a[3] = As[mb + g + 8][kk + t + 4];
            #pragma unroll
            for (int nt = 0; nt < 2; nt++) {
                uint32_t bb[2];
                int bn = wn * 16 + nt * 8;
                bb[0] = Bs[kk + t    ][bn + g];
                bb[1] = Bs[kk + t + 4][bn + g];
                mma_tf32(c[nt], a, bb);
            }
        }
    }
    int r = m0 + wm * 16 + g;
    #pragma unroll
    for (int nt = 0; nt < 2; nt++) {
        int col = wn * 16 + nt * 8 + t * 2;
        ckl[(size_t)r * 64 + col]           = c[nt][0];
        ckl[(size_t)r * 64 + col + 1]       = c[nt][1];
        ckl[(size_t)(r + 8) * 64 + col]     = c[nt][2];
        ckl[(size_t)(r + 8) * 64 + col + 1] = c[nt][3];
    }
}

// ---------- softmax over KS=9 per (pos, head), summing k-slabs ---------------
__global__ __launch_bounds__(256) void ck_softmax(
    const float* __restrict__ ckl0, const float* __restrict__ ckl1,
    const float* __restrict__ ckl2, const float* __restrict__ ckb,
    float* __restrict__ cko)
{
    int gid = blockIdx.x * 256 + threadIdx.x;
    if (gid >= CK_BS * CK_H) return;
    int p = gid / CK_H, h = gid % CK_H;
    float v[9]; float m = -1e30f;
    #pragma unroll
    for (int k = 0; k < 9; k++) {
        int col = h * 9 + k;
        v[k] = ckl0[(size_t)p * 64 + col] + ckl1[(size_t)p * 64 + col]
             + ckl2[(size_t)p * 64 + col] + ckb[col];
        m = fmaxf(m, v[k]);
    }
    float s = 0.0f;
    #pragma unroll
    for (int k = 0; k < 9; k++) { v[k] = __expf(v[k] - m); s += v[k]; }
    float inv = 1.0f / s;
    #pragma unroll
    for (int k = 0; k < 9; k++)
        cko[(size_t)p * 54 + h * 9 + k] = v[k] * inv;
}

// -------- dynamic-span conv out (float4 over head-dim) ----------------------
__global__ __launch_bounds__(256) void convout_kernel(
    const float* __restrict__ co, const float* __restrict__ cko,
    float* __restrict__ out)
{
    int idx = blockIdx.x * 256 + threadIdx.x;          // over BS * AH/4
    if (idx >= CK_BS * (CK_AH / 4)) return;
    int hd4 = idx % (CK_AH / 4);
    int bs  = idx / (CK_AH / 4);
    int s   = bs % CK_S;
    int hd  = hd4 * 4;
    int h   = hd >> 6;
    const float* ckp = cko + (size_t)bs * 54 + h * 9;
    float ck[9];
    #pragma unroll
    for (int k = 0; k < 9; k++) ck[k] = ckp[k];
    float4 acc = make_float4(0.f, 0.f, 0.f, 0.f);
    #pragma unroll
    for (int k = 0; k < 9; k++) {
        int ss = s + k - 4;
        if (ss >= 0 && ss < CK_S) {
            float4 x = *(const float4*)&co[((size_t)(bs - s + ss)) * CK_AH + hd];
            acc.x += x.x * ck[k];
            acc.y += x.y * ck[k];
            acc.z += x.z * ck[k];
            acc.w += x.w * ck[k];
        }
    }
    *(float4*)&out[(size_t)bs * (2 * CK_AH) + CK_AH + hd] = acc;
}

// ---------------- masked softmax of normalized td (per batch) ---------------
__global__ __launch_bounds__(256) void tdsm_kernel(
    const float* __restrict__ td, const int* __restrict__ mask,
    float* __restrict__ out)
{
    __shared__ float red[256];
    int b = blockIdx.x, tid = threadIdx.x;
    float v[4]; float ss = 0.0f;
    #pragma unroll
    for (int t = 0; t < 4; t++) { v[t] = td[b * CK_S + tid + t * 256]; ss += v[t] * v[t]; }
    red[tid] = ss; __syncthreads();
    for (int s = 128; s > 0; s >>= 1) { if (tid < s) red[tid] += red[tid + s]; __syncthreads(); }
    float denom = fmaxf(sqrtf(red[0]), 1e-12f);
    __syncthreads();
    float x[4]; float m = -1e30f;
    #pragma unroll
    for (int t = 0; t < 4; t++) {
        int j = tid + t * 256;
        x[t] = mask[b * CK_S + j] ? (v[t] / denom) : -1e4f;
        m = fmaxf(m, x[t]);
    }
    red[tid] = m; __syncthreads();
    for (int s = 128; s > 0; s >>= 1) { if (tid < s) red[tid] = fmaxf(red[tid], red[tid + s]); __syncthreads(); }
    m = red[0]; __syncthreads();
    float e[4]; float se = 0.0f;
    #pragma unroll
    for (int t = 0; t < 4; t++) { e[t] = __expf(x[t] - m); se += e[t]; }
    red[tid] = se; __syncthreads();
    for (int s = 128; s > 0; s >>= 1) { if (tid < s) red[tid] += red[tid + s]; __syncthreads(); }
    float inv = 1.0f / red[0];
    #pragma unroll
    for (int t = 0; t < 4; t++) out[b * CK_S + tid + t * 256] = e[t] * inv;
}

// ---------------- fused attention: pipelined chunk loads --------------------
// 32 rows/CTA, 512 threads, 1 CTA/SM. Phases 1 & 4 double-buffer the K/V
// chunk in smem and prefetch the next chunk's LDGs into registers right after
// the single per-iteration barrier, hiding global latency under the MMAs.
#define ATTN_SCP  1044   // 1044 % 32 == 20
#define ATTN_KP1  68     // phase-1 pitch (a-frag bank 4g+t)
#define ATTN_KP4  72     // phase-4 pitch (b-frag bank 8t+g)
#define ATTN_QSP  40     // q pitch: bank 8t+g distinct
#define ATTN_KVW  (2*64*72)  // double buffer, max pitch
#define ATTN_ROWS 32
#define ATTN_THR  512
#define ATTN_SMEM_WORDS (ATTN_ROWS*ATTN_SCP + ATTN_KVW + 64*ATTN_QSP + 1040 + 264)
#define ATTN_SMEM_BYTES (ATTN_SMEM_WORDS*4)
#define LOG2E 1.4426950408889634f

__global__ __launch_bounds__(ATTN_THR, 1) void attn_kernel(
    const float* __restrict__ mq, const float* __restrict__ mk,
    const float* __restrict__ mv, const int* __restrict__ mask,
    const float* __restrict__ tdsm, const float* __restrict__ gammas,
    float* __restrict__ out)
{
    extern __shared__ float smem[];
    float*    sc  = smem;                                      // [32][1044]
    uint32_t* kvb = (uint32_t*)(smem + ATTN_ROWS * ATTN_SCP);  // 2 chunk bufs
    uint32_t* qsu = kvb + ATTN_KVW;                            // q tf32 [d][i]
    float*    tds = (float*)(qsu + 64 * ATTN_QSP);             // [1040]
    uint8_t*  amf = (uint8_t*)(tds + 1040);                    // [1040] bytes

    int tid  = threadIdx.x;
    int warp = tid >> 5, lane = tid & 31;
    int g = lane >> 2, t = lane & 3;
    int blk = blockIdx.x;
    int it  = blk & 31;
    int h   = (blk >> 5) % CK_H;
    int b   = blk / (32 * CK_H);
    int i0  = it * ATTN_ROWS;

    // per-thread chunk-load coords (2 float4 per thread per 64-row chunk)
    int ldj0 = tid >> 4,                ldd0 = (tid & 15) << 2;
    int ldj1 = (tid + ATTN_THR) >> 4,   ldd1 = ((tid + ATTN_THR) & 15) << 2;
    const float* mkbase = mk + (size_t)(b * CK_S) * CK_AH + h * CK_D;
    const float* mvbase = mv + (size_t)(b * CK_S) * CK_AH + h * CK_D;

    for (int e = tid; e < ATTN_ROWS * 64; e += ATTN_THR) {
        int r = e >> 6, d = e & 63;
        qsu[d * ATTN_QSP + r] = f2tf32(
            mq[((size_t)(b * CK_S + i0 + r)) * CK_AH + h * CK_D + d] * 0.125f);
    }
    for (int j = tid; j < CK_S; j += ATTN_THR) {
        int fj = j + (j >> 6);
        amf[fj] = (uint8_t)(mask[b * CK_S + j] ? 1 : 0);
        tds[fj] = tdsm[b * CK_S + j];
    }
    float gamma = -log1pf(expf(gammas[h]));

    // prefetch K chunk 0 (before the setup barrier; independent of smem)
    float4 r0 = *(const float4*)&mkbase[(size_t)ldj0 * CK_AH + ldd0];
    float4 r1 = *(const float4*)&mkbase[(size_t)ldj1 * CK_AH + ldd1];
    __syncthreads();

    // ---- phase 1: scores^T = K @ q^T, pipelined ----------------------------
    {
        int jb  = (warp & 3) * 16;       // key m-subtile within 64-chunk
        int n0q = (warp >> 2) * 8;       // 8 query rows of 32
        uint32_t bq[8][2];
        #pragma unroll
        for (int ks = 0; ks < 8; ks++) {
            int kk = ks * 8;
            bq[ks][0] = qsu[(kk + t    ) * ATTN_QSP + n0q + g];
            bq[ks][1] = qsu[(kk + t + 4) * ATTN_QSP + n0q + g];
        }
        #pragma unroll 1
        for (int ci = 0; ci < 16; ci++) {
            uint32_t* cb = kvb + (ci & 1) * (64 * ATTN_KP1);
            *(uint4*)&cb[ldj0 * ATTN_KP1 + ldd0] = cvt4(r0);
            *(uint4*)&cb[ldj1 * ATTN_KP1 + ldd1] = cvt4(r1);
            __syncthreads();
            if (ci < 15) {
                const float* nb = mkbase + (size_t)(ci + 1) * 64 * CK_AH;
                r0 = *(const float4*)&nb[(size_t)ldj0 * CK_AH + ldd0];
                r1 = *(const float4*)&nb[(size_t)ldj1 * CK_AH + ldd1];
            }
            float c[4] = {0.f, 0.f, 0.f, 0.f};
            #pragma unroll
            for (int ks = 0; ks < 8; ks++) {
                int kk = ks * 8;
                uint32_t a[4];
                a[0] = cb[(jb + g    ) * ATTN_KP1 + kk + t];
                a[1] = cb[(jb + g + 8) * ATTN_KP1 + kk + t];
                a[2] = cb[(jb + g    ) * ATTN_KP1 + kk + t + 4];
                a[3] = cb[(jb + g + 8) * ATTN_KP1 + kk + t + 4];
                mma_tf32(c, a, bq[ks]);
            }
            int c0 = ci * 64;
            #pragma unroll
            for (int half = 0; half < 2; half++) {
                int jglob = c0 + jb + g + 8 * half;
                int fj = jglob + (jglob >> 6);
                bool on = amf[fj] != 0;
                #pragma unroll
                for (int e = 0; e < 2; e++) {
                    float val = on ? c[2 * half + e] : -1e8f;
                    sc[(n0q + t * 2 + e) * ATTN_SCP + fj] = val;
                }
            }
        }
    }
    __syncthreads();

    // ---- phase 2+3: no-max softmax -> raw cumsum -> effect -> softmax ------
    {
        int r = tid >> 4;                 // row 0..31
        int l = tid & 15;                 // 64-wide segment
        unsigned ln  = tid & 31;
        unsigned sub = ln & 15;
        float* scr = sc + r * ATTN_SCP + l * 65;
        const float* tdsl = tds + l * 65;
        int irow = i0 + r;

        float ev[64];
        float cum = 0.0f;
        #pragma unroll
        for (int k = 0; k < 64; k++) {
            float p = __expf(scr[k]);     // masked (-1e8) underflows to 0
            cum += p;
            ev[k] = cum;
        }
        float x = cum;
        #pragma unroll
        for (int dl = 1; dl < 16; dl <<= 1) {
            float v = __shfl_up_sync(0xffffffffu, x, dl);
            if (sub >= (unsigned)dl) x += v;
        }
        float excl = x - cum;
        float tot  = __shfl_sync(0xffffffffu, x, (ln & 16) | 15);
        float inv  = 1.0f / tot;
        float rem0 = tot - excl;
        float ig2  = inv * gamma * gamma * (LOG2E * LOG2E);
        float posbase = (float)(l * 64 - irow);

        float s2 = 0.0f;
        #pragma unroll
        for (int k = 0; k < 64; k++) {
            float rem = rem0 - ev[k];
            float pj  = posbase + (float)k;           // j - irow exactly
            float t1  = fmaxf(rem * fabsf(pj), 0.0f);
            float e2  = exp2f(-sqrtf(t1 * ig2));
            float eff = fmaxf(e2, 1e-5f);
            if (pj < 0.0f) eff -= tdsl[k];
            float x2 = scr[k] * eff;
            float p2 = __expf(x2);
            s2 += p2;
            ev[k] = p2;
        }
        #pragma unroll
        for (int dl = 8; dl >= 1; dl >>= 1)
            s2 += __shfl_xor_sync(0xffffffffu, s2, dl);
        float inv2 = 1.0f / s2;
        #pragma unroll
        for (int k = 0; k < 64; k++)
            scr[k] = __uint_as_float(f2tf32(ev[k] * inv2));   // tf32 probs
    }

    // prefetch V chunk 0 (no barrier needed: writes target kvb which phase 4
    // stores AFTER its first barrier; sc reads are covered by that barrier)
    r0 = *(const float4*)&mvbase[(size_t)ldj0 * CK_AH + ldd0];
    r1 = *(const float4*)&mvbase[(size_t)ldj1 * CK_AH + ldd1];

    // ---- phase 4: ctx = P @ V, pipelined -----------------------------------
    {
        int mt = warp & 1;               // row tile (16 of 32)
        int n0 = (warp >> 1) * 8;        // 8 d-cols
        int mb = mt * 16;
        const uint32_t* scu = (const uint32_t*)sc;
        float c[4] = {0.f, 0.f, 0.f, 0.f};
        #pragma unroll 1
        for (int ci = 0; ci < 16; ci++) {
            uint32_t* cb = kvb + (ci & 1) * (64 * ATTN_KP4);
            // barrier FIRST: ensures all phase-2/3 prob writes (and prior
            // chunk's MMA reads) are complete before overwriting cb
            __syncthreads();
            *(uint4*)&cb[ldj0 * ATTN_KP4 + ldd0] = cvt4(r0);
            *(uint4*)&cb[ldj1 * ATTN_KP4 + ldd1] = cvt4(r1);
            __syncthreads();
            if (ci < 15) {
                const float* nb = mvbase + (size_t)(ci + 1) * 64 * CK_AH;
                r0 = *(const float4*)&nb[(size_t)ldj0 * CK_AH + ldd0];
                r1 = *(const float4*)&nb[(size_t)ldj1 * CK_AH + ldd1];
            }
            int cbase = ci * 64 + ci;     // c0 + c0/64
            #pragma unroll
            for (int kk = 0; kk < 64; kk += 8) {
                uint32_t a[4], bh[2];
                int f0 = cbase + kk + t, f1 = f0 + 4;
                a[0] = scu[(mb + g    ) * ATTN_SCP + f0];
                a[1] = scu[(mb + g + 8) * ATTN_SCP + f0];
                a[2] = scu[(mb + g    ) * ATTN_SCP + f1];
                a[3] = scu[(mb + g + 8) * ATTN_SCP + f1];
                bh[0] = cb[(kk + t    ) * ATTN_KP4 + n0 + g];
                bh[1] = cb[(kk + t + 4) * ATTN_KP4 + n0 + g];
                mma_tf32(c, a, bh);
            }
        }
        #pragma unroll
        for (int half = 0; half < 2; half++) {
            int r = i0 + mb + g + 8 * half;
            float* op = out + ((size_t)(b * CK_S + r)) * (2 * CK_AH)
                            + h * CK_D + n0 + t * 2;
            op[0] = c[2 * half + 0];
            op[1] = c[2 * half + 1];
        }
    }
}

// ---------------------------------------------------------------------------
extern "C" void kernel_launch(void* const* d_in, const int* in_sizes, int n_in,
                              void* d_out, int out_size)
{
    const float* Q    = (const float*)d_in[0];
    const float* K    = (const float*)d_in[1];
    const float* V    = (const float*)d_in[2];
    const float* td   = (const float*)d_in[3];
    const int*   mask = (const int*)  d_in[4];
    const float* Wq   = (const float*)d_in[5];
    const float* Wk   = (const float*)d_in[6];
    const float* Wv   = (const float*)d_in[7];
    const float* dww  = (const float*)d_in[8];
    const float* pww  = (const float*)d_in[9];
    const float* sepb = (const float*)d_in[10];
    const float* ckW  = (const float*)d_in[11];
    const float* ckb  = (const float*)d_in[12];
    const float* coW  = (const float*)d_in[13];
    const float* cob  = (const float*)d_in[14];
    const float* gam  = (const float*)d_in[15];
    float* out = (float*)d_out;

    float *mq, *mk, *mv, *mkc, *co, *dw, *pwT, *ckl0, *ckl1, *ckl2, *cko, *tds;
    cudaGetSymbolAddress((void**)&mq,   g_mq);
    cudaGetSymbolAddress((void**)&mk,   g_mk);
    cudaGetSymbolAddress((void**)&mv,   g_mv);
    cudaGetSymbolAddress((void**)&mkc,  g_mkc);
    cudaGetSymbolAddress((void**)&co,   g_co);
    cudaGetSymbolAddress((void**)&dw,   g_dw);
    cudaGetSymbolAddress((void**)&pwT,  g_pwT);
    cudaGetSymbolAddress((void**)&ckl0, g_ckl0);
    cudaGetSymbolAddress((void**)&ckl1, g_ckl1);
    cudaGetSymbolAddress((void**)&ckl2, g_ckl2);
    cudaGetSymbolAddress((void**)&cko,  g_cko);
    cudaGetSymbolAddress((void**)&tds,  g_tds);

    transpose_pw<<<(CK_AH * CK_HID + 255) / 256, 256>>>(pww, pwT);
    dwconv_kernel<<<(CK_BS * (CK_HID / 4) + 255) / 256, 256>>>(K, dww, dw);

    dim3 ggrid(CK_AH / 128, CK_BS / 128, 5);
    gemm5_tf32<<<ggrid, 256>>>(Q, K, V, dw, Wq, Wk, Wv, coW, pwT,
                               cob, sepb, mq, mk, mv, co, mkc);

    dim3 ckgrid(CK_BS / 32, 3);
    ckgemm_tf32<<<ckgrid, 256>>>(mq, mkc, ckW, ckl0, ckl1, ckl2);
    ck_softmax<<<(CK_BS * CK_H + 255) / 256, 256>>>(ckl0, ckl1, ckl2, ckb, cko);
    convout_kernel<<<(CK_BS * (CK_AH / 4) + 255) / 256, 256>>>(co, cko, out);
    tdsm_kernel<<<CK_B, 256>>>(td, mask, tds);

    cudaFuncSetAttribute(attn_kernel, cudaFuncAttributeMaxDynamicSharedMemorySize,
                         ATTN_SMEM_BYTES);
    attn_kernel<<<CK_B * CK_H * (CK_S / ATTN_ROWS), ATTN_THR, ATTN_SMEM_BYTES>>>(
        mq, mk, mv, mask, tds, gam, out);
}